// round 4
// baseline (speedup 1.0000x reference)
#include <cuda_runtime.h>
#include <cuda_bf16.h>
#include <math.h>

#define Tn 1024
#define Hn 2048
#define In 1408
#define En 64
#define Fn 8
#define Kn 8
#define Rn 8
#define ISHn 2816
#define TOPKn 6
#define KRn 64

// ---------------- scratch (device globals; allocation-free) ----------------
__device__ float g_soft[Tn * Fn * Kn];
__device__ float g_scalar[Tn * Fn];
__device__ int   g_cnt[Fn];
__device__ int   g_tok[Fn * Tn];
__device__ int   g_pos[Fn * Tn];
__device__ float g_xe[(size_t)Fn * Tn * Hn];
__device__ float g_gug[(size_t)Fn * Tn * In];
__device__ float g_guu[(size_t)Fn * Tn * In];
__device__ float g_mg[(size_t)Fn * Tn * KRn];
__device__ float g_mu[(size_t)Fn * Tn * KRn];
__device__ float g_hmid[(size_t)Fn * Tn * In];
__device__ float g_md[(size_t)Fn * Tn * KRn];
__device__ float g_mixd[(size_t)Fn * Tn * Hn];
__device__ float g_down[(size_t)Fn * Tn * Hn];
__device__ float g_qbtg[(size_t)Fn * In * KRn];
__device__ float g_qbtu[(size_t)Fn * In * KRn];
__device__ float g_qbtd[(size_t)Fn * Hn * KRn];
__device__ float g_shg[(size_t)Tn * ISHn];
__device__ float g_shu[(size_t)Tn * ISHn];
__device__ float g_shm[(size_t)Tn * ISHn];

// ---------------- helpers ----------------
__device__ __forceinline__ float tf32r(float x) {
    float y;
    asm("cvt.rna.tf32.f32 %0, %1;" : "=f"(y) : "f"(x));
    return y;
}

#define MMA_TF32(d, a, b)                                                      \
    asm volatile(                                                              \
        "mma.sync.aligned.m16n8k8.row.col.f32.tf32.tf32.f32 "                  \
        "{%0,%1,%2,%3}, {%4,%5,%6,%7}, {%8,%9}, {%0,%1,%2,%3};\n"              \
        : "+f"((d)[0]), "+f"((d)[1]), "+f"((d)[2]), "+f"((d)[3])               \
        : "r"(__float_as_uint((a)[0])), "r"(__float_as_uint((a)[1])),          \
          "r"(__float_as_uint((a)[2])), "r"(__float_as_uint((a)[3])),          \
          "r"(__float_as_uint((b)[0])), "r"(__float_as_uint((b)[1])))

// ---------------- router (exact fp32: top-k must not flip) ----------------
__global__ void router_kernel(const float* __restrict__ x,
                              const float* __restrict__ gw,
                              const int* __restrict__ inv,
                              float* __restrict__ soft,
                              float* __restrict__ scal) {
    __shared__ float xs[Hn];
    __shared__ float sc[En];
    const int t = blockIdx.x;
    const int tid = threadIdx.x;  // 128 threads
    const float4* xv = reinterpret_cast<const float4*>(x + (size_t)t * Hn);
    for (int i = tid; i < Hn / 4; i += 128)
        reinterpret_cast<float4*>(xs)[i] = xv[i];
    __syncthreads();
    const int lane = tid & 31, w = tid >> 5;
    for (int e = w; e < En; e += 4) {
        const float* g = gw + (size_t)e * Hn;
        float s = 0.f;
        for (int h = lane; h < Hn; h += 32) s += xs[h] * g[h];
#pragma unroll
        for (int o = 16; o; o >>= 1) s += __shfl_xor_sync(0xffffffffu, s, o);
        if (lane == 0) sc[e] = s;
    }
    __syncthreads();
    if (tid == 0) {
        float mx = -1e30f;
        for (int e = 0; e < En; e++) mx = fmaxf(mx, sc[e]);
        float p[En];
        float sum = 0.f;
        for (int e = 0; e < En; e++) { p[e] = expf(sc[e] - mx); sum += p[e]; }
        float is = 1.f / sum;
        for (int e = 0; e < En; e++) p[e] *= is;
        float wv[En];
        for (int e = 0; e < En; e++) wv[e] = 0.f;
        for (int j = 0; j < TOPKn; j++) {
            int best = 0;
            float bv = -1.f;
            for (int e = 0; e < En; e++) {
                if (wv[e] == 0.f && p[e] > bv) { bv = p[e]; best = e; }
            }
            wv[best] = p[best];
        }
        for (int f = 0; f < Fn; f++) {
            float fl[Kn];
            float ssum = 0.f, fmx = -1e30f;
            for (int k = 0; k < Kn; k++) {
                int e = inv[f * Kn + k];
                float v = wv[e];
                ssum += v;
                float l = (v == 0.f) ? -1e9f : v;
                fl[k] = l;
                fmx = fmaxf(fmx, l);
            }
            float es = 0.f, ex[Kn];
            for (int k = 0; k < Kn; k++) { ex[k] = expf(fl[k] - fmx); es += ex[k]; }
            float ies = 1.f / es;
            for (int k = 0; k < Kn; k++)
                soft[((size_t)t * Fn + f) * Kn + k] = ex[k] * ies;
            scal[(size_t)t * Fn + f] = ssum;
        }
    }
}

// ---------------- deterministic per-group token compaction ----------------
__global__ void compact_kernel(const float* __restrict__ scal,
                               int* __restrict__ cnt,
                               int* __restrict__ tok,
                               int* __restrict__ pos) {
    const int z = blockIdx.x;
    const int t = threadIdx.x;  // Tn threads
    __shared__ int sbuf[Tn];
    int active = (scal[(size_t)t * Fn + z] != 0.f) ? 1 : 0;
    sbuf[t] = active;
    __syncthreads();
    for (int off = 1; off < Tn; off <<= 1) {
        int v = (t >= off) ? sbuf[t - off] : 0;
        __syncthreads();
        sbuf[t] += v;
        __syncthreads();
    }
    int incl = sbuf[t];
    if (active) {
        tok[z * Tn + incl - 1] = t;
        pos[z * Tn + t] = incl - 1;
    } else {
        pos[z * Tn + t] = -1;
    }
    if (t == Tn - 1) cnt[z] = incl;
}

// ---------------- xe (compacted): xe[z,i,h] = x[tok] + soft @ muW^T --------
__global__ void xe_kernel(const float* __restrict__ x,
                          const float* __restrict__ muW,
                          const float* __restrict__ soft,
                          const int* __restrict__ cnt,
                          const int* __restrict__ tok,
                          float* __restrict__ xe) {
    size_t idx = (size_t)blockIdx.x * blockDim.x + threadIdx.x;
    if (idx >= (size_t)Fn * Tn * Hn) return;
    int z = (int)(idx / ((size_t)Tn * Hn));
    int rem = (int)(idx % ((size_t)Tn * Hn));
    int i = rem / Hn, h = rem % Hn;
    if (i >= cnt[z]) return;
    int t = tok[z * Tn + i];
    const float* mw = muW + ((size_t)z * Hn + h) * Kn;
    const float* sf = soft + ((size_t)t * Fn + z) * Kn;
    float s = x[(size_t)t * Hn + h];
#pragma unroll
    for (int k = 0; k < Kn; k++) s += sf[k] * mw[k];
    xe[idx] = s;
}

// ---------------- qb transpose: [F,K,Nd,R] -> [F,Nd,K*R] ----------------
__global__ void tq_kernel(const float* __restrict__ qb, float* __restrict__ outp, int Nd) {
    int total = Fn * Nd * KRn;
    int idx = blockIdx.x * blockDim.x + threadIdx.x;
    if (idx >= total) return;
    int z = idx / (Nd * KRn);
    int rem = idx % (Nd * KRn);
    int n = rem >> 6, kr = rem & 63;
    int k = kr >> 3, r = kr & 7;
    outp[idx] = qb[(((size_t)z * Kn + k) * Nd + n) * Rn + r];
}

// ---------------- hmid = silu(gate)*up (compacted rows only) --------------
__global__ void fuse_kernel(const float* __restrict__ gg, const float* __restrict__ uu,
                            const int* __restrict__ cnt,
                            float* __restrict__ hm) {
    size_t idx = (size_t)blockIdx.x * blockDim.x + threadIdx.x;
    if (idx >= (size_t)Fn * Tn * In) return;
    int z = (int)(idx / ((size_t)Tn * In));
    int i = (int)((idx % ((size_t)Tn * In)) / In);
    if (i >= cnt[z]) return;
    float g = gg[idx], u = uu[idx];
    hm[idx] = g / (1.f + expf(-g)) * u;
}

__global__ void swiglu_kernel(const float* __restrict__ gg, const float* __restrict__ uu,
                              float* __restrict__ hm) {
    size_t idx = (size_t)blockIdx.x * blockDim.x + threadIdx.x;
    if (idx >= (size_t)Tn * ISHn) return;
    float g = gg[idx], u = uu[idx];
    hm[idx] = g / (1.f + expf(-g)) * u;
}

// ---------------- out[t] += sum_z active: down[z][pos[z,t]] ----------------
__global__ void reduce_kernel(float* __restrict__ out, const float* __restrict__ down,
                              const int* __restrict__ pos) {
    int idx = blockIdx.x * blockDim.x + threadIdx.x;
    if (idx >= Tn * Hn) return;
    int t = idx / Hn, h = idx % Hn;
    float s = out[idx];
#pragma unroll
    for (int z = 0; z < Fn; z++) {
        int p = pos[z * Tn + t];
        if (p >= 0) s += down[((size_t)z * Tn + p) * Hn + h];
    }
    out[idx] = s;
}

// ---------------- generic tf32 GEMM: C[MxN] = A[MxK] * B[NxK]^T ----------------
// 3-deep register-staged pipeline: LDG(kt+2) issued at chunk kt, stored to smem
// at chunk kt+1 -> ~2 chunks of latency budget instead of 1.
// M is bounded per-z by cnt[z] when cntp != nullptr (compacted rows).
// MODE 0: C=acc
// MODE 1: C=acc*soft[tok[r], z, n>>3]
// MODE 2: C=C + colscale[n]*acc   (in-place add)
// MODE 3: C=colscale[n]*acc
// MODE 4: C=rowscal[tok[r]*Fn+z]*(acc + mixadd[z,r,n])
#define KC 32
#define SM_LD 36
#define SM_BUF (128 * SM_LD)
#define SMEM_BYTES (4 * SM_BUF * 4)

template <int MODE>
__global__ void __launch_bounds__(256)
gemm_tn(const float* __restrict__ A, int lda, size_t sA,
        const float* __restrict__ B, int ldb, size_t sB,
        float* __restrict__ C, int ldc, size_t sC,
        int N, int Ktot,
        const float* __restrict__ soft,
        const float* __restrict__ rowscal,
        const float* __restrict__ colscale, size_t sCs,
        const float* __restrict__ mixadd,
        const int* __restrict__ cntp,
        const int* __restrict__ tokp) {
    const int z = blockIdx.z;
    const int Mz = cntp ? cntp[z] : Tn;
    const int bm = blockIdx.y * 128, bn = blockIdx.x * 128;
    if (bm >= Mz) return;
    A += (size_t)z * sA;
    B += (size_t)z * sB;
    C += (size_t)z * sC;
    const float* cs = (MODE == 2 || MODE == 3) ? colscale + (size_t)z * sCs : nullptr;
    const float* mixp = (MODE == 4) ? mixadd + (size_t)z * sC : nullptr;
    const int* tk = (MODE == 1 || MODE == 4) ? tokp + z * Tn : nullptr;

    extern __shared__ float smf[];
    float* As = smf;
    float* Bs = smf + 2 * SM_BUF;
    const int tid = threadIdx.x, lane = tid & 31, wid = tid >> 5;
    const int wm = (wid >> 2) * 64, wn = (wid & 3) * 32;

    int arow[4], kq4[4];
#pragma unroll
    for (int i = 0; i < 4; i++) {
        int lin = tid + i * 256;
        arow[i] = lin >> 3;
        kq4[i] = (lin & 7) << 2;
    }
    float4 ra[2][4], rb[2][4];
    float acc[4][4][4];
#pragma unroll
    for (int a = 0; a < 4; a++)
#pragma unroll
        for (int b = 0; b < 4; b++)
#pragma unroll
            for (int c = 0; c < 4; c++) acc[a][b][c] = 0.f;

    const float4 z4 = make_float4(0.f, 0.f, 0.f, 0.f);
    auto ldg = [&](int k0, int s) {
#pragma unroll
        for (int i = 0; i < 4; i++) {
            int m = bm + arow[i];
            ra[s][i] = (m < Mz)
                           ? *reinterpret_cast<const float4*>(A + (size_t)m * lda + k0 + kq4[i])
                           : z4;
            int n = bn + arow[i];
            rb[s][i] = (n < N)
                           ? *reinterpret_cast<const float4*>(B + (size_t)n * ldb + k0 + kq4[i])
                           : z4;
        }
    };
    auto sts = [&](int buf, int s) {
#pragma unroll
        for (int i = 0; i < 4; i++) {
            float4 a = ra[s][i];
            a.x = tf32r(a.x); a.y = tf32r(a.y); a.z = tf32r(a.z); a.w = tf32r(a.w);
            *reinterpret_cast<float4*>(&As[buf * SM_BUF + arow[i] * SM_LD + kq4[i]]) = a;
            float4 b = rb[s][i];
            b.x = tf32r(b.x); b.y = tf32r(b.y); b.z = tf32r(b.z); b.w = tf32r(b.w);
            *reinterpret_cast<float4*>(&Bs[buf * SM_BUF + arow[i] * SM_LD + kq4[i]]) = b;
        }
    };

    const int KT = Ktot / KC;
    // prologue: chunk0 -> set0 -> smem buf0; chunk1 -> set1 (kept in regs)
    ldg(0, 0);
    sts(0, 0);
    if (KT > 1) ldg(KC, 1);
    __syncthreads();

    for (int kt = 0; kt < KT; kt++) {
        const int cur = kt & 1;
        if (kt + 2 < KT) ldg((kt + 2) * KC, cur);  // set(cur) free: stored at kt-1
        const float* Ab = As + cur * SM_BUF;
        const float* Bb = Bs + cur * SM_BUF;
#pragma unroll
        for (int ks = 0; ks < 4; ks++) {
            int kk = ks * 8 + (lane & 3);
            float a[4][4], b[4][2];
#pragma unroll
            for (int mi = 0; mi < 4; mi++) {
                const float* p = Ab + (wm + mi * 16 + (lane >> 2)) * SM_LD + kk;
                a[mi][0] = p[0];
                a[mi][1] = p[8 * SM_LD];
                a[mi][2] = p[4];
                a[mi][3] = p[8 * SM_LD + 4];
            }
#pragma unroll
            for (int ni = 0; ni < 4; ni++) {
                const float* q = Bb + (wn + ni * 8 + (lane >> 2)) * SM_LD + kk;
                b[ni][0] = q[0];
                b[ni][1] = q[4];
            }
#pragma unroll
            for (int mi = 0; mi < 4; mi++)
#pragma unroll
                for (int ni = 0; ni < 4; ni++) MMA_TF32(acc[mi][ni], a[mi], b[ni]);
        }
        if (kt + 1 < KT) {
            sts(cur ^ 1, cur ^ 1);  // chunk kt+1 (loaded at kt-1) -> buf(cur^1)
            __syncthreads();
        }
    }

    // epilogue
#pragma unroll
    for (int mi = 0; mi < 4; mi++) {
#pragma unroll
        for (int ni = 0; ni < 4; ni++) {
            int cb = bn + wn + ni * 8;
            if (cb >= N) continue;
            int c = cb + ((lane & 3) << 1);
#pragma unroll
            for (int hh = 0; hh < 2; hh++) {
                int r = bm + wm + mi * 16 + (lane >> 2) + hh * 8;
                if (r >= Mz) continue;
                float v0 = acc[mi][ni][hh * 2 + 0];
                float v1 = acc[mi][ni][hh * 2 + 1];
                size_t off = (size_t)r * ldc + c;
                if (MODE == 1) {
                    float s = soft[((size_t)tk[r] * Fn + z) * Kn + (c >> 3)];
                    v0 *= s;
                    v1 *= s;
                } else if (MODE == 2) {
                    float2 prev = *reinterpret_cast<const float2*>(&C[off]);
                    v0 = prev.x + cs[c] * v0;
                    v1 = prev.y + cs[c + 1] * v1;
                } else if (MODE == 3) {
                    v0 *= cs[c];
                    v1 *= cs[c + 1];
                } else if (MODE == 4) {
                    float rs = rowscal[(size_t)tk[r] * Fn + z];
                    float2 mv = *reinterpret_cast<const float2*>(&mixp[off]);
                    v0 = rs * (v0 + mv.x);
                    v1 = rs * (v1 + mv.y);
                }
                *reinterpret_cast<float2*>(&C[off]) = make_float2(v0, v1);
            }
        }
    }
}

// ---------------- host ----------------
#define SYMP(v, T) ({ void* _p = nullptr; cudaGetSymbolAddress(&_p, v); (T*)_p; })

extern "C" void kernel_launch(void* const* d_in, const int* in_sizes, int n_in,
                              void* d_out, int out_size) {
    const float* x          = (const float*)d_in[0];
    const float* gate_wt    = (const float*)d_in[1];
    const int*   inv        = (const int*)d_in[2];
    const float* mask_up_W  = (const float*)d_in[3];
    const float* gate_W     = (const float*)d_in[4];
    const float* gate_qa    = (const float*)d_in[5];
    const float* gate_qb    = (const float*)d_in[6];
    const float* gate_scale = (const float*)d_in[7];
    const float* up_W       = (const float*)d_in[8];
    const float* up_qa      = (const float*)d_in[9];
    const float* up_qb      = (const float*)d_in[10];
    const float* up_scale   = (const float*)d_in[11];
    const float* down_W     = (const float*)d_in[12];
    const float* down_qa    = (const float*)d_in[13];
    const float* down_qb    = (const float*)d_in[14];
    const float* down_scale = (const float*)d_in[15];
    const float* sh_gate_W  = (const float*)d_in[16];
    const float* sh_up_W    = (const float*)d_in[17];
    const float* sh_down_W  = (const float*)d_in[18];
    float* out = (float*)d_out;

    float* p_soft = SYMP(g_soft, float);
    float* p_scal = SYMP(g_scalar, float);
    int*   p_cnt  = SYMP(g_cnt, int);
    int*   p_tok  = SYMP(g_tok, int);
    int*   p_pos  = SYMP(g_pos, int);
    float* p_xe   = SYMP(g_xe, float);
    float* p_gug  = SYMP(g_gug, float);
    float* p_guu  = SYMP(g_guu, float);
    float* p_mg   = SYMP(g_mg, float);
    float* p_mu   = SYMP(g_mu, float);
    float* p_hmid = SYMP(g_hmid, float);
    float* p_md   = SYMP(g_md, float);
    float* p_mixd = SYMP(g_mixd, float);
    float* p_down = SYMP(g_down, float);
    float* p_qbtg = SYMP(g_qbtg, float);
    float* p_qbtu = SYMP(g_qbtu, float);
    float* p_qbtd = SYMP(g_qbtd, float);
    float* p_shg  = SYMP(g_shg, float);
    float* p_shu  = SYMP(g_shu, float);
    float* p_shm  = SYMP(g_shm, float);

    cudaFuncSetAttribute(gemm_tn<0>, cudaFuncAttributeMaxDynamicSharedMemorySize, SMEM_BYTES);
    cudaFuncSetAttribute(gemm_tn<1>, cudaFuncAttributeMaxDynamicSharedMemorySize, SMEM_BYTES);
    cudaFuncSetAttribute(gemm_tn<2>, cudaFuncAttributeMaxDynamicSharedMemorySize, SMEM_BYTES);
    cudaFuncSetAttribute(gemm_tn<3>, cudaFuncAttributeMaxDynamicSharedMemorySize, SMEM_BYTES);
    cudaFuncSetAttribute(gemm_tn<4>, cudaFuncAttributeMaxDynamicSharedMemorySize, SMEM_BYTES);

#define GRID(N, zc) dim3(((N) + 127) / 128, Tn / 128, zc)

    // 1. router (exact fp32)
    router_kernel<<<Tn, 128>>>(x, gate_wt, inv, p_soft, p_scal);

    // 1b. deterministic token compaction per group
    compact_kernel<<<Fn, Tn>>>(p_scal, p_cnt, p_tok, p_pos);

    // 2. xe[z,i,h] = x[tok] + soft @ muW^T (compacted)
    {
        size_t cntT = (size_t)Fn * Tn * Hn;
        xe_kernel<<<(int)((cntT + 255) / 256), 256>>>(x, mask_up_W, p_soft, p_cnt, p_tok, p_xe);
    }

    // 3. qb transposes
    tq_kernel<<<(Fn * In * KRn + 255) / 256, 256>>>(gate_qb, p_qbtg, In);
    tq_kernel<<<(Fn * In * KRn + 255) / 256, 256>>>(up_qb, p_qbtu, In);
    tq_kernel<<<(Fn * Hn * KRn + 255) / 256, 256>>>(down_qb, p_qbtd, Hn);

    // 4. gate/up main GEMMs (compacted M)
    gemm_tn<0><<<GRID(In, Fn), 256, SMEM_BYTES>>>(
        p_xe, Hn, (size_t)Tn * Hn, gate_W, Hn, (size_t)In * Hn,
        p_gug, In, (size_t)Tn * In, In, Hn, nullptr, nullptr, nullptr, 0, nullptr, p_cnt, nullptr);
    gemm_tn<0><<<GRID(In, Fn), 256, SMEM_BYTES>>>(
        p_xe, Hn, (size_t)Tn * Hn, up_W, Hn, (size_t)In * Hn,
        p_guu, In, (size_t)Tn * In, In, Hn, nullptr, nullptr, nullptr, 0, nullptr, p_cnt, nullptr);

    // 5. LoRA "a" GEMMs with soft-weight epilogue
    gemm_tn<1><<<GRID(KRn, Fn), 256, SMEM_BYTES>>>(
        p_xe, Hn, (size_t)Tn * Hn, gate_qa, Hn, (size_t)KRn * Hn,
        p_mg, KRn, (size_t)Tn * KRn, KRn, Hn, p_soft, nullptr, nullptr, 0, nullptr, p_cnt, p_tok);
    gemm_tn<1><<<GRID(KRn, Fn), 256, SMEM_BYTES>>>(
        p_xe, Hn, (size_t)Tn * Hn, up_qa, Hn, (size_t)KRn * Hn,
        p_mu, KRn, (size_t)Tn * KRn, KRn, Hn, p_soft, nullptr, nullptr, 0, nullptr, p_cnt, p_tok);

    // 6. mix GEMMs, fused in-place: gu += scale[n] * (m @ qbt^T)
    gemm_tn<2><<<GRID(In, Fn), 256, SMEM_BYTES>>>(
        p_mg, KRn, (size_t)Tn * KRn, p_qbtg, KRn, (size_t)In * KRn,
        p_gug, In, (size_t)Tn * In, In, KRn, nullptr, nullptr, gate_scale, In, nullptr, p_cnt, nullptr);
    gemm_tn<2><<<GRID(In, Fn), 256, SMEM_BYTES>>>(
        p_mu, KRn, (size_t)Tn * KRn, p_qbtu, KRn, (size_t)In * KRn,
        p_guu, In, (size_t)Tn * In, In, KRn, nullptr, nullptr, up_scale, In, nullptr, p_cnt, nullptr);

    // 7. hmid = silu(gate)*up (compacted)
    {
        size_t cntT = (size_t)Fn * Tn * In;
        fuse_kernel<<<(int)((cntT + 255) / 256), 256>>>(p_gug, p_guu, p_cnt, p_hmid);
    }

    // 8. down LoRA a: md = (hmid @ dqa^T) * soft
    gemm_tn<1><<<GRID(KRn, Fn), 256, SMEM_BYTES>>>(
        p_hmid, In, (size_t)Tn * In, down_qa, In, (size_t)KRn * In,
        p_md, KRn, (size_t)Tn * KRn, KRn, In, p_soft, nullptr, nullptr, 0, nullptr, p_cnt, p_tok);

    // 9. mixd = down_scale[n] * (md @ qbtd^T)
    gemm_tn<3><<<GRID(Hn, Fn), 256, SMEM_BYTES>>>(
        p_md, KRn, (size_t)Tn * KRn, p_qbtd, KRn, (size_t)Hn * KRn,
        p_mixd, Hn, (size_t)Tn * Hn, Hn, KRn, nullptr, nullptr, down_scale, Hn, nullptr, p_cnt, nullptr);

    // 10. down GEMM fused: down = scalar[tok,z]*(hmid @ dW^T + mixd)
    gemm_tn<4><<<GRID(Hn, Fn), 256, SMEM_BYTES>>>(
        p_hmid, In, (size_t)Tn * In, down_W, In, (size_t)Hn * In,
        p_down, Hn, (size_t)Tn * Hn, Hn, In, nullptr, p_scal, nullptr, 0, p_mixd, p_cnt, p_tok);

    // 11. shared path (dense)
    gemm_tn<0><<<GRID(ISHn, 1), 256, SMEM_BYTES>>>(
        x, Hn, 0, sh_gate_W, Hn, 0,
        p_shg, ISHn, 0, ISHn, Hn, nullptr, nullptr, nullptr, 0, nullptr, nullptr, nullptr);
    gemm_tn<0><<<GRID(ISHn, 1), 256, SMEM_BYTES>>>(
        x, Hn, 0, sh_up_W, Hn, 0,
        p_shu, ISHn, 0, ISHn, Hn, nullptr, nullptr, nullptr, 0, nullptr, nullptr, nullptr);
    {
        size_t cntT = (size_t)Tn * ISHn;
        swiglu_kernel<<<(int)((cntT + 255) / 256), 256>>>(p_shg, p_shu, p_shm);
    }
    gemm_tn<0><<<GRID(Hn, 1), 256, SMEM_BYTES>>>(
        p_shm, ISHn, 0, sh_down_W, ISHn, 0,
        out, Hn, 0, Hn, ISHn, nullptr, nullptr, nullptr, 0, nullptr, nullptr, nullptr);

    // 12. out += gathered expert outputs
    reduce_kernel<<<(Tn * Hn + 255) / 256, 256>>>(out, p_down, p_pos);

#undef GRID
    (void)in_sizes; (void)n_in; (void)out_size;
}

// round 5
// speedup vs baseline: 1.6094x; 1.6094x over previous
#include <cuda_runtime.h>
#include <cuda_bf16.h>
#include <math.h>
#include <cstdint>

#define Tn 1024
#define Hn 2048
#define In 1408
#define En 64
#define Fn 8
#define Kn 8
#define Rn 8
#define ISHn 2816
#define TOPKn 6
#define KRn 64

// ---------------- scratch (device globals; allocation-free) ----------------
__device__ float g_soft[Tn * Fn * Kn];
__device__ float g_scalar[Tn * Fn];
__device__ int   g_cnt[Fn];
__device__ int   g_tok[Fn * Tn];
__device__ int   g_pos[Fn * Tn];
__device__ float g_xe[(size_t)Fn * Tn * Hn];
__device__ float g_gug[(size_t)Fn * Tn * In];
__device__ float g_guu[(size_t)Fn * Tn * In];
__device__ float g_mg[(size_t)Fn * Tn * KRn];
__device__ float g_mu[(size_t)Fn * Tn * KRn];
__device__ float g_hmid[(size_t)Fn * Tn * In];
__device__ float g_md[(size_t)Fn * Tn * KRn];
__device__ float g_mixd[(size_t)Fn * Tn * Hn];
__device__ float g_down[(size_t)Fn * Tn * Hn];
__device__ float g_qbtg[(size_t)Fn * In * KRn];
__device__ float g_qbtu[(size_t)Fn * In * KRn];
__device__ float g_qbtd[(size_t)Fn * Hn * KRn];
__device__ float g_shg[(size_t)Tn * ISHn];
__device__ float g_shu[(size_t)Tn * ISHn];
__device__ float g_shm[(size_t)Tn * ISHn];
// pre-rounded (tf32 RNA) weight copies
__device__ float g_wg[(size_t)Fn * In * Hn];
__device__ float g_wu[(size_t)Fn * In * Hn];
__device__ float g_wd[(size_t)Fn * Hn * In];
__device__ float g_qag[(size_t)Fn * KRn * Hn];
__device__ float g_qau[(size_t)Fn * KRn * Hn];
__device__ float g_qad[(size_t)Fn * KRn * In];
__device__ float g_shgw[(size_t)ISHn * Hn];
__device__ float g_shuw[(size_t)ISHn * Hn];
__device__ float g_shdw[(size_t)Hn * ISHn];
__device__ float g_xr[(size_t)Tn * Hn];

// ---------------- helpers ----------------
__device__ __forceinline__ float tf32r(float x) {
    float y;
    asm("cvt.rna.tf32.f32 %0, %1;" : "=f"(y) : "f"(x));
    return y;
}
__device__ __forceinline__ uint32_t smem_u32(const void* p) {
    uint32_t a;
    asm("{ .reg .u64 t; cvta.to.shared.u64 t, %1; cvt.u32.u64 %0, t; }" : "=r"(a) : "l"(p));
    return a;
}
__device__ __forceinline__ void cpa16(uint32_t dst, const void* src, bool pred) {
    int sz = pred ? 16 : 0;
    asm volatile("cp.async.cg.shared.global [%0], [%1], 16, %2;"
                 :: "r"(dst), "l"(src), "r"(sz) : "memory");
}
#define CP_COMMIT() asm volatile("cp.async.commit_group;" ::: "memory")
#define CP_WAIT1() asm volatile("cp.async.wait_group 1;" ::: "memory")

#define MMA_TF32(d, a, b)                                                      \
    asm volatile(                                                              \
        "mma.sync.aligned.m16n8k8.row.col.f32.tf32.tf32.f32 "                  \
        "{%0,%1,%2,%3}, {%4,%5,%6,%7}, {%8,%9}, {%0,%1,%2,%3};\n"              \
        : "+f"((d)[0]), "+f"((d)[1]), "+f"((d)[2]), "+f"((d)[3])               \
        : "r"(__float_as_uint((a)[0])), "r"(__float_as_uint((a)[1])),          \
          "r"(__float_as_uint((a)[2])), "r"(__float_as_uint((a)[3])),          \
          "r"(__float_as_uint((b)[0])), "r"(__float_as_uint((b)[1])))

// ---------------- rounding copy (fp32 -> tf32 RNA) ----------------
__global__ void round_copy(const float4* __restrict__ in, float4* __restrict__ out, int n4) {
    int i = blockIdx.x * blockDim.x + threadIdx.x;
    if (i >= n4) return;
    float4 v = in[i];
    v.x = tf32r(v.x); v.y = tf32r(v.y); v.z = tf32r(v.z); v.w = tf32r(v.w);
    out[i] = v;
}

// ---------------- router (exact fp32: top-k must not flip) ----------------
__global__ void router_kernel(const float* __restrict__ x,
                              const float* __restrict__ gw,
                              const int* __restrict__ inv,
                              float* __restrict__ soft,
                              float* __restrict__ scal) {
    __shared__ float xs[Hn];
    __shared__ float sc[En];
    const int t = blockIdx.x;
    const int tid = threadIdx.x;  // 128 threads
    const float4* xv = reinterpret_cast<const float4*>(x + (size_t)t * Hn);
    for (int i = tid; i < Hn / 4; i += 128)
        reinterpret_cast<float4*>(xs)[i] = xv[i];
    __syncthreads();
    const int lane = tid & 31, w = tid >> 5;
    for (int e = w; e < En; e += 4) {
        const float* g = gw + (size_t)e * Hn;
        float s = 0.f;
        for (int h = lane; h < Hn; h += 32) s += xs[h] * g[h];
#pragma unroll
        for (int o = 16; o; o >>= 1) s += __shfl_xor_sync(0xffffffffu, s, o);
        if (lane == 0) sc[e] = s;
    }
    __syncthreads();
    if (tid == 0) {
        float mx = -1e30f;
        for (int e = 0; e < En; e++) mx = fmaxf(mx, sc[e]);
        float p[En];
        float sum = 0.f;
        for (int e = 0; e < En; e++) { p[e] = expf(sc[e] - mx); sum += p[e]; }
        float is = 1.f / sum;
        for (int e = 0; e < En; e++) p[e] *= is;
        float wv[En];
        for (int e = 0; e < En; e++) wv[e] = 0.f;
        for (int j = 0; j < TOPKn; j++) {
            int best = 0;
            float bv = -1.f;
            for (int e = 0; e < En; e++) {
                if (wv[e] == 0.f && p[e] > bv) { bv = p[e]; best = e; }
            }
            wv[best] = p[best];
        }
        for (int f = 0; f < Fn; f++) {
            float fl[Kn];
            float ssum = 0.f, fmx = -1e30f;
            for (int k = 0; k < Kn; k++) {
                int e = inv[f * Kn + k];
                float v = wv[e];
                ssum += v;
                float l = (v == 0.f) ? -1e9f : v;
                fl[k] = l;
                fmx = fmaxf(fmx, l);
            }
            float es = 0.f, ex[Kn];
            for (int k = 0; k < Kn; k++) { ex[k] = expf(fl[k] - fmx); es += ex[k]; }
            float ies = 1.f / es;
            for (int k = 0; k < Kn; k++)
                soft[((size_t)t * Fn + f) * Kn + k] = ex[k] * ies;
            scal[(size_t)t * Fn + f] = ssum;
        }
    }
}

// ---------------- deterministic per-group token compaction ----------------
__global__ void compact_kernel(const float* __restrict__ scal,
                               int* __restrict__ cnt,
                               int* __restrict__ tok,
                               int* __restrict__ pos) {
    const int z = blockIdx.x;
    const int t = threadIdx.x;  // Tn threads
    __shared__ int sbuf[Tn];
    int active = (scal[(size_t)t * Fn + z] != 0.f) ? 1 : 0;
    sbuf[t] = active;
    __syncthreads();
    for (int off = 1; off < Tn; off <<= 1) {
        int v = (t >= off) ? sbuf[t - off] : 0;
        __syncthreads();
        sbuf[t] += v;
        __syncthreads();
    }
    int incl = sbuf[t];
    if (active) {
        tok[z * Tn + incl - 1] = t;
        pos[z * Tn + t] = incl - 1;
    } else {
        pos[z * Tn + t] = -1;
    }
    if (t == Tn - 1) cnt[z] = incl;
}

// ---------------- xe (compacted, tf32-rounded at write) ----------------
__global__ void xe_kernel(const float* __restrict__ x,
                          const float* __restrict__ muW,
                          const float* __restrict__ soft,
                          const int* __restrict__ cnt,
                          const int* __restrict__ tok,
                          float* __restrict__ xe) {
    size_t idx = (size_t)blockIdx.x * blockDim.x + threadIdx.x;
    if (idx >= (size_t)Fn * Tn * Hn) return;
    int z = (int)(idx / ((size_t)Tn * Hn));
    int rem = (int)(idx % ((size_t)Tn * Hn));
    int i = rem / Hn, h = rem % Hn;
    if (i >= cnt[z]) return;
    int t = tok[z * Tn + i];
    const float* mw = muW + ((size_t)z * Hn + h) * Kn;
    const float* sf = soft + ((size_t)t * Fn + z) * Kn;
    float s = x[(size_t)t * Hn + h];
#pragma unroll
    for (int k = 0; k < Kn; k++) s += sf[k] * mw[k];
    xe[idx] = tf32r(s);
}

// ---------------- qb transpose (tf32-rounded) ----------------
__global__ void tq_kernel(const float* __restrict__ qb, float* __restrict__ outp, int Nd) {
    int total = Fn * Nd * KRn;
    int idx = blockIdx.x * blockDim.x + threadIdx.x;
    if (idx >= total) return;
    int z = idx / (Nd * KRn);
    int rem = idx % (Nd * KRn);
    int n = rem >> 6, kr = rem & 63;
    int k = kr >> 3, r = kr & 7;
    outp[idx] = tf32r(qb[(((size_t)z * Kn + k) * Nd + n) * Rn + r]);
}

// ---------------- hmid = silu(gate)*up (tf32-rounded) ----------------
__global__ void fuse_kernel(const float* __restrict__ gg, const float* __restrict__ uu,
                            const int* __restrict__ cnt,
                            float* __restrict__ hm) {
    size_t idx = (size_t)blockIdx.x * blockDim.x + threadIdx.x;
    if (idx >= (size_t)Fn * Tn * In) return;
    int z = (int)(idx / ((size_t)Tn * In));
    int i = (int)((idx % ((size_t)Tn * In)) / In);
    if (i >= cnt[z]) return;
    float g = gg[idx], u = uu[idx];
    hm[idx] = tf32r(g / (1.f + expf(-g)) * u);
}

__global__ void swiglu_kernel(const float* __restrict__ gg, const float* __restrict__ uu,
                              float* __restrict__ hm) {
    size_t idx = (size_t)blockIdx.x * blockDim.x + threadIdx.x;
    if (idx >= (size_t)Tn * ISHn) return;
    float g = gg[idx], u = uu[idx];
    hm[idx] = tf32r(g / (1.f + expf(-g)) * u);
}

// ---------------- out[t] += sum_z active: down[z][pos[z,t]] ----------------
__global__ void reduce_kernel(float* __restrict__ out, const float* __restrict__ down,
                              const int* __restrict__ pos) {
    int idx = blockIdx.x * blockDim.x + threadIdx.x;
    if (idx >= Tn * Hn) return;
    int t = idx / Hn, h = idx % Hn;
    float s = out[idx];
#pragma unroll
    for (int z = 0; z < Fn; z++) {
        int p = pos[z * Tn + t];
        if (p >= 0) s += down[((size_t)z * Tn + p) * Hn + h];
    }
    out[idx] = s;
}

// ---------------- cp.async tf32 GEMM: C[MxN] = A[MxK] * B[NxK]^T ----------------
// Inputs must be pre-rounded to tf32. 3-stage cp.async smem pipeline.
// MODE 0: C=acc
// MODE 1: C=tf32r(acc*soft[tok[r], z, n>>3])
// MODE 2: C=C + colscale[n]*acc
// MODE 3: C=colscale[n]*acc
// MODE 4: C=rowscal[tok[r]*Fn+z]*(acc + mixadd[z,r,n])
#define KC 32
#define SM_LD 36
#define SM_BUF (128 * SM_LD)
#define STAGE_FLOATS (2 * SM_BUF)
#define SMEM_BYTES (3 * STAGE_FLOATS * 4)

template <int MODE>
__global__ void __launch_bounds__(256)
gemm_tn(const float* __restrict__ A, int lda, size_t sA,
        const float* __restrict__ B, int ldb, size_t sB,
        float* __restrict__ C, int ldc, size_t sC,
        int N, int Ktot,
        const float* __restrict__ soft,
        const float* __restrict__ rowscal,
        const float* __restrict__ colscale, size_t sCs,
        const float* __restrict__ mixadd,
        const int* __restrict__ cntp,
        const int* __restrict__ tokp) {
    const int z = blockIdx.z;
    const int Mz = cntp ? cntp[z] : Tn;
    const int bm = blockIdx.y * 128, bn = blockIdx.x * 128;
    if (bm >= Mz) return;
    A += (size_t)z * sA;
    B += (size_t)z * sB;
    C += (size_t)z * sC;
    const float* cs = (MODE == 2 || MODE == 3) ? colscale + (size_t)z * sCs : nullptr;
    const float* mixp = (MODE == 4) ? mixadd + (size_t)z * sC : nullptr;
    const int* tk = (MODE == 1 || MODE == 4) ? tokp + z * Tn : nullptr;

    extern __shared__ float smf[];
    const uint32_t sbase = smem_u32(smf);
    const int tid = threadIdx.x, lane = tid & 31, wid = tid >> 5;
    const int wm = (wid >> 2) * 64, wn = (wid & 3) * 32;

    int arow[4], kq4[4];
#pragma unroll
    for (int i = 0; i < 4; i++) {
        int lin = tid + i * 256;
        arow[i] = lin >> 3;
        kq4[i] = (lin & 7) << 2;
    }
    float acc[4][4][4];
#pragma unroll
    for (int a = 0; a < 4; a++)
#pragma unroll
        for (int b = 0; b < 4; b++)
#pragma unroll
            for (int c = 0; c < 4; c++) acc[a][b][c] = 0.f;

    auto issue = [&](int kt, int s) {
        const int k0 = kt * KC;
#pragma unroll
        for (int i = 0; i < 4; i++) {
            uint32_t da = sbase + (uint32_t)((s * STAGE_FLOATS + arow[i] * SM_LD + kq4[i]) * 4);
            cpa16(da, A + (size_t)(bm + arow[i]) * lda + k0 + kq4[i], bm + arow[i] < Mz);
            uint32_t db = da + (uint32_t)(SM_BUF * 4);
            cpa16(db, B + (size_t)(bn + arow[i]) * ldb + k0 + kq4[i], bn + arow[i] < N);
        }
    };

    const int KT = Ktot / KC;
    // prologue: 2 groups in flight
    issue(0, 0);
    CP_COMMIT();
    if (KT > 1) issue(1, 1);
    CP_COMMIT();

    for (int kt = 0; kt < KT; kt++) {
        CP_WAIT1();          // chunk kt complete
        __syncthreads();     // all warps done with stage being refilled
        if (kt + 2 < KT) issue(kt + 2, (kt + 2) % 3);
        CP_COMMIT();
        const float* Ab = smf + (kt % 3) * STAGE_FLOATS;
        const float* Bb = Ab + SM_BUF;
#pragma unroll
        for (int ks = 0; ks < 4; ks++) {
            int kk = ks * 8 + (lane & 3);
            float a[4][4], b[4][2];
#pragma unroll
            for (int mi = 0; mi < 4; mi++) {
                const float* p = Ab + (wm + mi * 16 + (lane >> 2)) * SM_LD + kk;
                a[mi][0] = p[0];
                a[mi][1] = p[8 * SM_LD];
                a[mi][2] = p[4];
                a[mi][3] = p[8 * SM_LD + 4];
            }
#pragma unroll
            for (int ni = 0; ni < 4; ni++) {
                const float* q = Bb + (wn + ni * 8 + (lane >> 2)) * SM_LD + kk;
                b[ni][0] = q[0];
                b[ni][1] = q[4];
            }
#pragma unroll
            for (int mi = 0; mi < 4; mi++)
#pragma unroll
                for (int ni = 0; ni < 4; ni++) MMA_TF32(acc[mi][ni], a[mi], b[ni]);
        }
    }

    // epilogue
#pragma unroll
    for (int mi = 0; mi < 4; mi++) {
#pragma unroll
        for (int ni = 0; ni < 4; ni++) {
            int cb = bn + wn + ni * 8;
            if (cb >= N) continue;
            int c = cb + ((lane & 3) << 1);
#pragma unroll
            for (int hh = 0; hh < 2; hh++) {
                int r = bm + wm + mi * 16 + (lane >> 2) + hh * 8;
                if (r >= Mz) continue;
                float v0 = acc[mi][ni][hh * 2 + 0];
                float v1 = acc[mi][ni][hh * 2 + 1];
                size_t off = (size_t)r * ldc + c;
                if (MODE == 1) {
                    float s = soft[((size_t)tk[r] * Fn + z) * Kn + (c >> 3)];
                    v0 = tf32r(v0 * s);
                    v1 = tf32r(v1 * s);
                } else if (MODE == 2) {
                    float2 prev = *reinterpret_cast<const float2*>(&C[off]);
                    v0 = prev.x + cs[c] * v0;
                    v1 = prev.y + cs[c + 1] * v1;
                } else if (MODE == 3) {
                    v0 *= cs[c];
                    v1 *= cs[c + 1];
                } else if (MODE == 4) {
                    float rs = rowscal[(size_t)tk[r] * Fn + z];
                    float2 mv = *reinterpret_cast<const float2*>(&mixp[off]);
                    v0 = rs * (v0 + mv.x);
                    v1 = rs * (v1 + mv.y);
                }
                *reinterpret_cast<float2*>(&C[off]) = make_float2(v0, v1);
            }
        }
    }
}

// ---------------- host ----------------
#define SYMP(v, T) ({ void* _p = nullptr; cudaGetSymbolAddress(&_p, v); (T*)_p; })

extern "C" void kernel_launch(void* const* d_in, const int* in_sizes, int n_in,
                              void* d_out, int out_size) {
    const float* x          = (const float*)d_in[0];
    const float* gate_wt    = (const float*)d_in[1];
    const int*   inv        = (const int*)d_in[2];
    const float* mask_up_W  = (const float*)d_in[3];
    const float* gate_W     = (const float*)d_in[4];
    const float* gate_qa    = (const float*)d_in[5];
    const float* gate_qb    = (const float*)d_in[6];
    const float* gate_scale = (const float*)d_in[7];
    const float* up_W       = (const float*)d_in[8];
    const float* up_qa      = (const float*)d_in[9];
    const float* up_qb      = (const float*)d_in[10];
    const float* up_scale   = (const float*)d_in[11];
    const float* down_W     = (const float*)d_in[12];
    const float* down_qa    = (const float*)d_in[13];
    const float* down_qb    = (const float*)d_in[14];
    const float* down_scale = (const float*)d_in[15];
    const float* sh_gate_W  = (const float*)d_in[16];
    const float* sh_up_W    = (const float*)d_in[17];
    const float* sh_down_W  = (const float*)d_in[18];
    float* out = (float*)d_out;

    float* p_soft = SYMP(g_soft, float);
    float* p_scal = SYMP(g_scalar, float);
    int*   p_cnt  = SYMP(g_cnt, int);
    int*   p_tok  = SYMP(g_tok, int);
    int*   p_pos  = SYMP(g_pos, int);
    float* p_xe   = SYMP(g_xe, float);
    float* p_gug  = SYMP(g_gug, float);
    float* p_guu  = SYMP(g_guu, float);
    float* p_mg   = SYMP(g_mg, float);
    float* p_mu   = SYMP(g_mu, float);
    float* p_hmid = SYMP(g_hmid, float);
    float* p_md   = SYMP(g_md, float);
    float* p_mixd = SYMP(g_mixd, float);
    float* p_down = SYMP(g_down, float);
    float* p_qbtg = SYMP(g_qbtg, float);
    float* p_qbtu = SYMP(g_qbtu, float);
    float* p_qbtd = SYMP(g_qbtd, float);
    float* p_shg  = SYMP(g_shg, float);
    float* p_shu  = SYMP(g_shu, float);
    float* p_shm  = SYMP(g_shm, float);
    float* p_wg   = SYMP(g_wg, float);
    float* p_wu   = SYMP(g_wu, float);
    float* p_wd   = SYMP(g_wd, float);
    float* p_qag  = SYMP(g_qag, float);
    float* p_qau  = SYMP(g_qau, float);
    float* p_qad  = SYMP(g_qad, float);
    float* p_shgw = SYMP(g_shgw, float);
    float* p_shuw = SYMP(g_shuw, float);
    float* p_shdw = SYMP(g_shdw, float);
    float* p_xr   = SYMP(g_xr, float);

    cudaFuncSetAttribute(gemm_tn<0>, cudaFuncAttributeMaxDynamicSharedMemorySize, SMEM_BYTES);
    cudaFuncSetAttribute(gemm_tn<1>, cudaFuncAttributeMaxDynamicSharedMemorySize, SMEM_BYTES);
    cudaFuncSetAttribute(gemm_tn<2>, cudaFuncAttributeMaxDynamicSharedMemorySize, SMEM_BYTES);
    cudaFuncSetAttribute(gemm_tn<3>, cudaFuncAttributeMaxDynamicSharedMemorySize, SMEM_BYTES);
    cudaFuncSetAttribute(gemm_tn<4>, cudaFuncAttributeMaxDynamicSharedMemorySize, SMEM_BYTES);

#define RC(src, dst, n) round_copy<<<(int)(((n) / 4 + 255) / 256), 256>>>( \
        (const float4*)(src), (float4*)(dst), (int)((n) / 4))
#define GRID(N, zc) dim3(((N) + 127) / 128, Tn / 128, zc)

    // 0. pre-round weights (independent; amortized across all GEMMs)
    RC(gate_W, p_wg, (size_t)Fn * In * Hn);
    RC(up_W, p_wu, (size_t)Fn * In * Hn);
    RC(down_W, p_wd, (size_t)Fn * Hn * In);
    RC(gate_qa, p_qag, (size_t)Fn * KRn * Hn);
    RC(up_qa, p_qau, (size_t)Fn * KRn * Hn);
    RC(down_qa, p_qad, (size_t)Fn * KRn * In);
    RC(sh_gate_W, p_shgw, (size_t)ISHn * Hn);
    RC(sh_up_W, p_shuw, (size_t)ISHn * Hn);
    RC(sh_down_W, p_shdw, (size_t)Hn * ISHn);
    RC(x, p_xr, (size_t)Tn * Hn);

    // 1. router (exact fp32)
    router_kernel<<<Tn, 128>>>(x, gate_wt, inv, p_soft, p_scal);

    // 1b. deterministic token compaction per group
    compact_kernel<<<Fn, Tn>>>(p_scal, p_cnt, p_tok, p_pos);

    // 2. xe[z,i,h] = tf32r(x[tok] + soft @ muW^T) (compacted)
    {
        size_t cntT = (size_t)Fn * Tn * Hn;
        xe_kernel<<<(int)((cntT + 255) / 256), 256>>>(x, mask_up_W, p_soft, p_cnt, p_tok, p_xe);
    }

    // 3. qb transposes (rounded)
    tq_kernel<<<(Fn * In * KRn + 255) / 256, 256>>>(gate_qb, p_qbtg, In);
    tq_kernel<<<(Fn * In * KRn + 255) / 256, 256>>>(up_qb, p_qbtu, In);
    tq_kernel<<<(Fn * Hn * KRn + 255) / 256, 256>>>(down_qb, p_qbtd, Hn);

    // 4. gate/up main GEMMs (compacted M)
    gemm_tn<0><<<GRID(In, Fn), 256, SMEM_BYTES>>>(
        p_xe, Hn, (size_t)Tn * Hn, p_wg, Hn, (size_t)In * Hn,
        p_gug, In, (size_t)Tn * In, In, Hn, nullptr, nullptr, nullptr, 0, nullptr, p_cnt, nullptr);
    gemm_tn<0><<<GRID(In, Fn), 256, SMEM_BYTES>>>(
        p_xe, Hn, (size_t)Tn * Hn, p_wu, Hn, (size_t)In * Hn,
        p_guu, In, (size_t)Tn * In, In, Hn, nullptr, nullptr, nullptr, 0, nullptr, p_cnt, nullptr);

    // 5. LoRA "a" GEMMs with soft-weight epilogue
    gemm_tn<1><<<GRID(KRn, Fn), 256, SMEM_BYTES>>>(
        p_xe, Hn, (size_t)Tn * Hn, p_qag, Hn, (size_t)KRn * Hn,
        p_mg, KRn, (size_t)Tn * KRn, KRn, Hn, p_soft, nullptr, nullptr, 0, nullptr, p_cnt, p_tok);
    gemm_tn<1><<<GRID(KRn, Fn), 256, SMEM_BYTES>>>(
        p_xe, Hn, (size_t)Tn * Hn, p_qau, Hn, (size_t)KRn * Hn,
        p_mu, KRn, (size_t)Tn * KRn, KRn, Hn, p_soft, nullptr, nullptr, 0, nullptr, p_cnt, p_tok);

    // 6. mix GEMMs, fused in-place: gu += scale[n] * (m @ qbt^T)
    gemm_tn<2><<<GRID(In, Fn), 256, SMEM_BYTES>>>(
        p_mg, KRn, (size_t)Tn * KRn, p_qbtg, KRn, (size_t)In * KRn,
        p_gug, In, (size_t)Tn * In, In, KRn, nullptr, nullptr, gate_scale, In, nullptr, p_cnt, nullptr);
    gemm_tn<2><<<GRID(In, Fn), 256, SMEM_BYTES>>>(
        p_mu, KRn, (size_t)Tn * KRn, p_qbtu, KRn, (size_t)In * KRn,
        p_guu, In, (size_t)Tn * In, In, KRn, nullptr, nullptr, up_scale, In, nullptr, p_cnt, nullptr);

    // 7. hmid = tf32r(silu(gate)*up) (compacted)
    {
        size_t cntT = (size_t)Fn * Tn * In;
        fuse_kernel<<<(int)((cntT + 255) / 256), 256>>>(p_gug, p_guu, p_cnt, p_hmid);
    }

    // 8. down LoRA a: md = tf32r((hmid @ dqa^T) * soft)
    gemm_tn<1><<<GRID(KRn, Fn), 256, SMEM_BYTES>>>(
        p_hmid, In, (size_t)Tn * In, p_qad, In, (size_t)KRn * In,
        p_md, KRn, (size_t)Tn * KRn, KRn, In, p_soft, nullptr, nullptr, 0, nullptr, p_cnt, p_tok);

    // 9. mixd = down_scale[n] * (md @ qbtd^T)
    gemm_tn<3><<<GRID(Hn, Fn), 256, SMEM_BYTES>>>(
        p_md, KRn, (size_t)Tn * KRn, p_qbtd, KRn, (size_t)Hn * KRn,
        p_mixd, Hn, (size_t)Tn * Hn, Hn, KRn, nullptr, nullptr, down_scale, Hn, nullptr, p_cnt, nullptr);

    // 10. down GEMM fused: down = scalar[tok,z]*(hmid @ dW^T + mixd)
    gemm_tn<4><<<GRID(Hn, Fn), 256, SMEM_BYTES>>>(
        p_hmid, In, (size_t)Tn * In, p_wd, In, (size_t)Hn * In,
        p_down, Hn, (size_t)Tn * Hn, Hn, In, nullptr, p_scal, nullptr, 0, p_mixd, p_cnt, p_tok);

    // 11. shared path (dense)
    gemm_tn<0><<<GRID(ISHn, 1), 256, SMEM_BYTES>>>(
        p_xr, Hn, 0, p_shgw, Hn, 0,
        p_shg, ISHn, 0, ISHn, Hn, nullptr, nullptr, nullptr, 0, nullptr, nullptr, nullptr);
    gemm_tn<0><<<GRID(ISHn, 1), 256, SMEM_BYTES>>>(
        p_xr, Hn, 0, p_shuw, Hn, 0,
        p_shu, ISHn, 0, ISHn, Hn, nullptr, nullptr, nullptr, 0, nullptr, nullptr, nullptr);
    {
        size_t cntT = (size_t)Tn * ISHn;
        swiglu_kernel<<<(int)((cntT + 255) / 256), 256>>>(p_shg, p_shu, p_shm);
    }
    gemm_tn<0><<<GRID(Hn, 1), 256, SMEM_BYTES>>>(
        p_shm, ISHn, 0, p_shdw, ISHn, 0,
        out, Hn, 0, Hn, ISHn, nullptr, nullptr, nullptr, 0, nullptr, nullptr, nullptr);

    // 12. out += gathered expert outputs
    reduce_kernel<<<(Tn * Hn + 255) / 256, 256>>>(out, p_down, p_pos);

#undef RC
#undef GRID
    (void)in_sizes; (void)n_in; (void)out_size;
}

// round 6
// speedup vs baseline: 1.7398x; 1.0810x over previous
#include <cuda_runtime.h>
#include <cuda_bf16.h>
#include <math.h>
#include <cstdint>

#define Tn 1024
#define Hn 2048
#define In 1408
#define En 64
#define Fn 8
#define Kn 8
#define Rn 8
#define ISHn 2816
#define TOPKn 6
#define KRn 64

// ---------------- scratch (device globals; allocation-free) ----------------
__device__ float g_soft[Tn * Fn * Kn];
__device__ float g_scalar[Tn * Fn];
__device__ int   g_cnt[Fn];
__device__ int   g_tok[Fn * Tn];
__device__ int   g_pos[Fn * Tn];
__device__ float g_xe[(size_t)Fn * Tn * Hn];
__device__ float g_gug[(size_t)Fn * Tn * In];
__device__ float g_guu[(size_t)Fn * Tn * In];
__device__ float g_mg[(size_t)Fn * Tn * KRn];
__device__ float g_mu[(size_t)Fn * Tn * KRn];
__device__ float g_hmid[(size_t)Fn * Tn * In];
__device__ float g_md[(size_t)Fn * Tn * KRn];
__device__ float g_mixd[(size_t)Fn * Tn * Hn];
__device__ float g_down[(size_t)Fn * Tn * Hn];
__device__ float g_qbtg[(size_t)Fn * In * KRn];
__device__ float g_qbtu[(size_t)Fn * In * KRn];
__device__ float g_qbtd[(size_t)Fn * Hn * KRn];
__device__ float g_shg[(size_t)Tn * ISHn];
__device__ float g_shu[(size_t)Tn * ISHn];
__device__ float g_shm[(size_t)Tn * ISHn];
// pre-rounded (tf32 RNA) weight copies
__device__ float g_wg[(size_t)Fn * In * Hn];
__device__ float g_wu[(size_t)Fn * In * Hn];
__device__ float g_wd[(size_t)Fn * Hn * In];
__device__ float g_qag[(size_t)Fn * KRn * Hn];
__device__ float g_qau[(size_t)Fn * KRn * Hn];
__device__ float g_qad[(size_t)Fn * KRn * In];
__device__ float g_shgw[(size_t)ISHn * Hn];
__device__ float g_shuw[(size_t)ISHn * Hn];
__device__ float g_shdw[(size_t)Hn * ISHn];
__device__ float g_xr[(size_t)Tn * Hn];

// ---------------- helpers ----------------
__device__ __forceinline__ float tf32r(float x) {
    float y;
    asm("cvt.rna.tf32.f32 %0, %1;" : "=f"(y) : "f"(x));
    return y;
}
__device__ __forceinline__ uint32_t smem_u32(const void* p) {
    uint32_t a;
    asm("{ .reg .u64 t; cvta.to.shared.u64 t, %1; cvt.u32.u64 %0, t; }" : "=r"(a) : "l"(p));
    return a;
}
__device__ __forceinline__ void cpa16(uint32_t dst, const void* src, bool pred) {
    int sz = pred ? 16 : 0;
    asm volatile("cp.async.cg.shared.global [%0], [%1], 16, %2;"
                 :: "r"(dst), "l"(src), "r"(sz) : "memory");
}
#define CP_COMMIT() asm volatile("cp.async.commit_group;" ::: "memory")
#define CP_WAIT1() asm volatile("cp.async.wait_group 1;" ::: "memory")

#define MMA_TF32(d, a, b)                                                      \
    asm volatile(                                                              \
        "mma.sync.aligned.m16n8k8.row.col.f32.tf32.tf32.f32 "                  \
        "{%0,%1,%2,%3}, {%4,%5,%6,%7}, {%8,%9}, {%0,%1,%2,%3};\n"              \
        : "+f"((d)[0]), "+f"((d)[1]), "+f"((d)[2]), "+f"((d)[3])               \
        : "r"(__float_as_uint((a)[0])), "r"(__float_as_uint((a)[1])),          \
          "r"(__float_as_uint((a)[2])), "r"(__float_as_uint((a)[3])),          \
          "r"(__float_as_uint((b)[0])), "r"(__float_as_uint((b)[1])))

// ---------------- rounding copy (fp32 -> tf32 RNA) ----------------
__global__ void round_copy(const float4* __restrict__ in, float4* __restrict__ out, int n4) {
    int i = blockIdx.x * blockDim.x + threadIdx.x;
    if (i >= n4) return;
    float4 v = in[i];
    v.x = tf32r(v.x); v.y = tf32r(v.y); v.z = tf32r(v.z); v.w = tf32r(v.w);
    out[i] = v;
}

// ---------------- router (exact fp32: top-k must not flip) ----------------
__global__ void router_kernel(const float* __restrict__ x,
                              const float* __restrict__ gw,
                              const int* __restrict__ inv,
                              float* __restrict__ soft,
                              float* __restrict__ scal) {
    __shared__ float xs[Hn];
    __shared__ float sc[En];
    const int t = blockIdx.x;
    const int tid = threadIdx.x;  // 128 threads
    const float4* xv = reinterpret_cast<const float4*>(x + (size_t)t * Hn);
    for (int i = tid; i < Hn / 4; i += 128)
        reinterpret_cast<float4*>(xs)[i] = xv[i];
    __syncthreads();
    const int lane = tid & 31, w = tid >> 5;
    for (int e = w; e < En; e += 4) {
        const float* g = gw + (size_t)e * Hn;
        float s = 0.f;
        for (int h = lane; h < Hn; h += 32) s += xs[h] * g[h];
#pragma unroll
        for (int o = 16; o; o >>= 1) s += __shfl_xor_sync(0xffffffffu, s, o);
        if (lane == 0) sc[e] = s;
    }
    __syncthreads();
    if (tid == 0) {
        float mx = -1e30f;
        for (int e = 0; e < En; e++) mx = fmaxf(mx, sc[e]);
        float p[En];
        float sum = 0.f;
        for (int e = 0; e < En; e++) { p[e] = expf(sc[e] - mx); sum += p[e]; }
        float is = 1.f / sum;
        for (int e = 0; e < En; e++) p[e] *= is;
        float wv[En];
        for (int e = 0; e < En; e++) wv[e] = 0.f;
        for (int j = 0; j < TOPKn; j++) {
            int best = 0;
            float bv = -1.f;
            for (int e = 0; e < En; e++) {
                if (wv[e] == 0.f && p[e] > bv) { bv = p[e]; best = e; }
            }
            wv[best] = p[best];
        }
        for (int f = 0; f < Fn; f++) {
            float fl[Kn];
            float ssum = 0.f, fmx = -1e30f;
            for (int k = 0; k < Kn; k++) {
                int e = inv[f * Kn + k];
                float v = wv[e];
                ssum += v;
                float l = (v == 0.f) ? -1e9f : v;
                fl[k] = l;
                fmx = fmaxf(fmx, l);
            }
            float es = 0.f, ex[Kn];
            for (int k = 0; k < Kn; k++) { ex[k] = expf(fl[k] - fmx); es += ex[k]; }
            float ies = 1.f / es;
            for (int k = 0; k < Kn; k++)
                soft[((size_t)t * Fn + f) * Kn + k] = ex[k] * ies;
            scal[(size_t)t * Fn + f] = ssum;
        }
    }
}

// ---------------- deterministic per-group token compaction ----------------
__global__ void compact_kernel(const float* __restrict__ scal,
                               int* __restrict__ cnt,
                               int* __restrict__ tok,
                               int* __restrict__ pos) {
    const int z = blockIdx.x;
    const int t = threadIdx.x;  // Tn threads
    __shared__ int sbuf[Tn];
    int active = (scal[(size_t)t * Fn + z] != 0.f) ? 1 : 0;
    sbuf[t] = active;
    __syncthreads();
    for (int off = 1; off < Tn; off <<= 1) {
        int v = (t >= off) ? sbuf[t - off] : 0;
        __syncthreads();
        sbuf[t] += v;
        __syncthreads();
    }
    int incl = sbuf[t];
    if (active) {
        tok[z * Tn + incl - 1] = t;
        pos[z * Tn + t] = incl - 1;
    } else {
        pos[z * Tn + t] = -1;
    }
    if (t == Tn - 1) cnt[z] = incl;
}

// ---------------- xe (compacted, tf32-rounded at write) ----------------
__global__ void xe_kernel(const float* __restrict__ x,
                          const float* __restrict__ muW,
                          const float* __restrict__ soft,
                          const int* __restrict__ cnt,
                          const int* __restrict__ tok,
                          float* __restrict__ xe) {
    size_t idx = (size_t)blockIdx.x * blockDim.x + threadIdx.x;
    if (idx >= (size_t)Fn * Tn * Hn) return;
    int z = (int)(idx / ((size_t)Tn * Hn));
    int rem = (int)(idx % ((size_t)Tn * Hn));
    int i = rem / Hn, h = rem % Hn;
    if (i >= cnt[z]) return;
    int t = tok[z * Tn + i];
    const float* mw = muW + ((size_t)z * Hn + h) * Kn;
    const float* sf = soft + ((size_t)t * Fn + z) * Kn;
    float s = x[(size_t)t * Hn + h];
#pragma unroll
    for (int k = 0; k < Kn; k++) s += sf[k] * mw[k];
    xe[idx] = tf32r(s);
}

// ---------------- qb transpose (tf32-rounded) ----------------
__global__ void tq_kernel(const float* __restrict__ qb, float* __restrict__ outp, int Nd) {
    int total = Fn * Nd * KRn;
    int idx = blockIdx.x * blockDim.x + threadIdx.x;
    if (idx >= total) return;
    int z = idx / (Nd * KRn);
    int rem = idx % (Nd * KRn);
    int n = rem >> 6, kr = rem & 63;
    int k = kr >> 3, r = kr & 7;
    outp[idx] = tf32r(qb[(((size_t)z * Kn + k) * Nd + n) * Rn + r]);
}

// ---------------- hmid = silu(gate)*up (tf32-rounded) ----------------
__global__ void fuse_kernel(const float* __restrict__ gg, const float* __restrict__ uu,
                            const int* __restrict__ cnt,
                            float* __restrict__ hm) {
    size_t idx = (size_t)blockIdx.x * blockDim.x + threadIdx.x;
    if (idx >= (size_t)Fn * Tn * In) return;
    int z = (int)(idx / ((size_t)Tn * In));
    int i = (int)((idx % ((size_t)Tn * In)) / In);
    if (i >= cnt[z]) return;
    float g = gg[idx], u = uu[idx];
    hm[idx] = tf32r(g / (1.f + expf(-g)) * u);
}

__global__ void swiglu_kernel(const float* __restrict__ gg, const float* __restrict__ uu,
                              float* __restrict__ hm) {
    size_t idx = (size_t)blockIdx.x * blockDim.x + threadIdx.x;
    if (idx >= (size_t)Tn * ISHn) return;
    float g = gg[idx], u = uu[idx];
    hm[idx] = tf32r(g / (1.f + expf(-g)) * u);
}

// ---------------- out[t] += sum_z active: down[z][pos[z,t]] ----------------
__global__ void reduce_kernel(float* __restrict__ out, const float* __restrict__ down,
                              const int* __restrict__ pos) {
    int idx = blockIdx.x * blockDim.x + threadIdx.x;
    if (idx >= Tn * Hn) return;
    int t = idx / Hn, h = idx % Hn;
    float s = out[idx];
#pragma unroll
    for (int z = 0; z < Fn; z++) {
        int p = pos[z * Tn + t];
        if (p >= 0) s += down[((size_t)z * Tn + p) * Hn + h];
    }
    out[idx] = s;
}

// ---------------- cp.async tf32 GEMM: C[MxN] = A[MxK] * B[NxK]^T ----------------
// Inputs must be pre-rounded to tf32. 3-stage cp.async smem pipeline.
// __launch_bounds__(256, 2): 2 CTAs/SM (221 KB smem, <=128 regs) so one CTA's
// MMA stream covers the other's wait/sync bubbles.
// MODE 0: C=acc
// MODE 1: C=tf32r(acc*soft[tok[r], z, n>>3])
// MODE 2: C=C + colscale[n]*acc
// MODE 3: C=colscale[n]*acc
// MODE 4: C=rowscal[tok[r]*Fn+z]*(acc + mixadd[z,r,n])
#define KC 32
#define SM_LD 36
#define SM_BUF (128 * SM_LD)
#define STAGE_FLOATS (2 * SM_BUF)
#define SMEM_BYTES (3 * STAGE_FLOATS * 4)

template <int MODE>
__global__ void __launch_bounds__(256, 2)
gemm_tn(const float* __restrict__ A, int lda, size_t sA,
        const float* __restrict__ B, int ldb, size_t sB,
        float* __restrict__ C, int ldc, size_t sC,
        int N, int Ktot,
        const float* __restrict__ soft,
        const float* __restrict__ rowscal,
        const float* __restrict__ colscale, size_t sCs,
        const float* __restrict__ mixadd,
        const int* __restrict__ cntp,
        const int* __restrict__ tokp) {
    const int z = blockIdx.z;
    const int Mz = cntp ? cntp[z] : Tn;
    const int bm = blockIdx.y * 128, bn = blockIdx.x * 128;
    if (bm >= Mz) return;
    A += (size_t)z * sA;
    B += (size_t)z * sB;
    C += (size_t)z * sC;
    const float* cs = (MODE == 2 || MODE == 3) ? colscale + (size_t)z * sCs : nullptr;
    const float* mixp = (MODE == 4) ? mixadd + (size_t)z * sC : nullptr;
    const int* tk = (MODE == 1 || MODE == 4) ? tokp + z * Tn : nullptr;

    extern __shared__ float smf[];
    const uint32_t sbase = smem_u32(smf);
    const int tid = threadIdx.x, lane = tid & 31, wid = tid >> 5;
    const int wm = (wid >> 2) * 64, wn = (wid & 3) * 32;

    int arow[4], kq4[4];
#pragma unroll
    for (int i = 0; i < 4; i++) {
        int lin = tid + i * 256;
        arow[i] = lin >> 3;
        kq4[i] = (lin & 7) << 2;
    }
    float acc[4][4][4];
#pragma unroll
    for (int a = 0; a < 4; a++)
#pragma unroll
        for (int b = 0; b < 4; b++)
#pragma unroll
            for (int c = 0; c < 4; c++) acc[a][b][c] = 0.f;

    auto issue = [&](int kt, int s) {
        const int k0 = kt * KC;
#pragma unroll
        for (int i = 0; i < 4; i++) {
            uint32_t da = sbase + (uint32_t)((s * STAGE_FLOATS + arow[i] * SM_LD + kq4[i]) * 4);
            cpa16(da, A + (size_t)(bm + arow[i]) * lda + k0 + kq4[i], bm + arow[i] < Mz);
            uint32_t db = da + (uint32_t)(SM_BUF * 4);
            cpa16(db, B + (size_t)(bn + arow[i]) * ldb + k0 + kq4[i], bn + arow[i] < N);
        }
    };

    const int KT = Ktot / KC;
    // prologue: 2 groups in flight
    issue(0, 0);
    CP_COMMIT();
    if (KT > 1) issue(1, 1);
    CP_COMMIT();

    for (int kt = 0; kt < KT; kt++) {
        CP_WAIT1();          // chunk kt complete
        __syncthreads();     // all warps done with stage being refilled
        if (kt + 2 < KT) issue(kt + 2, (kt + 2) % 3);
        CP_COMMIT();
        const float* Ab = smf + (kt % 3) * STAGE_FLOATS;
        const float* Bb = Ab + SM_BUF;
#pragma unroll
        for (int ks = 0; ks < 4; ks++) {
            int kk = ks * 8 + (lane & 3);
            float a[4][4], b[4][2];
#pragma unroll
            for (int mi = 0; mi < 4; mi++) {
                const float* p = Ab + (wm + mi * 16 + (lane >> 2)) * SM_LD + kk;
                a[mi][0] = p[0];
                a[mi][1] = p[8 * SM_LD];
                a[mi][2] = p[4];
                a[mi][3] = p[8 * SM_LD + 4];
            }
#pragma unroll
            for (int ni = 0; ni < 4; ni++) {
                const float* q = Bb + (wn + ni * 8 + (lane >> 2)) * SM_LD + kk;
                b[ni][0] = q[0];
                b[ni][1] = q[4];
            }
#pragma unroll
            for (int mi = 0; mi < 4; mi++)
#pragma unroll
                for (int ni = 0; ni < 4; ni++) MMA_TF32(acc[mi][ni], a[mi], b[ni]);
        }
    }

    // epilogue
#pragma unroll
    for (int mi = 0; mi < 4; mi++) {
#pragma unroll
        for (int ni = 0; ni < 4; ni++) {
            int cb = bn + wn + ni * 8;
            if (cb >= N) continue;
            int c = cb + ((lane & 3) << 1);
#pragma unroll
            for (int hh = 0; hh < 2; hh++) {
                int r = bm + wm + mi * 16 + (lane >> 2) + hh * 8;
                if (r >= Mz) continue;
                float v0 = acc[mi][ni][hh * 2 + 0];
                float v1 = acc[mi][ni][hh * 2 + 1];
                size_t off = (size_t)r * ldc + c;
                if (MODE == 1) {
                    float s = soft[((size_t)tk[r] * Fn + z) * Kn + (c >> 3)];
                    v0 = tf32r(v0 * s);
                    v1 = tf32r(v1 * s);
                } else if (MODE == 2) {
                    float2 prev = *reinterpret_cast<const float2*>(&C[off]);
                    v0 = prev.x + cs[c] * v0;
                    v1 = prev.y + cs[c + 1] * v1;
                } else if (MODE == 3) {
                    v0 *= cs[c];
                    v1 *= cs[c + 1];
                } else if (MODE == 4) {
                    float rs = rowscal[(size_t)tk[r] * Fn + z];
                    float2 mv = *reinterpret_cast<const float2*>(&mixp[off]);
                    v0 = rs * (v0 + mv.x);
                    v1 = rs * (v1 + mv.y);
                }
                *reinterpret_cast<float2*>(&C[off]) = make_float2(v0, v1);
            }
        }
    }
}

// ---------------- host ----------------
#define SYMP(v, T) ({ void* _p = nullptr; cudaGetSymbolAddress(&_p, v); (T*)_p; })

extern "C" void kernel_launch(void* const* d_in, const int* in_sizes, int n_in,
                              void* d_out, int out_size) {
    const float* x          = (const float*)d_in[0];
    const float* gate_wt    = (const float*)d_in[1];
    const int*   inv        = (const int*)d_in[2];
    const float* mask_up_W  = (const float*)d_in[3];
    const float* gate_W     = (const float*)d_in[4];
    const float* gate_qa    = (const float*)d_in[5];
    const float* gate_qb    = (const float*)d_in[6];
    const float* gate_scale = (const float*)d_in[7];
    const float* up_W       = (const float*)d_in[8];
    const float* up_qa      = (const float*)d_in[9];
    const float* up_qb      = (const float*)d_in[10];
    const float* up_scale   = (const float*)d_in[11];
    const float* down_W     = (const float*)d_in[12];
    const float* down_qa    = (const float*)d_in[13];
    const float* down_qb    = (const float*)d_in[14];
    const float* down_scale = (const float*)d_in[15];
    const float* sh_gate_W  = (const float*)d_in[16];
    const float* sh_up_W    = (const float*)d_in[17];
    const float* sh_down_W  = (const float*)d_in[18];
    float* out = (float*)d_out;

    float* p_soft = SYMP(g_soft, float);
    float* p_scal = SYMP(g_scalar, float);
    int*   p_cnt  = SYMP(g_cnt, int);
    int*   p_tok  = SYMP(g_tok, int);
    int*   p_pos  = SYMP(g_pos, int);
    float* p_xe   = SYMP(g_xe, float);
    float* p_gug  = SYMP(g_gug, float);
    float* p_guu  = SYMP(g_guu, float);
    float* p_mg   = SYMP(g_mg, float);
    float* p_mu   = SYMP(g_mu, float);
    float* p_hmid = SYMP(g_hmid, float);
    float* p_md   = SYMP(g_md, float);
    float* p_mixd = SYMP(g_mixd, float);
    float* p_down = SYMP(g_down, float);
    float* p_qbtg = SYMP(g_qbtg, float);
    float* p_qbtu = SYMP(g_qbtu, float);
    float* p_qbtd = SYMP(g_qbtd, float);
    float* p_shg  = SYMP(g_shg, float);
    float* p_shu  = SYMP(g_shu, float);
    float* p_shm  = SYMP(g_shm, float);
    float* p_wg   = SYMP(g_wg, float);
    float* p_wu   = SYMP(g_wu, float);
    float* p_wd   = SYMP(g_wd, float);
    float* p_qag  = SYMP(g_qag, float);
    float* p_qau  = SYMP(g_qau, float);
    float* p_qad  = SYMP(g_qad, float);
    float* p_shgw = SYMP(g_shgw, float);
    float* p_shuw = SYMP(g_shuw, float);
    float* p_shdw = SYMP(g_shdw, float);
    float* p_xr   = SYMP(g_xr, float);

#define SETUP(M)                                                                          \
    cudaFuncSetAttribute(gemm_tn<M>, cudaFuncAttributeMaxDynamicSharedMemorySize,         \
                         SMEM_BYTES);                                                     \
    cudaFuncSetAttribute(gemm_tn<M>, cudaFuncAttributePreferredSharedMemoryCarveout, 100)
    SETUP(0); SETUP(1); SETUP(2); SETUP(3); SETUP(4);
#undef SETUP

#define RC(src, dst, n) round_copy<<<(int)(((n) / 4 + 255) / 256), 256>>>( \
        (const float4*)(src), (float4*)(dst), (int)((n) / 4))
#define GRID(N, zc) dim3(((N) + 127) / 128, Tn / 128, zc)

    // 0. pre-round weights (independent; amortized across all GEMMs)
    RC(gate_W, p_wg, (size_t)Fn * In * Hn);
    RC(up_W, p_wu, (size_t)Fn * In * Hn);
    RC(down_W, p_wd, (size_t)Fn * Hn * In);
    RC(gate_qa, p_qag, (size_t)Fn * KRn * Hn);
    RC(up_qa, p_qau, (size_t)Fn * KRn * Hn);
    RC(down_qa, p_qad, (size_t)Fn * KRn * In);
    RC(sh_gate_W, p_shgw, (size_t)ISHn * Hn);
    RC(sh_up_W, p_shuw, (size_t)ISHn * Hn);
    RC(sh_down_W, p_shdw, (size_t)Hn * ISHn);
    RC(x, p_xr, (size_t)Tn * Hn);

    // 1. router (exact fp32)
    router_kernel<<<Tn, 128>>>(x, gate_wt, inv, p_soft, p_scal);

    // 1b. deterministic token compaction per group
    compact_kernel<<<Fn, Tn>>>(p_scal, p_cnt, p_tok, p_pos);

    // 2. xe[z,i,h] = tf32r(x[tok] + soft @ muW^T) (compacted)
    {
        size_t cntT = (size_t)Fn * Tn * Hn;
        xe_kernel<<<(int)((cntT + 255) / 256), 256>>>(x, mask_up_W, p_soft, p_cnt, p_tok, p_xe);
    }

    // 3. qb transposes (rounded)
    tq_kernel<<<(Fn * In * KRn + 255) / 256, 256>>>(gate_qb, p_qbtg, In);
    tq_kernel<<<(Fn * In * KRn + 255) / 256, 256>>>(up_qb, p_qbtu, In);
    tq_kernel<<<(Fn * Hn * KRn + 255) / 256, 256>>>(down_qb, p_qbtd, Hn);

    // 4. gate/up main GEMMs (compacted M)
    gemm_tn<0><<<GRID(In, Fn), 256, SMEM_BYTES>>>(
        p_xe, Hn, (size_t)Tn * Hn, p_wg, Hn, (size_t)In * Hn,
        p_gug, In, (size_t)Tn * In, In, Hn, nullptr, nullptr, nullptr, 0, nullptr, p_cnt, nullptr);
    gemm_tn<0><<<GRID(In, Fn), 256, SMEM_BYTES>>>(
        p_xe, Hn, (size_t)Tn * Hn, p_wu, Hn, (size_t)In * Hn,
        p_guu, In, (size_t)Tn * In, In, Hn, nullptr, nullptr, nullptr, 0, nullptr, p_cnt, nullptr);

    // 5. LoRA "a" GEMMs with soft-weight epilogue
    gemm_tn<1><<<GRID(KRn, Fn), 256, SMEM_BYTES>>>(
        p_xe, Hn, (size_t)Tn * Hn, p_qag, Hn, (size_t)KRn * Hn,
        p_mg, KRn, (size_t)Tn * KRn, KRn, Hn, p_soft, nullptr, nullptr, 0, nullptr, p_cnt, p_tok);
    gemm_tn<1><<<GRID(KRn, Fn), 256, SMEM_BYTES>>>(
        p_xe, Hn, (size_t)Tn * Hn, p_qau, Hn, (size_t)KRn * Hn,
        p_mu, KRn, (size_t)Tn * KRn, KRn, Hn, p_soft, nullptr, nullptr, 0, nullptr, p_cnt, p_tok);

    // 6. mix GEMMs, fused in-place: gu += scale[n] * (m @ qbt^T)
    gemm_tn<2><<<GRID(In, Fn), 256, SMEM_BYTES>>>(
        p_mg, KRn, (size_t)Tn * KRn, p_qbtg, KRn, (size_t)In * KRn,
        p_gug, In, (size_t)Tn * In, In, KRn, nullptr, nullptr, gate_scale, In, nullptr, p_cnt, nullptr);
    gemm_tn<2><<<GRID(In, Fn), 256, SMEM_BYTES>>>(
        p_mu, KRn, (size_t)Tn * KRn, p_qbtu, KRn, (size_t)In * KRn,
        p_guu, In, (size_t)Tn * In, In, KRn, nullptr, nullptr, up_scale, In, nullptr, p_cnt, nullptr);

    // 7. hmid = tf32r(silu(gate)*up) (compacted)
    {
        size_t cntT = (size_t)Fn * Tn * In;
        fuse_kernel<<<(int)((cntT + 255) / 256), 256>>>(p_gug, p_guu, p_cnt, p_hmid);
    }

    // 8. down LoRA a: md = tf32r((hmid @ dqa^T) * soft)
    gemm_tn<1><<<GRID(KRn, Fn), 256, SMEM_BYTES>>>(
        p_hmid, In, (size_t)Tn * In, p_qad, In, (size_t)KRn * In,
        p_md, KRn, (size_t)Tn * KRn, KRn, In, p_soft, nullptr, nullptr, 0, nullptr, p_cnt, p_tok);

    // 9. mixd = down_scale[n] * (md @ qbtd^T)
    gemm_tn<3><<<GRID(Hn, Fn), 256, SMEM_BYTES>>>(
        p_md, KRn, (size_t)Tn * KRn, p_qbtd, KRn, (size_t)Hn * KRn,
        p_mixd, Hn, (size_t)Tn * Hn, Hn, KRn, nullptr, nullptr, down_scale, Hn, nullptr, p_cnt, nullptr);

    // 10. down GEMM fused: down = scalar[tok,z]*(hmid @ dW^T + mixd)
    gemm_tn<4><<<GRID(Hn, Fn), 256, SMEM_BYTES>>>(
        p_hmid, In, (size_t)Tn * In, p_wd, In, (size_t)Hn * In,
        p_down, Hn, (size_t)Tn * Hn, Hn, In, nullptr, p_scal, nullptr, 0, p_mixd, p_cnt, p_tok);

    // 11. shared path (dense)
    gemm_tn<0><<<GRID(ISHn, 1), 256, SMEM_BYTES>>>(
        p_xr, Hn, 0, p_shgw, Hn, 0,
        p_shg, ISHn, 0, ISHn, Hn, nullptr, nullptr, nullptr, 0, nullptr, nullptr, nullptr);
    gemm_tn<0><<<GRID(ISHn, 1), 256, SMEM_BYTES>>>(
        p_xr, Hn, 0, p_shuw, Hn, 0,
        p_shu, ISHn, 0, ISHn, Hn, nullptr, nullptr, nullptr, 0, nullptr, nullptr, nullptr);
    {
        size_t cntT = (size_t)Tn * ISHn;
        swiglu_kernel<<<(int)((cntT + 255) / 256), 256>>>(p_shg, p_shu, p_shm);
    }
    gemm_tn<0><<<GRID(Hn, 1), 256, SMEM_BYTES>>>(
        p_shm, ISHn, 0, p_shdw, ISHn, 0,
        out, Hn, 0, Hn, ISHn, nullptr, nullptr, nullptr, 0, nullptr, nullptr, nullptr);

    // 12. out += gathered expert outputs
    reduce_kernel<<<(Tn * Hn + 255) / 256, 256>>>(out, p_down, p_pos);

#undef RC
#undef GRID
    (void)in_sizes; (void)n_in; (void)out_size;
}

// round 7
// speedup vs baseline: 1.8999x; 1.0920x over previous
#include <cuda_runtime.h>
#include <cuda_bf16.h>
#include <math.h>
#include <cstdint>

#define Tn 1024
#define Hn 2048
#define In 1408
#define IGU 2816            // 2*In (gate||up concat)
#define En 64
#define Fn 8
#define Kn 8
#define Rn 8
#define ISHn 2816
#define SH2 5632            // 2*ISHn
#define TOPKn 6
#define KRn 64

// ---------------- scratch (device globals; allocation-free) ----------------
__device__ float g_soft[Tn * Fn * Kn];
__device__ float g_scalar[Tn * Fn];
__device__ int   g_cnt[Fn];
__device__ int   g_tok[Fn * Tn];
__device__ int   g_pos[Fn * Tn];
__device__ float g_xe[(size_t)Fn * Tn * Hn];
__device__ float g_gu[(size_t)Fn * Tn * IGU];      // gate||up outputs
__device__ float g_mgu[(size_t)Fn * Tn * 128];     // LoRA-a gate||up
__device__ float g_hmid[(size_t)Fn * Tn * In];
__device__ float g_md[(size_t)Fn * Tn * KRn];
__device__ float g_mixd[(size_t)Fn * Tn * Hn];
__device__ float g_down[(size_t)Fn * Tn * Hn];
__device__ float g_qbtgu[(size_t)Fn * IGU * 128];  // block-diag [qbtg 0; 0 qbtu]
__device__ float g_qbtd[(size_t)Fn * Hn * KRn];
__device__ float g_shgu[(size_t)Tn * SH2];
__device__ float g_shm[(size_t)Tn * ISHn];
// pre-rounded (tf32 RNA) weights
__device__ float g_wgu[(size_t)Fn * IGU * Hn];     // gate_W||up_W
__device__ float g_wd[(size_t)Fn * Hn * In];
__device__ float g_qagu[(size_t)Fn * 128 * Hn];    // gate_qa||up_qa
__device__ float g_qad[(size_t)Fn * KRn * In];
__device__ float g_sgu[Fn * IGU];                  // gate_scale||up_scale (fp32)
__device__ float g_shguw[(size_t)SH2 * Hn];        // sh_gate_W||sh_up_W
__device__ float g_shdw[(size_t)Hn * ISHn];
__device__ float g_xr[(size_t)Tn * Hn];

// ---------------- helpers ----------------
__device__ __forceinline__ float tf32r(float x) {
    float y;
    asm("cvt.rna.tf32.f32 %0, %1;" : "=f"(y) : "f"(x));
    return y;
}
__device__ __forceinline__ uint32_t smem_u32(const void* p) {
    uint32_t a;
    asm("{ .reg .u64 t; cvta.to.shared.u64 t, %1; cvt.u32.u64 %0, t; }" : "=r"(a) : "l"(p));
    return a;
}
__device__ __forceinline__ void cpa16(uint32_t dst, const void* src, bool pred) {
    int sz = pred ? 16 : 0;
    asm volatile("cp.async.cg.shared.global [%0], [%1], 16, %2;"
                 :: "r"(dst), "l"(src), "r"(sz) : "memory");
}
#define CP_COMMIT() asm volatile("cp.async.commit_group;" ::: "memory")
#define CP_WAIT1() asm volatile("cp.async.wait_group 1;" ::: "memory")

#define MMA_TF32(d, a, b)                                                      \
    asm volatile(                                                              \
        "mma.sync.aligned.m16n8k8.row.col.f32.tf32.tf32.f32 "                  \
        "{%0,%1,%2,%3}, {%4,%5,%6,%7}, {%8,%9}, {%0,%1,%2,%3};\n"              \
        : "+f"((d)[0]), "+f"((d)[1]), "+f"((d)[2]), "+f"((d)[3])               \
        : "r"(__float_as_uint((a)[0])), "r"(__float_as_uint((a)[1])),          \
          "r"(__float_as_uint((a)[2])), "r"(__float_as_uint((a)[3])),          \
          "r"(__float_as_uint((b)[0])), "r"(__float_as_uint((b)[1])))

// ---------------- rounding copies ----------------
__global__ void round_copy(const float4* __restrict__ in, float4* __restrict__ out, int n4) {
    int i = blockIdx.x * blockDim.x + threadIdx.x;
    if (i >= n4) return;
    float4 v = in[i];
    v.x = tf32r(v.x); v.y = tf32r(v.y); v.z = tf32r(v.z); v.w = tf32r(v.w);
    out[i] = v;
}
// strided-dest rounding copy: out[z*zs4 + off4 + r] = rna(in[z*n4z + r])
__global__ void rc_off(const float4* __restrict__ in, float4* __restrict__ out,
                       int n4z, int zs4, int off4, int nz) {
    int i = blockIdx.x * blockDim.x + threadIdx.x;
    if (i >= nz * n4z) return;
    int z = i / n4z, r = i % n4z;
    float4 v = in[i];
    v.x = tf32r(v.x); v.y = tf32r(v.y); v.z = tf32r(v.z); v.w = tf32r(v.w);
    out[(size_t)z * zs4 + off4 + r] = v;
}
// scale concat (fp32, no rounding)
__global__ void sc_cat(const float* __restrict__ in, float* __restrict__ out,
                       int per, int ostride, int off) {
    int i = blockIdx.x * blockDim.x + threadIdx.x;
    if (i >= Fn * per) return;
    int z = i / per, r = i % per;
    out[z * ostride + off + r] = in[i];
}

// ---------------- router (exact fp32: top-k must not flip) ----------------
__global__ void router_kernel(const float* __restrict__ x,
                              const float* __restrict__ gw,
                              const int* __restrict__ inv,
                              float* __restrict__ soft,
                              float* __restrict__ scal) {
    __shared__ float xs[Hn];
    __shared__ float sc[En];
    const int t = blockIdx.x;
    const int tid = threadIdx.x;  // 128 threads
    const float4* xv = reinterpret_cast<const float4*>(x + (size_t)t * Hn);
    for (int i = tid; i < Hn / 4; i += 128)
        reinterpret_cast<float4*>(xs)[i] = xv[i];
    __syncthreads();
    const int lane = tid & 31, w = tid >> 5;
    for (int e = w; e < En; e += 4) {
        const float* g = gw + (size_t)e * Hn;
        float s = 0.f;
        for (int h = lane; h < Hn; h += 32) s += xs[h] * g[h];
#pragma unroll
        for (int o = 16; o; o >>= 1) s += __shfl_xor_sync(0xffffffffu, s, o);
        if (lane == 0) sc[e] = s;
    }
    __syncthreads();
    if (tid == 0) {
        float mx = -1e30f;
        for (int e = 0; e < En; e++) mx = fmaxf(mx, sc[e]);
        float p[En];
        float sum = 0.f;
        for (int e = 0; e < En; e++) { p[e] = expf(sc[e] - mx); sum += p[e]; }
        float is = 1.f / sum;
        for (int e = 0; e < En; e++) p[e] *= is;
        float wv[En];
        for (int e = 0; e < En; e++) wv[e] = 0.f;
        for (int j = 0; j < TOPKn; j++) {
            int best = 0;
            float bv = -1.f;
            for (int e = 0; e < En; e++) {
                if (wv[e] == 0.f && p[e] > bv) { bv = p[e]; best = e; }
            }
            wv[best] = p[best];
        }
        for (int f = 0; f < Fn; f++) {
            float fl[Kn];
            float ssum = 0.f, fmx = -1e30f;
            for (int k = 0; k < Kn; k++) {
                int e = inv[f * Kn + k];
                float v = wv[e];
                ssum += v;
                float l = (v == 0.f) ? -1e9f : v;
                fl[k] = l;
                fmx = fmaxf(fmx, l);
            }
            float es = 0.f, ex[Kn];
            for (int k = 0; k < Kn; k++) { ex[k] = expf(fl[k] - fmx); es += ex[k]; }
            float ies = 1.f / es;
            for (int k = 0; k < Kn; k++)
                soft[((size_t)t * Fn + f) * Kn + k] = ex[k] * ies;
            scal[(size_t)t * Fn + f] = ssum;
        }
    }
}

// ---------------- deterministic per-group token compaction ----------------
__global__ void compact_kernel(const float* __restrict__ scal,
                               int* __restrict__ cnt,
                               int* __restrict__ tok,
                               int* __restrict__ pos) {
    const int z = blockIdx.x;
    const int t = threadIdx.x;  // Tn threads
    __shared__ int sbuf[Tn];
    int active = (scal[(size_t)t * Fn + z] != 0.f) ? 1 : 0;
    sbuf[t] = active;
    __syncthreads();
    for (int off = 1; off < Tn; off <<= 1) {
        int v = (t >= off) ? sbuf[t - off] : 0;
        __syncthreads();
        sbuf[t] += v;
        __syncthreads();
    }
    int incl = sbuf[t];
    if (active) {
        tok[z * Tn + incl - 1] = t;
        pos[z * Tn + t] = incl - 1;
    } else {
        pos[z * Tn + t] = -1;
    }
    if (t == Tn - 1) cnt[z] = incl;
}

// ---------------- xe (compacted, tf32-rounded at write) ----------------
__global__ void xe_kernel(const float* __restrict__ x,
                          const float* __restrict__ muW,
                          const float* __restrict__ soft,
                          const int* __restrict__ cnt,
                          const int* __restrict__ tok,
                          float* __restrict__ xe) {
    size_t idx = (size_t)blockIdx.x * blockDim.x + threadIdx.x;
    if (idx >= (size_t)Fn * Tn * Hn) return;
    int z = (int)(idx / ((size_t)Tn * Hn));
    int rem = (int)(idx % ((size_t)Tn * Hn));
    int i = rem / Hn, h = rem % Hn;
    if (i >= cnt[z]) return;
    int t = tok[z * Tn + i];
    const float* mw = muW + ((size_t)z * Hn + h) * Kn;
    const float* sf = soft + ((size_t)t * Fn + z) * Kn;
    float s = x[(size_t)t * Hn + h];
#pragma unroll
    for (int k = 0; k < Kn; k++) s += sf[k] * mw[k];
    xe[idx] = tf32r(s);
}

// ---------------- qbt builders ----------------
// combined block-diagonal: out[z][n][kr], n<In & kr<64 -> gate_qb, n>=In & kr>=64 -> up_qb, else 0
__global__ void tq2_kernel(const float* __restrict__ gqb, const float* __restrict__ uqb,
                           float* __restrict__ outp) {
    int total = Fn * IGU * 128;
    int idx = blockIdx.x * blockDim.x + threadIdx.x;
    if (idx >= total) return;
    int z = idx / (IGU * 128);
    int rem = idx % (IGU * 128);
    int n = rem >> 7, kr = rem & 127;
    float v = 0.f;
    if (n < In) {
        if (kr < 64) {
            int k = kr >> 3, r = kr & 7;
            v = tf32r(gqb[(((size_t)z * Kn + k) * In + n) * Rn + r]);
        }
    } else {
        if (kr >= 64) {
            int k = (kr - 64) >> 3, r = kr & 7;
            v = tf32r(uqb[(((size_t)z * Kn + k) * In + (n - In)) * Rn + r]);
        }
    }
    outp[idx] = v;
}
// down: [F,K,Nd,R] -> [F,Nd,64]
__global__ void tq_kernel(const float* __restrict__ qb, float* __restrict__ outp, int Nd) {
    int total = Fn * Nd * KRn;
    int idx = blockIdx.x * blockDim.x + threadIdx.x;
    if (idx >= total) return;
    int z = idx / (Nd * KRn);
    int rem = idx % (Nd * KRn);
    int n = rem >> 6, kr = rem & 63;
    int k = kr >> 3, r = kr & 7;
    outp[idx] = tf32r(qb[(((size_t)z * Kn + k) * Nd + n) * Rn + r]);
}

// ---------------- hmid = silu(gate)*up from concat layout ----------------
__global__ void fuse_kernel(const float* __restrict__ gu,
                            const int* __restrict__ cnt,
                            float* __restrict__ hm) {
    size_t idx = (size_t)blockIdx.x * blockDim.x + threadIdx.x;
    if (idx >= (size_t)Fn * Tn * In) return;
    int z = (int)(idx / ((size_t)Tn * In));
    int rem = (int)(idx % ((size_t)Tn * In));
    int i = rem / In, c = rem % In;
    if (i >= cnt[z]) return;
    size_t base = ((size_t)z * Tn + i) * IGU;
    float g = gu[base + c], u = gu[base + In + c];
    hm[idx] = tf32r(g / (1.f + expf(-g)) * u);
}

__global__ void swiglu_kernel(const float* __restrict__ sgu, float* __restrict__ hm) {
    size_t idx = (size_t)blockIdx.x * blockDim.x + threadIdx.x;
    if (idx >= (size_t)Tn * ISHn) return;
    int t = (int)(idx / ISHn), c = (int)(idx % ISHn);
    size_t base = (size_t)t * SH2;
    float g = sgu[base + c], u = sgu[base + ISHn + c];
    hm[idx] = tf32r(g / (1.f + expf(-g)) * u);
}

// ---------------- out[t] += sum_z active: down[z][pos[z,t]] ----------------
__global__ void reduce_kernel(float* __restrict__ out, const float* __restrict__ down,
                              const int* __restrict__ pos) {
    int idx = blockIdx.x * blockDim.x + threadIdx.x;
    if (idx >= Tn * Hn) return;
    int t = idx / Hn, h = idx % Hn;
    float s = out[idx];
#pragma unroll
    for (int z = 0; z < Fn; z++) {
        int p = pos[z * Tn + t];
        if (p >= 0) s += down[((size_t)z * Tn + p) * Hn + h];
    }
    out[idx] = s;
}

// ---------------- cp.async tf32 GEMM: C[MxN] = A[MxK] * B[NxK]^T ----------------
// MODE 0: C=acc
// MODE 1: C=tf32r(acc*soft[tok[r], z, (n&63)>>3])
// MODE 2: C=C + colscale[n]*acc
// MODE 3: C=colscale[n]*acc
// MODE 4: C=rowscal[tok[r]*Fn+z]*(acc + mixadd[z,r,n])
#define KC 32
#define SM_LD 36
#define SM_BUF (128 * SM_LD)
#define STAGE_FLOATS (2 * SM_BUF)
#define SMEM_BYTES (3 * STAGE_FLOATS * 4)

template <int MODE>
__global__ void __launch_bounds__(256, 2)
gemm_tn(const float* __restrict__ A, int lda, size_t sA,
        const float* __restrict__ B, int ldb, size_t sB,
        float* __restrict__ C, int ldc, size_t sC,
        int N, int Ktot,
        const float* __restrict__ soft,
        const float* __restrict__ rowscal,
        const float* __restrict__ colscale, size_t sCs,
        const float* __restrict__ mixadd,
        const int* __restrict__ cntp,
        const int* __restrict__ tokp) {
    const int z = blockIdx.z;
    const int Mz = cntp ? cntp[z] : Tn;
    const int bm = blockIdx.y * 128, bn = blockIdx.x * 128;
    if (bm >= Mz) return;
    A += (size_t)z * sA;
    B += (size_t)z * sB;
    C += (size_t)z * sC;
    const float* cs = (MODE == 2 || MODE == 3) ? colscale + (size_t)z * sCs : nullptr;
    const float* mixp = (MODE == 4) ? mixadd + (size_t)z * sC : nullptr;
    const int* tk = (MODE == 1 || MODE == 4) ? tokp + z * Tn : nullptr;

    extern __shared__ float smf[];
    const uint32_t sbase = smem_u32(smf);
    const int tid = threadIdx.x, lane = tid & 31, wid = tid >> 5;
    const int wm = (wid >> 2) * 64, wn = (wid & 3) * 32;

    int arow[4], kq4[4];
#pragma unroll
    for (int i = 0; i < 4; i++) {
        int lin = tid + i * 256;
        arow[i] = lin >> 3;
        kq4[i] = (lin & 7) << 2;
    }
    float acc[4][4][4];
#pragma unroll
    for (int a = 0; a < 4; a++)
#pragma unroll
        for (int b = 0; b < 4; b++)
#pragma unroll
            for (int c = 0; c < 4; c++) acc[a][b][c] = 0.f;

    auto issue = [&](int kt, int s) {
        const int k0 = kt * KC;
#pragma unroll
        for (int i = 0; i < 4; i++) {
            uint32_t da = sbase + (uint32_t)((s * STAGE_FLOATS + arow[i] * SM_LD + kq4[i]) * 4);
            cpa16(da, A + (size_t)(bm + arow[i]) * lda + k0 + kq4[i], bm + arow[i] < Mz);
            uint32_t db = da + (uint32_t)(SM_BUF * 4);
            cpa16(db, B + (size_t)(bn + arow[i]) * ldb + k0 + kq4[i], bn + arow[i] < N);
        }
    };

    const int KT = Ktot / KC;
    issue(0, 0);
    CP_COMMIT();
    if (KT > 1) issue(1, 1);
    CP_COMMIT();

    for (int kt = 0; kt < KT; kt++) {
        CP_WAIT1();
        __syncthreads();
        if (kt + 2 < KT) issue(kt + 2, (kt + 2) % 3);
        CP_COMMIT();
        const float* Ab = smf + (kt % 3) * STAGE_FLOATS;
        const float* Bb = Ab + SM_BUF;
#pragma unroll
        for (int ks = 0; ks < 4; ks++) {
            int kk = ks * 8 + (lane & 3);
            float a[4][4], b[4][2];
#pragma unroll
            for (int mi = 0; mi < 4; mi++) {
                const float* p = Ab + (wm + mi * 16 + (lane >> 2)) * SM_LD + kk;
                a[mi][0] = p[0];
                a[mi][1] = p[8 * SM_LD];
                a[mi][2] = p[4];
                a[mi][3] = p[8 * SM_LD + 4];
            }
#pragma unroll
            for (int ni = 0; ni < 4; ni++) {
                const float* q = Bb + (wn + ni * 8 + (lane >> 2)) * SM_LD + kk;
                b[ni][0] = q[0];
                b[ni][1] = q[4];
            }
#pragma unroll
            for (int mi = 0; mi < 4; mi++)
#pragma unroll
                for (int ni = 0; ni < 4; ni++) MMA_TF32(acc[mi][ni], a[mi], b[ni]);
        }
    }

    // epilogue
#pragma unroll
    for (int mi = 0; mi < 4; mi++) {
#pragma unroll
        for (int ni = 0; ni < 4; ni++) {
            int cb = bn + wn + ni * 8;
            if (cb >= N) continue;
            int c = cb + ((lane & 3) << 1);
#pragma unroll
            for (int hh = 0; hh < 2; hh++) {
                int r = bm + wm + mi * 16 + (lane >> 2) + hh * 8;
                if (r >= Mz) continue;
                float v0 = acc[mi][ni][hh * 2 + 0];
                float v1 = acc[mi][ni][hh * 2 + 1];
                size_t off = (size_t)r * ldc + c;
                if (MODE == 1) {
                    float s = soft[((size_t)tk[r] * Fn + z) * Kn + ((c & 63) >> 3)];
                    v0 = tf32r(v0 * s);
                    v1 = tf32r(v1 * s);
                } else if (MODE == 2) {
                    float2 prev = *reinterpret_cast<const float2*>(&C[off]);
                    v0 = prev.x + cs[c] * v0;
                    v1 = prev.y + cs[c + 1] * v1;
                } else if (MODE == 3) {
                    v0 *= cs[c];
                    v1 *= cs[c + 1];
                } else if (MODE == 4) {
                    float rs = rowscal[(size_t)tk[r] * Fn + z];
                    float2 mv = *reinterpret_cast<const float2*>(&mixp[off]);
                    v0 = rs * (v0 + mv.x);
                    v1 = rs * (v1 + mv.y);
                }
                *reinterpret_cast<float2*>(&C[off]) = make_float2(v0, v1);
            }
        }
    }
}

// ---------------- host ----------------
#define SYMP(v, T) ({ void* _p = nullptr; cudaGetSymbolAddress(&_p, v); (T*)_p; })

extern "C" void kernel_launch(void* const* d_in, const int* in_sizes, int n_in,
                              void* d_out, int out_size) {
    const float* x          = (const float*)d_in[0];
    const float* gate_wt    = (const float*)d_in[1];
    const int*   inv        = (const int*)d_in[2];
    const float* mask_up_W  = (const float*)d_in[3];
    const float* gate_W     = (const float*)d_in[4];
    const float* gate_qa    = (const float*)d_in[5];
    const float* gate_qb    = (const float*)d_in[6];
    const float* gate_scale = (const float*)d_in[7];
    const float* up_W       = (const float*)d_in[8];
    const float* up_qa      = (const float*)d_in[9];
    const float* up_qb      = (const float*)d_in[10];
    const float* up_scale   = (const float*)d_in[11];
    const float* down_W     = (const float*)d_in[12];
    const float* down_qa    = (const float*)d_in[13];
    const float* down_qb    = (const float*)d_in[14];
    const float* down_scale = (const float*)d_in[15];
    const float* sh_gate_W  = (const float*)d_in[16];
    const float* sh_up_W    = (const float*)d_in[17];
    const float* sh_down_W  = (const float*)d_in[18];
    float* out = (float*)d_out;

    float* p_soft  = SYMP(g_soft, float);
    float* p_scal  = SYMP(g_scalar, float);
    int*   p_cnt   = SYMP(g_cnt, int);
    int*   p_tok   = SYMP(g_tok, int);
    int*   p_pos   = SYMP(g_pos, int);
    float* p_xe    = SYMP(g_xe, float);
    float* p_gu    = SYMP(g_gu, float);
    float* p_mgu   = SYMP(g_mgu, float);
    float* p_hmid  = SYMP(g_hmid, float);
    float* p_md    = SYMP(g_md, float);
    float* p_mixd  = SYMP(g_mixd, float);
    float* p_down  = SYMP(g_down, float);
    float* p_qbtgu = SYMP(g_qbtgu, float);
    float* p_qbtd  = SYMP(g_qbtd, float);
    float* p_shgu  = SYMP(g_shgu, float);
    float* p_shm   = SYMP(g_shm, float);
    float* p_wgu   = SYMP(g_wgu, float);
    float* p_wd    = SYMP(g_wd, float);
    float* p_qagu  = SYMP(g_qagu, float);
    float* p_qad   = SYMP(g_qad, float);
    float* p_sgu   = SYMP(g_sgu, float);
    float* p_shguw = SYMP(g_shguw, float);
    float* p_shdw  = SYMP(g_shdw, float);
    float* p_xr    = SYMP(g_xr, float);

#define SETUP(M)                                                                          \
    cudaFuncSetAttribute(gemm_tn<M>, cudaFuncAttributeMaxDynamicSharedMemorySize,         \
                         SMEM_BYTES);                                                     \
    cudaFuncSetAttribute(gemm_tn<M>, cudaFuncAttributePreferredSharedMemoryCarveout, 100)
    SETUP(0); SETUP(1); SETUP(2); SETUP(3); SETUP(4);
#undef SETUP

#define NB(n) ((int)(((n) + 255) / 256))
#define GRID(N, zc) dim3(((N) + 127) / 128, Tn / 128, zc)

    // ---- launches 1-5 (so launch #6 = the big combined GEMM for ncu -s 5) ----
    router_kernel<<<Tn, 128>>>(x, gate_wt, inv, p_soft, p_scal);                       // 1
    compact_kernel<<<Fn, Tn>>>(p_scal, p_cnt, p_tok, p_pos);                           // 2
    {
        size_t c = (size_t)Fn * Tn * Hn;                                               // 3
        xe_kernel<<<NB(c), 256>>>(x, mask_up_W, p_soft, p_cnt, p_tok, p_xe);
    }
    {
        int n4z = In * Hn / 4, zs4 = IGU * Hn / 4;
        rc_off<<<NB(Fn * n4z), 256>>>((const float4*)gate_W, (float4*)p_wgu,           // 4
                                      n4z, zs4, 0, Fn);
        rc_off<<<NB(Fn * n4z), 256>>>((const float4*)up_W, (float4*)p_wgu,             // 5
                                      n4z, zs4, n4z, Fn);
    }

    // 6. combined gate||up GEMM  <-- ncu target
    gemm_tn<0><<<GRID(IGU, Fn), 256, SMEM_BYTES>>>(
        p_xe, Hn, (size_t)Tn * Hn, p_wgu, Hn, (size_t)IGU * Hn,
        p_gu, IGU, (size_t)Tn * IGU, IGU, Hn, nullptr, nullptr, nullptr, 0, nullptr,
        p_cnt, nullptr);

    // 7-8. qa concat (rounded)
    {
        int n4z = KRn * Hn / 4, zs4 = 128 * Hn / 4;
        rc_off<<<NB(Fn * n4z), 256>>>((const float4*)gate_qa, (float4*)p_qagu, n4z, zs4, 0, Fn);
        rc_off<<<NB(Fn * n4z), 256>>>((const float4*)up_qa, (float4*)p_qagu, n4z, zs4, n4z, Fn);
    }
    // 9. combined LoRA-a GEMM (N=128) with soft epilogue
    gemm_tn<1><<<GRID(128, Fn), 256, SMEM_BYTES>>>(
        p_xe, Hn, (size_t)Tn * Hn, p_qagu, Hn, (size_t)128 * Hn,
        p_mgu, 128, (size_t)Tn * 128, 128, Hn, p_soft, nullptr, nullptr, 0, nullptr,
        p_cnt, p_tok);

    // 10. block-diagonal qbt concat
    tq2_kernel<<<NB(Fn * IGU * 128), 256>>>(gate_qb, up_qb, p_qbtgu);
    // 11-12. scale concat
    sc_cat<<<NB(Fn * In), 256>>>(gate_scale, p_sgu, In, IGU, 0);
    sc_cat<<<NB(Fn * In), 256>>>(up_scale, p_sgu, In, IGU, In);

    // 13. combined mix GEMM, in-place: gu += sgu[n] * (mgu @ qbtgu^T)
    gemm_tn<2><<<GRID(IGU, Fn), 256, SMEM_BYTES>>>(
        p_mgu, 128, (size_t)Tn * 128, p_qbtgu, 128, (size_t)IGU * 128,
        p_gu, IGU, (size_t)Tn * IGU, IGU, 128, nullptr, nullptr, p_sgu, IGU, nullptr,
        p_cnt, nullptr);

    // 14. hmid = silu(gate)*up
    {
        size_t c = (size_t)Fn * Tn * In;
        fuse_kernel<<<NB(c), 256>>>(p_gu, p_cnt, p_hmid);
    }

    // 15-17. down-path weight prep
    round_copy<<<NB((size_t)Fn * Hn * In / 4), 256>>>(
        (const float4*)down_W, (float4*)p_wd, (int)((size_t)Fn * Hn * In / 4));
    round_copy<<<NB((size_t)Fn * KRn * In / 4), 256>>>(
        (const float4*)down_qa, (float4*)p_qad, (int)((size_t)Fn * KRn * In / 4));
    tq_kernel<<<NB(Fn * Hn * KRn), 256>>>(down_qb, p_qbtd, Hn);

    // 18. down LoRA a
    gemm_tn<1><<<GRID(KRn, Fn), 256, SMEM_BYTES>>>(
        p_hmid, In, (size_t)Tn * In, p_qad, In, (size_t)KRn * In,
        p_md, KRn, (size_t)Tn * KRn, KRn, In, p_soft, nullptr, nullptr, 0, nullptr,
        p_cnt, p_tok);
    // 19. mixd
    gemm_tn<3><<<GRID(Hn, Fn), 256, SMEM_BYTES>>>(
        p_md, KRn, (size_t)Tn * KRn, p_qbtd, KRn, (size_t)Hn * KRn,
        p_mixd, Hn, (size_t)Tn * Hn, Hn, KRn, nullptr, nullptr, down_scale, Hn, nullptr,
        p_cnt, nullptr);
    // 20. down GEMM fused
    gemm_tn<4><<<GRID(Hn, Fn), 256, SMEM_BYTES>>>(
        p_hmid, In, (size_t)Tn * In, p_wd, In, (size_t)Hn * In,
        p_down, Hn, (size_t)Tn * Hn, Hn, In, nullptr, p_scal, nullptr, 0, p_mixd,
        p_cnt, p_tok);

    // 21-23. shared-path prep
    round_copy<<<NB((size_t)Tn * Hn / 4), 256>>>(
        (const float4*)x, (float4*)p_xr, (int)((size_t)Tn * Hn / 4));
    {
        int n4 = ISHn * Hn / 4;
        rc_off<<<NB(n4), 256>>>((const float4*)sh_gate_W, (float4*)p_shguw, n4, 2 * n4, 0, 1);
        rc_off<<<NB(n4), 256>>>((const float4*)sh_up_W, (float4*)p_shguw, n4, 2 * n4, n4, 1);
    }
    // 24. combined shared gate||up GEMM (N=5632)
    gemm_tn<0><<<GRID(SH2, 1), 256, SMEM_BYTES>>>(
        p_xr, Hn, 0, p_shguw, Hn, 0,
        p_shgu, SH2, 0, SH2, Hn, nullptr, nullptr, nullptr, 0, nullptr, nullptr, nullptr);
    // 25. swiglu
    swiglu_kernel<<<NB((size_t)Tn * ISHn), 256>>>(p_shgu, p_shm);
    // 26. sh_down weight
    round_copy<<<NB((size_t)Hn * ISHn / 4), 256>>>(
        (const float4*)sh_down_W, (float4*)p_shdw, (int)((size_t)Hn * ISHn / 4));
    // 27. shared down GEMM -> out
    gemm_tn<0><<<GRID(Hn, 1), 256, SMEM_BYTES>>>(
        p_shm, ISHn, 0, p_shdw, ISHn, 0,
        out, Hn, 0, Hn, ISHn, nullptr, nullptr, nullptr, 0, nullptr, nullptr, nullptr);

    // 28. out += gathered expert outputs
    reduce_kernel<<<NB(Tn * Hn), 256>>>(out, p_down, p_pos);

#undef NB
#undef GRID
    (void)in_sizes; (void)n_in; (void)out_size;
}

// round 8
// speedup vs baseline: 1.9315x; 1.0166x over previous
#include <cuda_runtime.h>
#include <cuda_bf16.h>
#include <math.h>
#include <cstdint>

#define Tn 1024
#define Hn 2048
#define In 1408
#define IGU 2816            // 2*In (gate||up concat)
#define En 64
#define Fn 8
#define Kn 8
#define Rn 8
#define ISHn 2816
#define SH2 5632            // 2*ISHn
#define TOPKn 6
#define KRn 64

// ---------------- scratch (device globals; allocation-free) ----------------
__device__ float g_soft[Tn * Fn * Kn];
__device__ float g_scalar[Tn * Fn];
__device__ int   g_cnt[Fn];
__device__ int   g_tok[Fn * Tn];
__device__ int   g_pos[Fn * Tn];
__device__ float g_xe[(size_t)Fn * Tn * Hn];
__device__ float g_gu[(size_t)Fn * Tn * IGU];      // gate||up outputs
__device__ float g_mgu[(size_t)Fn * Tn * 128];     // LoRA-a gate||up
__device__ float g_hmid[(size_t)Fn * Tn * In];
__device__ float g_md[(size_t)Fn * Tn * KRn];
__device__ float g_mixd[(size_t)Fn * Tn * Hn];
__device__ float g_down[(size_t)Fn * Tn * Hn];
__device__ float g_qbtgu[(size_t)Fn * IGU * 128];  // block-diag [qbtg 0; 0 qbtu]
__device__ float g_qbtd[(size_t)Fn * Hn * KRn];
__device__ float g_shgu[(size_t)Tn * SH2];
__device__ float g_shm[(size_t)Tn * ISHn];
// pre-rounded (tf32 RNA) weights
__device__ float g_wgu[(size_t)Fn * IGU * Hn];     // gate_W||up_W
__device__ float g_wd[(size_t)Fn * Hn * In];
__device__ float g_qagu[(size_t)Fn * 128 * Hn];    // gate_qa||up_qa
__device__ float g_qad[(size_t)Fn * KRn * In];
__device__ float g_sgu[Fn * IGU];                  // gate_scale||up_scale (fp32)
__device__ float g_shguw[(size_t)SH2 * Hn];        // sh_gate_W||sh_up_W
__device__ float g_shdw[(size_t)Hn * ISHn];
__device__ float g_xr[(size_t)Tn * Hn];

// ---------------- helpers ----------------
__device__ __forceinline__ float tf32r(float x) {
    float y;
    asm("cvt.rna.tf32.f32 %0, %1;" : "=f"(y) : "f"(x));
    return y;
}
__device__ __forceinline__ float4 tf32r4(float4 v) {
    v.x = tf32r(v.x); v.y = tf32r(v.y); v.z = tf32r(v.z); v.w = tf32r(v.w);
    return v;
}
__device__ __forceinline__ uint32_t smem_u32(const void* p) {
    uint32_t a;
    asm("{ .reg .u64 t; cvta.to.shared.u64 t, %1; cvt.u32.u64 %0, t; }" : "=r"(a) : "l"(p));
    return a;
}
__device__ __forceinline__ void cpa16(uint32_t dst, const void* src, bool pred) {
    int sz = pred ? 16 : 0;
    asm volatile("cp.async.cg.shared.global [%0], [%1], 16, %2;"
                 :: "r"(dst), "l"(src), "r"(sz) : "memory");
}
#define CP_COMMIT() asm volatile("cp.async.commit_group;" ::: "memory")
#define CP_WAIT1() asm volatile("cp.async.wait_group 1;" ::: "memory")

#define MMA_TF32(d, a, b)                                                      \
    asm volatile(                                                              \
        "mma.sync.aligned.m16n8k8.row.col.f32.tf32.tf32.f32 "                  \
        "{%0,%1,%2,%3}, {%4,%5,%6,%7}, {%8,%9}, {%0,%1,%2,%3};\n"              \
        : "+f"((d)[0]), "+f"((d)[1]), "+f"((d)[2]), "+f"((d)[3])               \
        : "r"(__float_as_uint((a)[0])), "r"(__float_as_uint((a)[1])),          \
          "r"(__float_as_uint((a)[2])), "r"(__float_as_uint((a)[3])),          \
          "r"(__float_as_uint((b)[0])), "r"(__float_as_uint((b)[1])))

// ---------------- fused multi-segment rounding copies ----------------
// gate/up path: gate_W||up_W -> wgu (z-strided), gate_qa||up_qa -> qagu (z-strided)
__global__ void rc_gu(const float4* __restrict__ gW, const float4* __restrict__ uW,
                      const float4* __restrict__ gqa, const float4* __restrict__ uqa,
                      float4* __restrict__ wgu, float4* __restrict__ qagu) {
    const int SW = Fn * In * Hn / 4;    // 5767168 per weight tensor
    const int SQ = Fn * KRn * Hn / 4;   // 262144 per qa tensor
    long idx = (long)blockIdx.x * blockDim.x + threadIdx.x;
    if (idx < 2L * SW) {
        int seg = idx >= SW;
        int i = (int)(idx - (long)seg * SW);
        const int n4z = In * Hn / 4, zs4 = IGU * Hn / 4;
        int z = i / n4z, r = i % n4z;
        wgu[(size_t)z * zs4 + (size_t)seg * n4z + r] = tf32r4((seg ? uW : gW)[i]);
    } else {
        idx -= 2L * SW;
        if (idx >= 2L * SQ) return;
        int seg = idx >= SQ;
        int i = (int)(idx - (long)seg * SQ);
        const int n4z = KRn * Hn / 4, zs4 = 128 * Hn / 4;
        int z = i / n4z, r = i % n4z;
        qagu[(size_t)z * zs4 + (size_t)seg * n4z + r] = tf32r4((seg ? uqa : gqa)[i]);
    }
}
// down path: down_W -> wd, down_qa -> qad (contiguous)
__global__ void rc_down(const float4* __restrict__ dW, const float4* __restrict__ dqa,
                        float4* __restrict__ wd, float4* __restrict__ qad) {
    const int S0 = Fn * Hn * In / 4, S1 = Fn * KRn * In / 4;
    int idx = blockIdx.x * blockDim.x + threadIdx.x;
    if (idx < S0) {
        wd[idx] = tf32r4(dW[idx]);
    } else {
        idx -= S0;
        if (idx < S1) qad[idx] = tf32r4(dqa[idx]);
    }
}
// shared path: x -> xr, sh_gate||sh_up -> shguw, sh_down -> shdw
__global__ void rc_sh(const float4* __restrict__ x, const float4* __restrict__ sg,
                      const float4* __restrict__ su, const float4* __restrict__ sd,
                      float4* __restrict__ xr, float4* __restrict__ shguw,
                      float4* __restrict__ shdw) {
    const int SX = Tn * Hn / 4;          // 524288
    const int SW = ISHn * Hn / 4;        // 1441792
    int idx = blockIdx.x * blockDim.x + threadIdx.x;
    if (idx < SX) {
        xr[idx] = tf32r4(x[idx]);
        return;
    }
    idx -= SX;
    if (idx < SW) { shguw[idx] = tf32r4(sg[idx]); return; }
    idx -= SW;
    if (idx < SW) { shguw[SW + idx] = tf32r4(su[idx]); return; }
    idx -= SW;
    if (idx < SW) shdw[idx] = tf32r4(sd[idx]);
}
// scale concat (fp32, no rounding), both halves in one launch
__global__ void sc2(const float* __restrict__ gs, const float* __restrict__ us,
                    float* __restrict__ sgu) {
    int i = blockIdx.x * blockDim.x + threadIdx.x;
    if (i >= 2 * Fn * In) return;
    int seg = i >= Fn * In;
    int j = i - seg * Fn * In;
    int z = j / In, r = j % In;
    sgu[z * IGU + seg * In + r] = (seg ? us : gs)[j];
}

// ---------------- router (exact fp32: top-k must not flip) ----------------
__global__ void router_kernel(const float* __restrict__ x,
                              const float* __restrict__ gw,
                              const int* __restrict__ inv,
                              float* __restrict__ soft,
                              float* __restrict__ scal) {
    __shared__ float xs[Hn];
    __shared__ float sc[En];
    const int t = blockIdx.x;
    const int tid = threadIdx.x;  // 128 threads
    const float4* xv = reinterpret_cast<const float4*>(x + (size_t)t * Hn);
    for (int i = tid; i < Hn / 4; i += 128)
        reinterpret_cast<float4*>(xs)[i] = xv[i];
    __syncthreads();
    const int lane = tid & 31, w = tid >> 5;
    for (int e = w; e < En; e += 4) {
        const float* g = gw + (size_t)e * Hn;
        float s = 0.f;
        for (int h = lane; h < Hn; h += 32) s += xs[h] * g[h];
#pragma unroll
        for (int o = 16; o; o >>= 1) s += __shfl_xor_sync(0xffffffffu, s, o);
        if (lane == 0) sc[e] = s;
    }
    __syncthreads();
    if (tid == 0) {
        float mx = -1e30f;
        for (int e = 0; e < En; e++) mx = fmaxf(mx, sc[e]);
        float p[En];
        float sum = 0.f;
        for (int e = 0; e < En; e++) { p[e] = expf(sc[e] - mx); sum += p[e]; }
        float is = 1.f / sum;
        for (int e = 0; e < En; e++) p[e] *= is;
        float wv[En];
        for (int e = 0; e < En; e++) wv[e] = 0.f;
        for (int j = 0; j < TOPKn; j++) {
            int best = 0;
            float bv = -1.f;
            for (int e = 0; e < En; e++) {
                if (wv[e] == 0.f && p[e] > bv) { bv = p[e]; best = e; }
            }
            wv[best] = p[best];
        }
        for (int f = 0; f < Fn; f++) {
            float fl[Kn];
            float ssum = 0.f, fmx = -1e30f;
            for (int k = 0; k < Kn; k++) {
                int e = inv[f * Kn + k];
                float v = wv[e];
                ssum += v;
                float l = (v == 0.f) ? -1e9f : v;
                fl[k] = l;
                fmx = fmaxf(fmx, l);
            }
            float es = 0.f, ex[Kn];
            for (int k = 0; k < Kn; k++) { ex[k] = expf(fl[k] - fmx); es += ex[k]; }
            float ies = 1.f / es;
            for (int k = 0; k < Kn; k++)
                soft[((size_t)t * Fn + f) * Kn + k] = ex[k] * ies;
            scal[(size_t)t * Fn + f] = ssum;
        }
    }
}

// ---------------- deterministic per-group token compaction ----------------
__global__ void compact_kernel(const float* __restrict__ scal,
                               int* __restrict__ cnt,
                               int* __restrict__ tok,
                               int* __restrict__ pos) {
    const int z = blockIdx.x;
    const int t = threadIdx.x;  // Tn threads
    __shared__ int sbuf[Tn];
    int active = (scal[(size_t)t * Fn + z] != 0.f) ? 1 : 0;
    sbuf[t] = active;
    __syncthreads();
    for (int off = 1; off < Tn; off <<= 1) {
        int v = (t >= off) ? sbuf[t - off] : 0;
        __syncthreads();
        sbuf[t] += v;
        __syncthreads();
    }
    int incl = sbuf[t];
    if (active) {
        tok[z * Tn + incl - 1] = t;
        pos[z * Tn + t] = incl - 1;
    } else {
        pos[z * Tn + t] = -1;
    }
    if (t == Tn - 1) cnt[z] = incl;
}

// ---------------- xe (compacted, tf32-rounded at write) ----------------
__global__ void xe_kernel(const float* __restrict__ x,
                          const float* __restrict__ muW,
                          const float* __restrict__ soft,
                          const int* __restrict__ cnt,
                          const int* __restrict__ tok,
                          float* __restrict__ xe) {
    size_t idx = (size_t)blockIdx.x * blockDim.x + threadIdx.x;
    if (idx >= (size_t)Fn * Tn * Hn) return;
    int z = (int)(idx / ((size_t)Tn * Hn));
    int rem = (int)(idx % ((size_t)Tn * Hn));
    int i = rem / Hn, h = rem % Hn;
    if (i >= cnt[z]) return;
    int t = tok[z * Tn + i];
    const float* mw = muW + ((size_t)z * Hn + h) * Kn;
    const float* sf = soft + ((size_t)t * Fn + z) * Kn;
    float s = x[(size_t)t * Hn + h];
#pragma unroll
    for (int k = 0; k < Kn; k++) s += sf[k] * mw[k];
    xe[idx] = tf32r(s);
}

// ---------------- qbt builders ----------------
__global__ void tq2_kernel(const float* __restrict__ gqb, const float* __restrict__ uqb,
                           float* __restrict__ outp) {
    int total = Fn * IGU * 128;
    int idx = blockIdx.x * blockDim.x + threadIdx.x;
    if (idx >= total) return;
    int z = idx / (IGU * 128);
    int rem = idx % (IGU * 128);
    int n = rem >> 7, kr = rem & 127;
    float v = 0.f;
    if (n < In) {
        if (kr < 64) {
            int k = kr >> 3, r = kr & 7;
            v = tf32r(gqb[(((size_t)z * Kn + k) * In + n) * Rn + r]);
        }
    } else {
        if (kr >= 64) {
            int k = (kr - 64) >> 3, r = kr & 7;
            v = tf32r(uqb[(((size_t)z * Kn + k) * In + (n - In)) * Rn + r]);
        }
    }
    outp[idx] = v;
}
__global__ void tq_kernel(const float* __restrict__ qb, float* __restrict__ outp, int Nd) {
    int total = Fn * Nd * KRn;
    int idx = blockIdx.x * blockDim.x + threadIdx.x;
    if (idx >= total) return;
    int z = idx / (Nd * KRn);
    int rem = idx % (Nd * KRn);
    int n = rem >> 6, kr = rem & 63;
    int k = kr >> 3, r = kr & 7;
    outp[idx] = tf32r(qb[(((size_t)z * Kn + k) * Nd + n) * Rn + r]);
}

// ---------------- hmid = silu(gate)*up from concat layout ----------------
__global__ void fuse_kernel(const float* __restrict__ gu,
                            const int* __restrict__ cnt,
                            float* __restrict__ hm) {
    size_t idx = (size_t)blockIdx.x * blockDim.x + threadIdx.x;
    if (idx >= (size_t)Fn * Tn * In) return;
    int z = (int)(idx / ((size_t)Tn * In));
    int rem = (int)(idx % ((size_t)Tn * In));
    int i = rem / In, c = rem % In;
    if (i >= cnt[z]) return;
    size_t base = ((size_t)z * Tn + i) * IGU;
    float g = gu[base + c], u = gu[base + In + c];
    hm[idx] = tf32r(g / (1.f + expf(-g)) * u);
}

__global__ void swiglu_kernel(const float* __restrict__ sgu, float* __restrict__ hm) {
    size_t idx = (size_t)blockIdx.x * blockDim.x + threadIdx.x;
    if (idx >= (size_t)Tn * ISHn) return;
    int t = (int)(idx / ISHn), c = (int)(idx % ISHn);
    size_t base = (size_t)t * SH2;
    float g = sgu[base + c], u = sgu[base + ISHn + c];
    hm[idx] = tf32r(g / (1.f + expf(-g)) * u);
}

// ---------------- out[t] += sum_z active: down[z][pos[z,t]] ----------------
__global__ void reduce_kernel(float* __restrict__ out, const float* __restrict__ down,
                              const int* __restrict__ pos) {
    int idx = blockIdx.x * blockDim.x + threadIdx.x;
    if (idx >= Tn * Hn) return;
    int t = idx / Hn, h = idx % Hn;
    float s = out[idx];
#pragma unroll
    for (int z = 0; z < Fn; z++) {
        int p = pos[z * Tn + t];
        if (p >= 0) s += down[((size_t)z * Tn + p) * Hn + h];
    }
    out[idx] = s;
}

// ---------------- cp.async tf32 GEMM: C[MxN] = A[MxK] * B[NxK]^T ----------------
// MODE 0: C=acc
// MODE 1: C=tf32r(acc*soft[tok[r], z, (n&63)>>3])
// MODE 2: C=C + colscale[n]*acc
// MODE 3: C=colscale[n]*acc
// MODE 4: C=rowscal[tok[r]*Fn+z]*(acc + mixadd[z,r,n])
#define KC 32
#define SM_LD 36
#define SM_BUF (128 * SM_LD)
#define STAGE_FLOATS (2 * SM_BUF)
#define SMEM_BYTES (3 * STAGE_FLOATS * 4)

template <int MODE>
__global__ void __launch_bounds__(256, 2)
gemm_tn(const float* __restrict__ A, int lda, size_t sA,
        const float* __restrict__ B, int ldb, size_t sB,
        float* __restrict__ C, int ldc, size_t sC,
        int N, int Ktot,
        const float* __restrict__ soft,
        const float* __restrict__ rowscal,
        const float* __restrict__ colscale, size_t sCs,
        const float* __restrict__ mixadd,
        const int* __restrict__ cntp,
        const int* __restrict__ tokp) {
    const int z = blockIdx.z;
    const int Mz = cntp ? cntp[z] : Tn;
    const int bm = blockIdx.y * 128, bn = blockIdx.x * 128;
    if (bm >= Mz) return;
    A += (size_t)z * sA;
    B += (size_t)z * sB;
    C += (size_t)z * sC;
    const float* cs = (MODE == 2 || MODE == 3) ? colscale + (size_t)z * sCs : nullptr;
    const float* mixp = (MODE == 4) ? mixadd + (size_t)z * sC : nullptr;
    const int* tk = (MODE == 1 || MODE == 4) ? tokp + z * Tn : nullptr;

    extern __shared__ float smf[];
    const uint32_t sbase = smem_u32(smf);
    const int tid = threadIdx.x, lane = tid & 31, wid = tid >> 5;
    const int wm = (wid >> 2) * 64, wn = (wid & 3) * 32;

    int arow[4], kq4[4];
#pragma unroll
    for (int i = 0; i < 4; i++) {
        int lin = tid + i * 256;
        arow[i] = lin >> 3;
        kq4[i] = (lin & 7) << 2;
    }
    float acc[4][4][4];
#pragma unroll
    for (int a = 0; a < 4; a++)
#pragma unroll
        for (int b = 0; b < 4; b++)
#pragma unroll
            for (int c = 0; c < 4; c++) acc[a][b][c] = 0.f;

    auto issue = [&](int kt, int s) {
        const int k0 = kt * KC;
#pragma unroll
        for (int i = 0; i < 4; i++) {
            uint32_t da = sbase + (uint32_t)((s * STAGE_FLOATS + arow[i] * SM_LD + kq4[i]) * 4);
            cpa16(da, A + (size_t)(bm + arow[i]) * lda + k0 + kq4[i], bm + arow[i] < Mz);
            uint32_t db = da + (uint32_t)(SM_BUF * 4);
            cpa16(db, B + (size_t)(bn + arow[i]) * ldb + k0 + kq4[i], bn + arow[i] < N);
        }
    };

    const int KT = Ktot / KC;
    issue(0, 0);
    CP_COMMIT();
    if (KT > 1) issue(1, 1);
    CP_COMMIT();

    for (int kt = 0; kt < KT; kt++) {
        CP_WAIT1();
        __syncthreads();
        if (kt + 2 < KT) issue(kt + 2, (kt + 2) % 3);
        CP_COMMIT();
        const float* Ab = smf + (kt % 3) * STAGE_FLOATS;
        const float* Bb = Ab + SM_BUF;
#pragma unroll
        for (int ks = 0; ks < 4; ks++) {
            int kk = ks * 8 + (lane & 3);
            float a[4][4], b[4][2];
#pragma unroll
            for (int mi = 0; mi < 4; mi++) {
                const float* p = Ab + (wm + mi * 16 + (lane >> 2)) * SM_LD + kk;
                a[mi][0] = p[0];
                a[mi][1] = p[8 * SM_LD];
                a[mi][2] = p[4];
                a[mi][3] = p[8 * SM_LD + 4];
            }
#pragma unroll
            for (int ni = 0; ni < 4; ni++) {
                const float* q = Bb + (wn + ni * 8 + (lane >> 2)) * SM_LD + kk;
                b[ni][0] = q[0];
                b[ni][1] = q[4];
            }
#pragma unroll
            for (int mi = 0; mi < 4; mi++)
#pragma unroll
                for (int ni = 0; ni < 4; ni++) MMA_TF32(acc[mi][ni], a[mi], b[ni]);
        }
    }

    // epilogue
#pragma unroll
    for (int mi = 0; mi < 4; mi++) {
#pragma unroll
        for (int ni = 0; ni < 4; ni++) {
            int cb = bn + wn + ni * 8;
            if (cb >= N) continue;
            int c = cb + ((lane & 3) << 1);
#pragma unroll
            for (int hh = 0; hh < 2; hh++) {
                int r = bm + wm + mi * 16 + (lane >> 2) + hh * 8;
                if (r >= Mz) continue;
                float v0 = acc[mi][ni][hh * 2 + 0];
                float v1 = acc[mi][ni][hh * 2 + 1];
                size_t off = (size_t)r * ldc + c;
                if (MODE == 1) {
                    float s = soft[((size_t)tk[r] * Fn + z) * Kn + ((c & 63) >> 3)];
                    v0 = tf32r(v0 * s);
                    v1 = tf32r(v1 * s);
                } else if (MODE == 2) {
                    float2 prev = *reinterpret_cast<const float2*>(&C[off]);
                    v0 = prev.x + cs[c] * v0;
                    v1 = prev.y + cs[c + 1] * v1;
                } else if (MODE == 3) {
                    v0 *= cs[c];
                    v1 *= cs[c + 1];
                } else if (MODE == 4) {
                    float rs = rowscal[(size_t)tk[r] * Fn + z];
                    float2 mv = *reinterpret_cast<const float2*>(&mixp[off]);
                    v0 = rs * (v0 + mv.x);
                    v1 = rs * (v1 + mv.y);
                }
                *reinterpret_cast<float2*>(&C[off]) = make_float2(v0, v1);
            }
        }
    }
}

// ---------------- host ----------------
#define SYMP(v, T) ({ void* _p = nullptr; cudaGetSymbolAddress(&_p, v); (T*)_p; })

extern "C" void kernel_launch(void* const* d_in, const int* in_sizes, int n_in,
                              void* d_out, int out_size) {
    const float* x          = (const float*)d_in[0];
    const float* gate_wt    = (const float*)d_in[1];
    const int*   inv        = (const int*)d_in[2];
    const float* mask_up_W  = (const float*)d_in[3];
    const float* gate_W     = (const float*)d_in[4];
    const float* gate_qa    = (const float*)d_in[5];
    const float* gate_qb    = (const float*)d_in[6];
    const float* gate_scale = (const float*)d_in[7];
    const float* up_W       = (const float*)d_in[8];
    const float* up_qa      = (const float*)d_in[9];
    const float* up_qb      = (const float*)d_in[10];
    const float* up_scale   = (const float*)d_in[11];
    const float* down_W     = (const float*)d_in[12];
    const float* down_qa    = (const float*)d_in[13];
    const float* down_qb    = (const float*)d_in[14];
    const float* down_scale = (const float*)d_in[15];
    const float* sh_gate_W  = (const float*)d_in[16];
    const float* sh_up_W    = (const float*)d_in[17];
    const float* sh_down_W  = (const float*)d_in[18];
    float* out = (float*)d_out;

    float* p_soft  = SYMP(g_soft, float);
    float* p_scal  = SYMP(g_scalar, float);
    int*   p_cnt   = SYMP(g_cnt, int);
    int*   p_tok   = SYMP(g_tok, int);
    int*   p_pos   = SYMP(g_pos, int);
    float* p_xe    = SYMP(g_xe, float);
    float* p_gu    = SYMP(g_gu, float);
    float* p_mgu   = SYMP(g_mgu, float);
    float* p_hmid  = SYMP(g_hmid, float);
    float* p_md    = SYMP(g_md, float);
    float* p_mixd  = SYMP(g_mixd, float);
    float* p_down  = SYMP(g_down, float);
    float* p_qbtgu = SYMP(g_qbtgu, float);
    float* p_qbtd  = SYMP(g_qbtd, float);
    float* p_shgu  = SYMP(g_shgu, float);
    float* p_shm   = SYMP(g_shm, float);
    float* p_wgu   = SYMP(g_wgu, float);
    float* p_wd    = SYMP(g_wd, float);
    float* p_qagu  = SYMP(g_qagu, float);
    float* p_qad   = SYMP(g_qad, float);
    float* p_sgu   = SYMP(g_sgu, float);
    float* p_shguw = SYMP(g_shguw, float);
    float* p_shdw  = SYMP(g_shdw, float);
    float* p_xr    = SYMP(g_xr, float);

#define SETUP(M)                                                                          \
    cudaFuncSetAttribute(gemm_tn<M>, cudaFuncAttributeMaxDynamicSharedMemorySize,         \
                         SMEM_BYTES);                                                     \
    cudaFuncSetAttribute(gemm_tn<M>, cudaFuncAttributePreferredSharedMemoryCarveout, 100)
    SETUP(0); SETUP(1); SETUP(2); SETUP(3); SETUP(4);
#undef SETUP

#define NB(n) ((int)(((n) + 255) / 256))
#define GRID(N, zc) dim3(((N) + 127) / 128, Tn / 128, zc)

    // 1. router (exact fp32)
    router_kernel<<<Tn, 128>>>(x, gate_wt, inv, p_soft, p_scal);
    // 2. deterministic token compaction
    compact_kernel<<<Fn, Tn>>>(p_scal, p_cnt, p_tok, p_pos);
    // 3. xe (compacted, rounded)
    xe_kernel<<<NB((size_t)Fn * Tn * Hn), 256>>>(x, mask_up_W, p_soft, p_cnt, p_tok, p_xe);
    // 4. fused gate/up weight + qa rounding (single launch)
    {
        long tot = 2L * (Fn * In * Hn / 4) + 2L * (Fn * KRn * Hn / 4);
        rc_gu<<<NB(tot), 256>>>((const float4*)gate_W, (const float4*)up_W,
                                (const float4*)gate_qa, (const float4*)up_qa,
                                (float4*)p_wgu, (float4*)p_qagu);
    }
    // 5. combined gate||up GEMM   <-- ncu target (launch #5)
    gemm_tn<0><<<GRID(IGU, Fn), 256, SMEM_BYTES>>>(
        p_xe, Hn, (size_t)Tn * Hn, p_wgu, Hn, (size_t)IGU * Hn,
        p_gu, IGU, (size_t)Tn * IGU, IGU, Hn, nullptr, nullptr, nullptr, 0, nullptr,
        p_cnt, nullptr);
    // 6. combined LoRA-a GEMM     <-- alt ncu target (launch #6)
    gemm_tn<1><<<GRID(128, Fn), 256, SMEM_BYTES>>>(
        p_xe, Hn, (size_t)Tn * Hn, p_qagu, Hn, (size_t)128 * Hn,
        p_mgu, 128, (size_t)Tn * 128, 128, Hn, p_soft, nullptr, nullptr, 0, nullptr,
        p_cnt, p_tok);

    // 7. block-diagonal qbt concat
    tq2_kernel<<<NB(Fn * IGU * 128), 256>>>(gate_qb, up_qb, p_qbtgu);
    // 8. scale concat (both halves)
    sc2<<<NB(2 * Fn * In), 256>>>(gate_scale, up_scale, p_sgu);
    // 9. combined mix GEMM, in-place
    gemm_tn<2><<<GRID(IGU, Fn), 256, SMEM_BYTES>>>(
        p_mgu, 128, (size_t)Tn * 128, p_qbtgu, 128, (size_t)IGU * 128,
        p_gu, IGU, (size_t)Tn * IGU, IGU, 128, nullptr, nullptr, p_sgu, IGU, nullptr,
        p_cnt, nullptr);
    // 10. hmid = silu(gate)*up
    fuse_kernel<<<NB((size_t)Fn * Tn * In), 256>>>(p_gu, p_cnt, p_hmid);

    // 11. down-path weight rounding (single launch)
    rc_down<<<NB((size_t)(Fn * Hn * In / 4) + (Fn * KRn * In / 4)), 256>>>(
        (const float4*)down_W, (const float4*)down_qa, (float4*)p_wd, (float4*)p_qad);
    // 12. down qbt
    tq_kernel<<<NB(Fn * Hn * KRn), 256>>>(down_qb, p_qbtd, Hn);
    // 13. down LoRA a
    gemm_tn<1><<<GRID(KRn, Fn), 256, SMEM_BYTES>>>(
        p_hmid, In, (size_t)Tn * In, p_qad, In, (size_t)KRn * In,
        p_md, KRn, (size_t)Tn * KRn, KRn, In, p_soft, nullptr, nullptr, 0, nullptr,
        p_cnt, p_tok);
    // 14. mixd
    gemm_tn<3><<<GRID(Hn, Fn), 256, SMEM_BYTES>>>(
        p_md, KRn, (size_t)Tn * KRn, p_qbtd, KRn, (size_t)Hn * KRn,
        p_mixd, Hn, (size_t)Tn * Hn, Hn, KRn, nullptr, nullptr, down_scale, Hn, nullptr,
        p_cnt, nullptr);
    // 15. down GEMM fused
    gemm_tn<4><<<GRID(Hn, Fn), 256, SMEM_BYTES>>>(
        p_hmid, In, (size_t)Tn * In, p_wd, In, (size_t)Hn * In,
        p_down, Hn, (size_t)Tn * Hn, Hn, In, nullptr, p_scal, nullptr, 0, p_mixd,
        p_cnt, p_tok);

    // 16. shared-path rounding (single launch)
    {
        int tot = Tn * Hn / 4 + 3 * (ISHn * Hn / 4);
        rc_sh<<<NB(tot), 256>>>((const float4*)x, (const float4*)sh_gate_W,
                                (const float4*)sh_up_W, (const float4*)sh_down_W,
                                (float4*)p_xr, (float4*)p_shguw, (float4*)p_shdw);
    }
    // 17. combined shared gate||up GEMM (N=5632)
    gemm_tn<0><<<GRID(SH2, 1), 256, SMEM_BYTES>>>(
        p_xr, Hn, 0, p_shguw, Hn, 0,
        p_shgu, SH2, 0, SH2, Hn, nullptr, nullptr, nullptr, 0, nullptr, nullptr, nullptr);
    // 18. swiglu
    swiglu_kernel<<<NB((size_t)Tn * ISHn), 256>>>(p_shgu, p_shm);
    // 19. shared down GEMM -> out
    gemm_tn<0><<<GRID(Hn, 1), 256, SMEM_BYTES>>>(
        p_shm, ISHn, 0, p_shdw, ISHn, 0,
        out, Hn, 0, Hn, ISHn, nullptr, nullptr, nullptr, 0, nullptr, nullptr, nullptr);

    // 20. out += gathered expert outputs
    reduce_kernel<<<NB(Tn * Hn), 256>>>(out, p_down, p_pos);

#undef NB
#undef GRID
    (void)in_sizes; (void)n_in; (void)out_size;
}

// round 9
// speedup vs baseline: 1.9505x; 1.0099x over previous
#include <cuda_runtime.h>
#include <cuda_bf16.h>
#include <math.h>
#include <cstdint>

#define Tn 1024
#define Hn 2048
#define In 1408
#define IGU 2816            // 2*In (gate||up concat)
#define En 64
#define Fn 8
#define Kn 8
#define Rn 8
#define ISHn 2816
#define SH2 5632            // 2*ISHn
#define TOPKn 6
#define KRn 64

// ---------------- scratch (device globals; allocation-free) ----------------
__device__ float g_soft[Tn * Fn * Kn];
__device__ float g_scalar[Tn * Fn];
__device__ int   g_cnt[Fn];
__device__ int   g_tok[Fn * Tn];
__device__ int   g_pos[Fn * Tn];
__device__ float g_xe[(size_t)Fn * Tn * Hn];
__device__ float g_gu[(size_t)Fn * Tn * IGU];      // gate||up outputs
__device__ float g_mgu[(size_t)Fn * Tn * 128];     // LoRA-a gate||up
__device__ float g_hmid[(size_t)Fn * Tn * In];
__device__ float g_md[(size_t)Fn * Tn * KRn];
__device__ float g_mixd[(size_t)Fn * Tn * Hn];
__device__ float g_down[(size_t)Fn * Tn * Hn];
__device__ float g_qbtgu[(size_t)Fn * IGU * 128];  // block-diag [qbtg 0; 0 qbtu]
__device__ float g_qbtd[(size_t)Fn * Hn * KRn];
__device__ float g_shgu[(size_t)Tn * SH2];
__device__ float g_shm[(size_t)Tn * ISHn];
__device__ float g_sgu[Fn * IGU];                  // gate_scale||up_scale (fp32)

// ---------------- helpers ----------------
__device__ __forceinline__ float tf32r(float x) {
    float y;
    asm("cvt.rna.tf32.f32 %0, %1;" : "=f"(y) : "f"(x));
    return y;
}
__device__ __forceinline__ uint32_t smem_u32(const void* p) {
    uint32_t a;
    asm("{ .reg .u64 t; cvta.to.shared.u64 t, %1; cvt.u32.u64 %0, t; }" : "=r"(a) : "l"(p));
    return a;
}
__device__ __forceinline__ void cpa16(uint32_t dst, const void* src, bool pred) {
    int sz = pred ? 16 : 0;
    asm volatile("cp.async.cg.shared.global [%0], [%1], 16, %2;"
                 :: "r"(dst), "l"(src), "r"(sz) : "memory");
}
#define CP_COMMIT() asm volatile("cp.async.commit_group;" ::: "memory")
#define CP_WAIT1() asm volatile("cp.async.wait_group 1;" ::: "memory")

#define MMA_TF32(d, a, b)                                                      \
    asm volatile(                                                              \
        "mma.sync.aligned.m16n8k8.row.col.f32.tf32.tf32.f32 "                  \
        "{%0,%1,%2,%3}, {%4,%5,%6,%7}, {%8,%9}, {%0,%1,%2,%3};\n"              \
        : "+f"((d)[0]), "+f"((d)[1]), "+f"((d)[2]), "+f"((d)[3])               \
        : "r"(__float_as_uint((a)[0])), "r"(__float_as_uint((a)[1])),          \
          "r"(__float_as_uint((a)[2])), "r"(__float_as_uint((a)[3])),          \
          "r"(__float_as_uint((b)[0])), "r"(__float_as_uint((b)[1])))

// ---------------- router (exact fp32: top-k must not flip) ----------------
__global__ void router_kernel(const float* __restrict__ x,
                              const float* __restrict__ gw,
                              const int* __restrict__ inv,
                              float* __restrict__ soft,
                              float* __restrict__ scal) {
    __shared__ float xs[Hn];
    __shared__ float sc[En];
    const int t = blockIdx.x;
    const int tid = threadIdx.x;  // 128 threads
    const float4* xv = reinterpret_cast<const float4*>(x + (size_t)t * Hn);
    for (int i = tid; i < Hn / 4; i += 128)
        reinterpret_cast<float4*>(xs)[i] = xv[i];
    __syncthreads();
    const int lane = tid & 31, w = tid >> 5;
    for (int e = w; e < En; e += 4) {
        const float* g = gw + (size_t)e * Hn;
        float s = 0.f;
        for (int h = lane; h < Hn; h += 32) s += xs[h] * g[h];
#pragma unroll
        for (int o = 16; o; o >>= 1) s += __shfl_xor_sync(0xffffffffu, s, o);
        if (lane == 0) sc[e] = s;
    }
    __syncthreads();
    if (tid == 0) {
        float mx = -1e30f;
        for (int e = 0; e < En; e++) mx = fmaxf(mx, sc[e]);
        float p[En];
        float sum = 0.f;
        for (int e = 0; e < En; e++) { p[e] = expf(sc[e] - mx); sum += p[e]; }
        float is = 1.f / sum;
        for (int e = 0; e < En; e++) p[e] *= is;
        float wv[En];
        for (int e = 0; e < En; e++) wv[e] = 0.f;
        for (int j = 0; j < TOPKn; j++) {
            int best = 0;
            float bv = -1.f;
            for (int e = 0; e < En; e++) {
                if (wv[e] == 0.f && p[e] > bv) { bv = p[e]; best = e; }
            }
            wv[best] = p[best];
        }
        for (int f = 0; f < Fn; f++) {
            float fl[Kn];
            float ssum = 0.f, fmx = -1e30f;
            for (int k = 0; k < Kn; k++) {
                int e = inv[f * Kn + k];
                float v = wv[e];
                ssum += v;
                float l = (v == 0.f) ? -1e9f : v;
                fl[k] = l;
                fmx = fmaxf(fmx, l);
            }
            float es = 0.f, ex[Kn];
            for (int k = 0; k < Kn; k++) { ex[k] = expf(fl[k] - fmx); es += ex[k]; }
            float ies = 1.f / es;
            for (int k = 0; k < Kn; k++)
                soft[((size_t)t * Fn + f) * Kn + k] = ex[k] * ies;
            scal[(size_t)t * Fn + f] = ssum;
        }
    }
}

// ---------------- deterministic per-group token compaction ----------------
__global__ void compact_kernel(const float* __restrict__ scal,
                               int* __restrict__ cnt,
                               int* __restrict__ tok,
                               int* __restrict__ pos) {
    const int z = blockIdx.x;
    const int t = threadIdx.x;  // Tn threads
    __shared__ int sbuf[Tn];
    int active = (scal[(size_t)t * Fn + z] != 0.f) ? 1 : 0;
    sbuf[t] = active;
    __syncthreads();
    for (int off = 1; off < Tn; off <<= 1) {
        int v = (t >= off) ? sbuf[t - off] : 0;
        __syncthreads();
        sbuf[t] += v;
        __syncthreads();
    }
    int incl = sbuf[t];
    if (active) {
        tok[z * Tn + incl - 1] = t;
        pos[z * Tn + t] = incl - 1;
    } else {
        pos[z * Tn + t] = -1;
    }
    if (t == Tn - 1) cnt[z] = incl;
}

// ---------------- xe (compacted; raw fp32, GEMM rounds at consumption) ----
__global__ void xe_kernel(const float* __restrict__ x,
                          const float* __restrict__ muW,
                          const float* __restrict__ soft,
                          const int* __restrict__ cnt,
                          const int* __restrict__ tok,
                          float* __restrict__ xe) {
    size_t idx = (size_t)blockIdx.x * blockDim.x + threadIdx.x;
    if (idx >= (size_t)Fn * Tn * Hn) return;
    int z = (int)(idx / ((size_t)Tn * Hn));
    int rem = (int)(idx % ((size_t)Tn * Hn));
    int i = rem / Hn, h = rem % Hn;
    if (i >= cnt[z]) return;
    int t = tok[z * Tn + i];
    const float* mw = muW + ((size_t)z * Hn + h) * Kn;
    const float* sf = soft + ((size_t)t * Fn + z) * Kn;
    float s = x[(size_t)t * Hn + h];
#pragma unroll
    for (int k = 0; k < Kn; k++) s += sf[k] * mw[k];
    xe[idx] = s;
}

// ---------------- qbt builders (layout only; GEMM rounds) ----------------
__global__ void tq2_kernel(const float* __restrict__ gqb, const float* __restrict__ uqb,
                           float* __restrict__ outp) {
    int total = Fn * IGU * 128;
    int idx = blockIdx.x * blockDim.x + threadIdx.x;
    if (idx >= total) return;
    int z = idx / (IGU * 128);
    int rem = idx % (IGU * 128);
    int n = rem >> 7, kr = rem & 127;
    float v = 0.f;
    if (n < In) {
        if (kr < 64) {
            int k = kr >> 3, r = kr & 7;
            v = gqb[(((size_t)z * Kn + k) * In + n) * Rn + r];
        }
    } else {
        if (kr >= 64) {
            int k = (kr - 64) >> 3, r = kr & 7;
            v = uqb[(((size_t)z * Kn + k) * In + (n - In)) * Rn + r];
        }
    }
    outp[idx] = v;
}
__global__ void tq_kernel(const float* __restrict__ qb, float* __restrict__ outp, int Nd) {
    int total = Fn * Nd * KRn;
    int idx = blockIdx.x * blockDim.x + threadIdx.x;
    if (idx >= total) return;
    int z = idx / (Nd * KRn);
    int rem = idx % (Nd * KRn);
    int n = rem >> 6, kr = rem & 63;
    int k = kr >> 3, r = kr & 7;
    outp[idx] = qb[(((size_t)z * Kn + k) * Nd + n) * Rn + r];
}

// ---------------- scale concat (fp32) ----------------
__global__ void sc2(const float* __restrict__ gs, const float* __restrict__ us,
                    float* __restrict__ sgu) {
    int i = blockIdx.x * blockDim.x + threadIdx.x;
    if (i >= 2 * Fn * In) return;
    int seg = i >= Fn * In;
    int j = i - seg * Fn * In;
    int z = j / In, r = j % In;
    sgu[z * IGU + seg * In + r] = (seg ? us : gs)[j];
}

// ---------------- hmid = silu(gate)*up (raw fp32) ----------------
__global__ void fuse_kernel(const float* __restrict__ gu,
                            const int* __restrict__ cnt,
                            float* __restrict__ hm) {
    size_t idx = (size_t)blockIdx.x * blockDim.x + threadIdx.x;
    if (idx >= (size_t)Fn * Tn * In) return;
    int z = (int)(idx / ((size_t)Tn * In));
    int rem = (int)(idx % ((size_t)Tn * In));
    int i = rem / In, c = rem % In;
    if (i >= cnt[z]) return;
    size_t base = ((size_t)z * Tn + i) * IGU;
    float g = gu[base + c], u = gu[base + In + c];
    hm[idx] = g / (1.f + expf(-g)) * u;
}

__global__ void swiglu_kernel(const float* __restrict__ sgu, float* __restrict__ hm) {
    size_t idx = (size_t)blockIdx.x * blockDim.x + threadIdx.x;
    if (idx >= (size_t)Tn * ISHn) return;
    int t = (int)(idx / ISHn), c = (int)(idx % ISHn);
    size_t base = (size_t)t * SH2;
    float g = sgu[base + c], u = sgu[base + ISHn + c];
    hm[idx] = g / (1.f + expf(-g)) * u;
}

// ---------------- out[t] += sum_z active: down[z][pos[z,t]] ----------------
__global__ void reduce_kernel(float* __restrict__ out, const float* __restrict__ down,
                              const int* __restrict__ pos) {
    int idx = blockIdx.x * blockDim.x + threadIdx.x;
    if (idx >= Tn * Hn) return;
    int t = idx / Hn, h = idx % Hn;
    float s = out[idx];
#pragma unroll
    for (int z = 0; z < Fn; z++) {
        int p = pos[z * Tn + t];
        if (p >= 0) s += down[((size_t)z * Tn + p) * Hn + h];
    }
    out[idx] = s;
}

// ---------------- cp.async tf32 GEMM with fragment rounding ----------------
// C[MxN] = rna(A)[MxK] * rna(Bcat)[NxK]^T, Bcat = B rows [0,nsplit) || B2 rows.
// Inputs are raw fp32; cvt.rna.tf32 applied to fragments before each MMA.
// MODE 0: C=acc
// MODE 1: C=acc*soft[tok[r], z, (n&63)>>3]
// MODE 2: C=C + colscale[n]*acc
// MODE 3: C=colscale[n]*acc
// MODE 4: C=rowscal[tok[r]*Fn+z]*(acc + mixadd[z,r,n])
#define KC 32
#define SM_LD 36
#define SM_BUF (128 * SM_LD)
#define STAGE_FLOATS (2 * SM_BUF)
#define SMEM_BYTES (3 * STAGE_FLOATS * 4)

template <int MODE>
__global__ void __launch_bounds__(256, 2)
gemm_tn(const float* __restrict__ A, int lda, size_t sA,
        const float* __restrict__ B, int ldb, size_t sB,
        const float* __restrict__ B2, int nsplit,
        float* __restrict__ C, int ldc, size_t sC,
        int N, int Ktot,
        const float* __restrict__ soft,
        const float* __restrict__ rowscal,
        const float* __restrict__ colscale, size_t sCs,
        const float* __restrict__ mixadd,
        const int* __restrict__ cntp,
        const int* __restrict__ tokp) {
    const int z = blockIdx.z;
    const int Mz = cntp ? cntp[z] : Tn;
    const int bm = blockIdx.y * 128, bn = blockIdx.x * 128;
    if (bm >= Mz) return;
    A += (size_t)z * sA;
    B += (size_t)z * sB;
    B2 += (size_t)z * sB;
    C += (size_t)z * sC;
    const float* cs = (MODE == 2 || MODE == 3) ? colscale + (size_t)z * sCs : nullptr;
    const float* mixp = (MODE == 4) ? mixadd + (size_t)z * sC : nullptr;
    const int* tk = (MODE == 1 || MODE == 4) ? tokp + z * Tn : nullptr;

    extern __shared__ float smf[];
    const uint32_t sbase = smem_u32(smf);
    const int tid = threadIdx.x, lane = tid & 31, wid = tid >> 5;
    const int wm = (wid >> 2) * 64, wn = (wid & 3) * 32;

    int arow[4], kq4[4];
#pragma unroll
    for (int i = 0; i < 4; i++) {
        int lin = tid + i * 256;
        arow[i] = lin >> 3;
        kq4[i] = (lin & 7) << 2;
    }
    float acc[4][4][4];
#pragma unroll
    for (int a = 0; a < 4; a++)
#pragma unroll
        for (int b = 0; b < 4; b++)
#pragma unroll
            for (int c = 0; c < 4; c++) acc[a][b][c] = 0.f;

    auto issue = [&](int kt, int s) {
        const int k0 = kt * KC;
#pragma unroll
        for (int i = 0; i < 4; i++) {
            uint32_t da = sbase + (uint32_t)((s * STAGE_FLOATS + arow[i] * SM_LD + kq4[i]) * 4);
            cpa16(da, A + (size_t)(bm + arow[i]) * lda + k0 + kq4[i], bm + arow[i] < Mz);
            uint32_t db = da + (uint32_t)(SM_BUF * 4);
            int n = bn + arow[i];
            const float* bs = (n < nsplit) ? B + (size_t)n * ldb
                                           : B2 + (size_t)(n - nsplit) * ldb;
            cpa16(db, bs + k0 + kq4[i], n < N);
        }
    };

    const int KT = Ktot / KC;
    issue(0, 0);
    CP_COMMIT();
    if (KT > 1) issue(1, 1);
    CP_COMMIT();

    for (int kt = 0; kt < KT; kt++) {
        CP_WAIT1();
        __syncthreads();
        if (kt + 2 < KT) issue(kt + 2, (kt + 2) % 3);
        CP_COMMIT();
        const float* Ab = smf + (kt % 3) * STAGE_FLOATS;
        const float* Bb = Ab + SM_BUF;
#pragma unroll
        for (int ks = 0; ks < 4; ks++) {
            int kk = ks * 8 + (lane & 3);
            float a[4][4], b[4][2];
#pragma unroll
            for (int mi = 0; mi < 4; mi++) {
                const float* p = Ab + (wm + mi * 16 + (lane >> 2)) * SM_LD + kk;
                a[mi][0] = tf32r(p[0]);
                a[mi][1] = tf32r(p[8 * SM_LD]);
                a[mi][2] = tf32r(p[4]);
                a[mi][3] = tf32r(p[8 * SM_LD + 4]);
            }
#pragma unroll
            for (int ni = 0; ni < 4; ni++) {
                const float* q = Bb + (wn + ni * 8 + (lane >> 2)) * SM_LD + kk;
                b[ni][0] = tf32r(q[0]);
                b[ni][1] = tf32r(q[4]);
            }
#pragma unroll
            for (int mi = 0; mi < 4; mi++)
#pragma unroll
                for (int ni = 0; ni < 4; ni++) MMA_TF32(acc[mi][ni], a[mi], b[ni]);
        }
    }

    // epilogue
#pragma unroll
    for (int mi = 0; mi < 4; mi++) {
#pragma unroll
        for (int ni = 0; ni < 4; ni++) {
            int cb = bn + wn + ni * 8;
            if (cb >= N) continue;
            int c = cb + ((lane & 3) << 1);
#pragma unroll
            for (int hh = 0; hh < 2; hh++) {
                int r = bm + wm + mi * 16 + (lane >> 2) + hh * 8;
                if (r >= Mz) continue;
                float v0 = acc[mi][ni][hh * 2 + 0];
                float v1 = acc[mi][ni][hh * 2 + 1];
                size_t off = (size_t)r * ldc + c;
                if (MODE == 1) {
                    float s = soft[((size_t)tk[r] * Fn + z) * Kn + ((c & 63) >> 3)];
                    v0 *= s;
                    v1 *= s;
                } else if (MODE == 2) {
                    float2 prev = *reinterpret_cast<const float2*>(&C[off]);
                    v0 = prev.x + cs[c] * v0;
                    v1 = prev.y + cs[c + 1] * v1;
                } else if (MODE == 3) {
                    v0 *= cs[c];
                    v1 *= cs[c + 1];
                } else if (MODE == 4) {
                    float rs = rowscal[(size_t)tk[r] * Fn + z];
                    float2 mv = *reinterpret_cast<const float2*>(&mixp[off]);
                    v0 = rs * (v0 + mv.x);
                    v1 = rs * (v1 + mv.y);
                }
                *reinterpret_cast<float2*>(&C[off]) = make_float2(v0, v1);
            }
        }
    }
}

// ---------------- host ----------------
#define SYMP(v, T) ({ void* _p = nullptr; cudaGetSymbolAddress(&_p, v); (T*)_p; })

extern "C" void kernel_launch(void* const* d_in, const int* in_sizes, int n_in,
                              void* d_out, int out_size) {
    const float* x          = (const float*)d_in[0];
    const float* gate_wt    = (const float*)d_in[1];
    const int*   inv        = (const int*)d_in[2];
    const float* mask_up_W  = (const float*)d_in[3];
    const float* gate_W     = (const float*)d_in[4];
    const float* gate_qa    = (const float*)d_in[5];
    const float* gate_qb    = (const float*)d_in[6];
    const float* gate_scale = (const float*)d_in[7];
    const float* up_W       = (const float*)d_in[8];
    const float* up_qa      = (const float*)d_in[9];
    const float* up_qb      = (const float*)d_in[10];
    const float* up_scale   = (const float*)d_in[11];
    const float* down_W     = (const float*)d_in[12];
    const float* down_qa    = (const float*)d_in[13];
    const float* down_qb    = (const float*)d_in[14];
    const float* down_scale = (const float*)d_in[15];
    const float* sh_gate_W  = (const float*)d_in[16];
    const float* sh_up_W    = (const float*)d_in[17];
    const float* sh_down_W  = (const float*)d_in[18];
    float* out = (float*)d_out;

    float* p_soft  = SYMP(g_soft, float);
    float* p_scal  = SYMP(g_scalar, float);
    int*   p_cnt   = SYMP(g_cnt, int);
    int*   p_tok   = SYMP(g_tok, int);
    int*   p_pos   = SYMP(g_pos, int);
    float* p_xe    = SYMP(g_xe, float);
    float* p_gu    = SYMP(g_gu, float);
    float* p_mgu   = SYMP(g_mgu, float);
    float* p_hmid  = SYMP(g_hmid, float);
    float* p_md    = SYMP(g_md, float);
    float* p_mixd  = SYMP(g_mixd, float);
    float* p_down  = SYMP(g_down, float);
    float* p_qbtgu = SYMP(g_qbtgu, float);
    float* p_qbtd  = SYMP(g_qbtd, float);
    float* p_shgu  = SYMP(g_shgu, float);
    float* p_shm   = SYMP(g_shm, float);
    float* p_sgu   = SYMP(g_sgu, float);

#define SETUP(M)                                                                          \
    cudaFuncSetAttribute(gemm_tn<M>, cudaFuncAttributeMaxDynamicSharedMemorySize,         \
                         SMEM_BYTES);                                                     \
    cudaFuncSetAttribute(gemm_tn<M>, cudaFuncAttributePreferredSharedMemoryCarveout, 100)
    SETUP(0); SETUP(1); SETUP(2); SETUP(3); SETUP(4);
#undef SETUP

#define NB(n) ((int)(((n) + 255) / 256))
#define GRID(N, zc) dim3(((N) + 127) / 128, Tn / 128, zc)

    // 1. router (exact fp32)
    router_kernel<<<Tn, 128>>>(x, gate_wt, inv, p_soft, p_scal);
    // 2. deterministic token compaction
    compact_kernel<<<Fn, Tn>>>(p_scal, p_cnt, p_tok, p_pos);
    // 3. xe (compacted)
    xe_kernel<<<NB((size_t)Fn * Tn * Hn), 256>>>(x, mask_up_W, p_soft, p_cnt, p_tok, p_xe);

    // 4. combined gate||up GEMM (B = gate_W rows [0,In), B2 = up_W)
    gemm_tn<0><<<GRID(IGU, Fn), 256, SMEM_BYTES>>>(
        p_xe, Hn, (size_t)Tn * Hn, gate_W, Hn, (size_t)In * Hn, up_W, In,
        p_gu, IGU, (size_t)Tn * IGU, IGU, Hn, nullptr, nullptr, nullptr, 0, nullptr,
        p_cnt, nullptr);
    // 5. combined LoRA-a GEMM (B = gate_qa rows [0,64), B2 = up_qa)
    gemm_tn<1><<<GRID(128, Fn), 256, SMEM_BYTES>>>(
        p_xe, Hn, (size_t)Tn * Hn, gate_qa, Hn, (size_t)KRn * Hn, up_qa, KRn,
        p_mgu, 128, (size_t)Tn * 128, 128, Hn, p_soft, nullptr, nullptr, 0, nullptr,
        p_cnt, p_tok);

    // 6. block-diagonal qbt concat (layout only)
    tq2_kernel<<<NB(Fn * IGU * 128), 256>>>(gate_qb, up_qb, p_qbtgu);
    // 7. scale concat
    sc2<<<NB(2 * Fn * In), 256>>>(gate_scale, up_scale, p_sgu);
    // 8. combined mix GEMM, in-place
    gemm_tn<2><<<GRID(IGU, Fn), 256, SMEM_BYTES>>>(
        p_mgu, 128, (size_t)Tn * 128, p_qbtgu, 128, (size_t)IGU * 128, p_qbtgu, IGU,
        p_gu, IGU, (size_t)Tn * IGU, IGU, 128, nullptr, nullptr, p_sgu, IGU, nullptr,
        p_cnt, nullptr);
    // 9. hmid = silu(gate)*up
    fuse_kernel<<<NB((size_t)Fn * Tn * In), 256>>>(p_gu, p_cnt, p_hmid);

    // 10. down qbt (layout only)
    tq_kernel<<<NB(Fn * Hn * KRn), 256>>>(down_qb, p_qbtd, Hn);
    // 11. down LoRA a (B = down_qa raw)
    gemm_tn<1><<<GRID(KRn, Fn), 256, SMEM_BYTES>>>(
        p_hmid, In, (size_t)Tn * In, down_qa, In, (size_t)KRn * In, down_qa, KRn,
        p_md, KRn, (size_t)Tn * KRn, KRn, In, p_soft, nullptr, nullptr, 0, nullptr,
        p_cnt, p_tok);
    // 12. mixd
    gemm_tn<3><<<GRID(Hn, Fn), 256, SMEM_BYTES>>>(
        p_md, KRn, (size_t)Tn * KRn, p_qbtd, KRn, (size_t)Hn * KRn, p_qbtd, Hn,
        p_mixd, Hn, (size_t)Tn * Hn, Hn, KRn, nullptr, nullptr, down_scale, Hn, nullptr,
        p_cnt, nullptr);
    // 13. down GEMM fused (B = down_W raw)
    gemm_tn<4><<<GRID(Hn, Fn), 256, SMEM_BYTES>>>(
        p_hmid, In, (size_t)Tn * In, down_W, In, (size_t)Hn * In, down_W, Hn,
        p_down, Hn, (size_t)Tn * Hn, Hn, In, nullptr, p_scal, nullptr, 0, p_mixd,
        p_cnt, p_tok);

    // 14. combined shared gate||up GEMM (A = x raw; B = sh_gate_W, B2 = sh_up_W)
    gemm_tn<0><<<GRID(SH2, 1), 256, SMEM_BYTES>>>(
        x, Hn, 0, sh_gate_W, Hn, 0, sh_up_W, ISHn,
        p_shgu, SH2, 0, SH2, Hn, nullptr, nullptr, nullptr, 0, nullptr, nullptr, nullptr);
    // 15. swiglu
    swiglu_kernel<<<NB((size_t)Tn * ISHn), 256>>>(p_shgu, p_shm);
    // 16. shared down GEMM -> out (B = sh_down_W raw)
    gemm_tn<0><<<GRID(Hn, 1), 256, SMEM_BYTES>>>(
        p_shm, ISHn, 0, sh_down_W, ISHn, 0, sh_down_W, Hn,
        out, Hn, 0, Hn, ISHn, nullptr, nullptr, nullptr, 0, nullptr, nullptr, nullptr);

    // 17. out += gathered expert outputs
    reduce_kernel<<<NB(Tn * Hn), 256>>>(out, p_down, p_pos);

#undef NB
#undef GRID
    (void)in_sizes; (void)n_in; (void)out_size;
}

// round 10
// speedup vs baseline: 1.9783x; 1.0142x over previous
#include <cuda_runtime.h>
#include <cuda_bf16.h>
#include <math.h>
#include <cstdint>

#define Tn 1024
#define Hn 2048
#define In 1408
#define IGU 2816            // 2*In (gate||up concat)
#define En 64
#define Fn 8
#define Kn 8
#define Rn 8
#define ISHn 2816
#define SH2 5632            // 2*ISHn
#define TOPKn 6
#define KRn 64

// ---------------- scratch (device globals; allocation-free) ----------------
__device__ float g_soft[Tn * Fn * Kn];
__device__ float g_scalar[Tn * Fn];
__device__ int   g_cnt[Fn];
__device__ int   g_tok[Fn * Tn];
__device__ int   g_pos[Fn * Tn];
__device__ float g_xe[(size_t)Fn * Tn * Hn];
__device__ float g_gu[(size_t)Fn * Tn * IGU];      // gate||up outputs
__device__ float g_mgu[(size_t)Fn * Tn * 128];     // LoRA-a gate||up (rounded)
__device__ float g_hmid[(size_t)Fn * Tn * In];
__device__ float g_md[(size_t)Fn * Tn * KRn];
__device__ float g_mixd[(size_t)Fn * Tn * Hn];
__device__ float g_down[(size_t)Fn * Tn * Hn];
__device__ float g_qbtgu[(size_t)Fn * IGU * 128];  // block-diag, pre-rounded
__device__ float g_qbtd[(size_t)Fn * Hn * KRn];    // pre-rounded
__device__ float g_shgu[(size_t)Tn * SH2];
__device__ float g_shm[(size_t)Tn * ISHn];
__device__ float g_sgu[Fn * IGU];                  // gate_scale||up_scale (fp32)
__device__ float g_xr[(size_t)Tn * Hn];            // rounded x (shared path A)

// ---------------- helpers ----------------
__device__ __forceinline__ float tf32r(float x) {
    float y;
    asm("cvt.rna.tf32.f32 %0, %1;" : "=f"(y) : "f"(x));
    return y;
}
__device__ __forceinline__ uint32_t smem_u32(const void* p) {
    uint32_t a;
    asm("{ .reg .u64 t; cvta.to.shared.u64 t, %1; cvt.u32.u64 %0, t; }" : "=r"(a) : "l"(p));
    return a;
}
__device__ __forceinline__ void cpa16(uint32_t dst, const void* src, bool pred) {
    int sz = pred ? 16 : 0;
    asm volatile("cp.async.cg.shared.global [%0], [%1], 16, %2;"
                 :: "r"(dst), "l"(src), "r"(sz) : "memory");
}
#define CP_COMMIT() asm volatile("cp.async.commit_group;" ::: "memory")
#define CP_WAIT1() asm volatile("cp.async.wait_group 1;" ::: "memory")

#define MMA_TF32(d, a, b)                                                      \
    asm volatile(                                                              \
        "mma.sync.aligned.m16n8k8.row.col.f32.tf32.tf32.f32 "                  \
        "{%0,%1,%2,%3}, {%4,%5,%6,%7}, {%8,%9}, {%0,%1,%2,%3};\n"              \
        : "+f"((d)[0]), "+f"((d)[1]), "+f"((d)[2]), "+f"((d)[3])               \
        : "r"(__float_as_uint((a)[0])), "r"(__float_as_uint((a)[1])),          \
          "r"(__float_as_uint((a)[2])), "r"(__float_as_uint((a)[3])),          \
          "r"(__float_as_uint((b)[0])), "r"(__float_as_uint((b)[1])))

// ---------------- rounding copy (fp32 -> tf32 RNA), for x only ----------------
__global__ void round_copy(const float4* __restrict__ in, float4* __restrict__ out, int n4) {
    int i = blockIdx.x * blockDim.x + threadIdx.x;
    if (i >= n4) return;
    float4 v = in[i];
    v.x = tf32r(v.x); v.y = tf32r(v.y); v.z = tf32r(v.z); v.w = tf32r(v.w);
    out[i] = v;
}

// ---------------- router (exact fp32: top-k must not flip) ----------------
__global__ void router_kernel(const float* __restrict__ x,
                              const float* __restrict__ gw,
                              const int* __restrict__ inv,
                              float* __restrict__ soft,
                              float* __restrict__ scal) {
    __shared__ float xs[Hn];
    __shared__ float sc[En];
    const int t = blockIdx.x;
    const int tid = threadIdx.x;  // 128 threads
    const float4* xv = reinterpret_cast<const float4*>(x + (size_t)t * Hn);
    for (int i = tid; i < Hn / 4; i += 128)
        reinterpret_cast<float4*>(xs)[i] = xv[i];
    __syncthreads();
    const int lane = tid & 31, w = tid >> 5;
    for (int e = w; e < En; e += 4) {
        const float* g = gw + (size_t)e * Hn;
        float s = 0.f;
        for (int h = lane; h < Hn; h += 32) s += xs[h] * g[h];
#pragma unroll
        for (int o = 16; o; o >>= 1) s += __shfl_xor_sync(0xffffffffu, s, o);
        if (lane == 0) sc[e] = s;
    }
    __syncthreads();
    if (tid == 0) {
        float mx = -1e30f;
        for (int e = 0; e < En; e++) mx = fmaxf(mx, sc[e]);
        float p[En];
        float sum = 0.f;
        for (int e = 0; e < En; e++) { p[e] = expf(sc[e] - mx); sum += p[e]; }
        float is = 1.f / sum;
        for (int e = 0; e < En; e++) p[e] *= is;
        float wv[En];
        for (int e = 0; e < En; e++) wv[e] = 0.f;
        for (int j = 0; j < TOPKn; j++) {
            int best = 0;
            float bv = -1.f;
            for (int e = 0; e < En; e++) {
                if (wv[e] == 0.f && p[e] > bv) { bv = p[e]; best = e; }
            }
            wv[best] = p[best];
        }
        for (int f = 0; f < Fn; f++) {
            float fl[Kn];
            float ssum = 0.f, fmx = -1e30f;
            for (int k = 0; k < Kn; k++) {
                int e = inv[f * Kn + k];
                float v = wv[e];
                ssum += v;
                float l = (v == 0.f) ? -1e9f : v;
                fl[k] = l;
                fmx = fmaxf(fmx, l);
            }
            float es = 0.f, ex[Kn];
            for (int k = 0; k < Kn; k++) { ex[k] = expf(fl[k] - fmx); es += ex[k]; }
            float ies = 1.f / es;
            for (int k = 0; k < Kn; k++)
                soft[((size_t)t * Fn + f) * Kn + k] = ex[k] * ies;
            scal[(size_t)t * Fn + f] = ssum;
        }
    }
}

// ---------------- deterministic per-group token compaction ----------------
__global__ void compact_kernel(const float* __restrict__ scal,
                               int* __restrict__ cnt,
                               int* __restrict__ tok,
                               int* __restrict__ pos) {
    const int z = blockIdx.x;
    const int t = threadIdx.x;  // Tn threads
    __shared__ int sbuf[Tn];
    int active = (scal[(size_t)t * Fn + z] != 0.f) ? 1 : 0;
    sbuf[t] = active;
    __syncthreads();
    for (int off = 1; off < Tn; off <<= 1) {
        int v = (t >= off) ? sbuf[t - off] : 0;
        __syncthreads();
        sbuf[t] += v;
        __syncthreads();
    }
    int incl = sbuf[t];
    if (active) {
        tok[z * Tn + incl - 1] = t;
        pos[z * Tn + t] = incl - 1;
    } else {
        pos[z * Tn + t] = -1;
    }
    if (t == Tn - 1) cnt[z] = incl;
}

// ---------------- xe (compacted, tf32-rounded at write) ----------------
__global__ void xe_kernel(const float* __restrict__ x,
                          const float* __restrict__ muW,
                          const float* __restrict__ soft,
                          const int* __restrict__ cnt,
                          const int* __restrict__ tok,
                          float* __restrict__ xe) {
    size_t idx = (size_t)blockIdx.x * blockDim.x + threadIdx.x;
    if (idx >= (size_t)Fn * Tn * Hn) return;
    int z = (int)(idx / ((size_t)Tn * Hn));
    int rem = (int)(idx % ((size_t)Tn * Hn));
    int i = rem / Hn, h = rem % Hn;
    if (i >= cnt[z]) return;
    int t = tok[z * Tn + i];
    const float* mw = muW + ((size_t)z * Hn + h) * Kn;
    const float* sf = soft + ((size_t)t * Fn + z) * Kn;
    float s = x[(size_t)t * Hn + h];
#pragma unroll
    for (int k = 0; k < Kn; k++) s += sf[k] * mw[k];
    xe[idx] = tf32r(s);
}

// ---------------- qbt builders (pre-rounded; B-cvt is idempotent) ----------
__global__ void tq2_kernel(const float* __restrict__ gqb, const float* __restrict__ uqb,
                           float* __restrict__ outp) {
    int total = Fn * IGU * 128;
    int idx = blockIdx.x * blockDim.x + threadIdx.x;
    if (idx >= total) return;
    int z = idx / (IGU * 128);
    int rem = idx % (IGU * 128);
    int n = rem >> 7, kr = rem & 127;
    float v = 0.f;
    if (n < In) {
        if (kr < 64) {
            int k = kr >> 3, r = kr & 7;
            v = tf32r(gqb[(((size_t)z * Kn + k) * In + n) * Rn + r]);
        }
    } else {
        if (kr >= 64) {
            int k = (kr - 64) >> 3, r = kr & 7;
            v = tf32r(uqb[(((size_t)z * Kn + k) * In + (n - In)) * Rn + r]);
        }
    }
    outp[idx] = v;
}
__global__ void tq_kernel(const float* __restrict__ qb, float* __restrict__ outp, int Nd) {
    int total = Fn * Nd * KRn;
    int idx = blockIdx.x * blockDim.x + threadIdx.x;
    if (idx >= total) return;
    int z = idx / (Nd * KRn);
    int rem = idx % (Nd * KRn);
    int n = rem >> 6, kr = rem & 63;
    int k = kr >> 3, r = kr & 7;
    outp[idx] = tf32r(qb[(((size_t)z * Kn + k) * Nd + n) * Rn + r]);
}

// ---------------- scale concat (fp32) ----------------
__global__ void sc2(const float* __restrict__ gs, const float* __restrict__ us,
                    float* __restrict__ sgu) {
    int i = blockIdx.x * blockDim.x + threadIdx.x;
    if (i >= 2 * Fn * In) return;
    int seg = i >= Fn * In;
    int j = i - seg * Fn * In;
    int z = j / In, r = j % In;
    sgu[z * IGU + seg * In + r] = (seg ? us : gs)[j];
}

// ---------------- hmid = silu(gate)*up (rounded) ----------------
__global__ void fuse_kernel(const float* __restrict__ gu,
                            const int* __restrict__ cnt,
                            float* __restrict__ hm) {
    size_t idx = (size_t)blockIdx.x * blockDim.x + threadIdx.x;
    if (idx >= (size_t)Fn * Tn * In) return;
    int z = (int)(idx / ((size_t)Tn * In));
    int rem = (int)(idx % ((size_t)Tn * In));
    int i = rem / In, c = rem % In;
    if (i >= cnt[z]) return;
    size_t base = ((size_t)z * Tn + i) * IGU;
    float g = gu[base + c], u = gu[base + In + c];
    hm[idx] = tf32r(g / (1.f + expf(-g)) * u);
}

__global__ void swiglu_kernel(const float* __restrict__ sgu, float* __restrict__ hm) {
    size_t idx = (size_t)blockIdx.x * blockDim.x + threadIdx.x;
    if (idx >= (size_t)Tn * ISHn) return;
    int t = (int)(idx / ISHn), c = (int)(idx % ISHn);
    size_t base = (size_t)t * SH2;
    float g = sgu[base + c], u = sgu[base + ISHn + c];
    hm[idx] = tf32r(g / (1.f + expf(-g)) * u);
}

// ---------------- out[t] += sum_z active: down[z][pos[z,t]] ----------------
__global__ void reduce_kernel(float* __restrict__ out, const float* __restrict__ down,
                              const int* __restrict__ pos) {
    int idx = blockIdx.x * blockDim.x + threadIdx.x;
    if (idx >= Tn * Hn) return;
    int t = idx / Hn, h = idx % Hn;
    float s = out[idx];
#pragma unroll
    for (int z = 0; z < Fn; z++) {
        int p = pos[z * Tn + t];
        if (p >= 0) s += down[((size_t)z * Tn + p) * Hn + h];
    }
    out[idx] = s;
}

// ---------------- cp.async tf32 GEMM, tile 64x128 ----------------
// C[MxN] = A[MxK] * rna(Bcat)[NxK]^T. A must be pre-rounded to tf32;
// B fragments are rounded in-register (idempotent on pre-rounded scratch).
// Bcat = B rows [0,nsplit) || B2 rows.
// MODE 0: C=acc
// MODE 1: C=tf32r(acc*soft[tok[r], z, (n&63)>>3])
// MODE 2: C=C + colscale[n]*acc
// MODE 3: C=colscale[n]*acc
// MODE 4: C=rowscal[tok[r]*Fn+z]*(acc + mixadd[z,r,n])
#define KC 32
#define SM_LD 36
#define ABUF (64 * SM_LD)
#define BBUF (128 * SM_LD)
#define STAGE_FLOATS (ABUF + BBUF)
#define SMEM_BYTES (3 * STAGE_FLOATS * 4)

template <int MODE>
__global__ void __launch_bounds__(256, 2)
gemm_tn(const float* __restrict__ A, int lda, size_t sA,
        const float* __restrict__ B, int ldb, size_t sB,
        const float* __restrict__ B2, int nsplit,
        float* __restrict__ C, int ldc, size_t sC,
        int N, int Ktot,
        const float* __restrict__ soft,
        const float* __restrict__ rowscal,
        const float* __restrict__ colscale, size_t sCs,
        const float* __restrict__ mixadd,
        const int* __restrict__ cntp,
        const int* __restrict__ tokp) {
    const int z = blockIdx.z;
    const int Mz = cntp ? cntp[z] : Tn;
    const int bm = blockIdx.y * 64, bn = blockIdx.x * 128;
    if (bm >= Mz) return;
    A += (size_t)z * sA;
    B += (size_t)z * sB;
    B2 += (size_t)z * sB;
    C += (size_t)z * sC;
    const float* cs = (MODE == 2 || MODE == 3) ? colscale + (size_t)z * sCs : nullptr;
    const float* mixp = (MODE == 4) ? mixadd + (size_t)z * sC : nullptr;
    const int* tk = (MODE == 1 || MODE == 4) ? tokp + z * Tn : nullptr;

    extern __shared__ float smf[];
    const uint32_t sbase = smem_u32(smf);
    const int tid = threadIdx.x, lane = tid & 31, wid = tid >> 5;
    const int wm = (wid >> 2) * 32, wn = (wid & 3) * 32;

    float acc[2][4][4];
#pragma unroll
    for (int a = 0; a < 2; a++)
#pragma unroll
        for (int b = 0; b < 4; b++)
#pragma unroll
            for (int c = 0; c < 4; c++) acc[a][b][c] = 0.f;

    auto issue = [&](int kt, int s) {
        const int k0 = kt * KC;
        // A tile: 64 rows x 8 chunks = 512 cp.async / 256 threads = 2 each
#pragma unroll
        for (int i = 0; i < 2; i++) {
            int lin = tid + i * 256;
            int r = lin >> 3, cf = (lin & 7) << 2;
            uint32_t da = sbase + (uint32_t)((s * STAGE_FLOATS + r * SM_LD + cf) * 4);
            cpa16(da, A + (size_t)(bm + r) * lda + k0 + cf, bm + r < Mz);
        }
        // B tile: 128 rows x 8 chunks = 1024 / 256 = 4 each
#pragma unroll
        for (int i = 0; i < 4; i++) {
            int lin = tid + i * 256;
            int r = lin >> 3, cf = (lin & 7) << 2;
            uint32_t db = sbase + (uint32_t)((s * STAGE_FLOATS + ABUF + r * SM_LD + cf) * 4);
            int n = bn + r;
            const float* bs = (n < nsplit) ? B + (size_t)n * ldb
                                           : B2 + (size_t)(n - nsplit) * ldb;
            cpa16(db, bs + k0 + cf, n < N);
        }
    };

    const int KT = Ktot / KC;
    issue(0, 0);
    CP_COMMIT();
    if (KT > 1) issue(1, 1);
    CP_COMMIT();

    for (int kt = 0; kt < KT; kt++) {
        CP_WAIT1();
        __syncthreads();
        if (kt + 2 < KT) issue(kt + 2, (kt + 2) % 3);
        CP_COMMIT();
        const float* Ab = smf + (kt % 3) * STAGE_FLOATS;
        const float* Bb = Ab + ABUF;
#pragma unroll
        for (int ks = 0; ks < 4; ks++) {
            int kk = ks * 8 + (lane & 3);
            float a[2][4], b[4][2];
#pragma unroll
            for (int mi = 0; mi < 2; mi++) {
                const float* p = Ab + (wm + mi * 16 + (lane >> 2)) * SM_LD + kk;
                a[mi][0] = p[0];
                a[mi][1] = p[8 * SM_LD];
                a[mi][2] = p[4];
                a[mi][3] = p[8 * SM_LD + 4];
            }
#pragma unroll
            for (int ni = 0; ni < 4; ni++) {
                const float* q = Bb + (wn + ni * 8 + (lane >> 2)) * SM_LD + kk;
                b[ni][0] = tf32r(q[0]);
                b[ni][1] = tf32r(q[4]);
            }
#pragma unroll
            for (int mi = 0; mi < 2; mi++)
#pragma unroll
                for (int ni = 0; ni < 4; ni++) MMA_TF32(acc[mi][ni], a[mi], b[ni]);
        }
    }

    // epilogue
#pragma unroll
    for (int mi = 0; mi < 2; mi++) {
#pragma unroll
        for (int ni = 0; ni < 4; ni++) {
            int cb = bn + wn + ni * 8;
            if (cb >= N) continue;
            int c = cb + ((lane & 3) << 1);
#pragma unroll
            for (int hh = 0; hh < 2; hh++) {
                int r = bm + wm + mi * 16 + (lane >> 2) + hh * 8;
                if (r >= Mz) continue;
                float v0 = acc[mi][ni][hh * 2 + 0];
                float v1 = acc[mi][ni][hh * 2 + 1];
                size_t off = (size_t)r * ldc + c;
                if (MODE == 1) {
                    float s = soft[((size_t)tk[r] * Fn + z) * Kn + ((c & 63) >> 3)];
                    v0 = tf32r(v0 * s);
                    v1 = tf32r(v1 * s);
                } else if (MODE == 2) {
                    float2 prev = *reinterpret_cast<const float2*>(&C[off]);
                    v0 = prev.x + cs[c] * v0;
                    v1 = prev.y + cs[c + 1] * v1;
                } else if (MODE == 3) {
                    v0 *= cs[c];
                    v1 *= cs[c + 1];
                } else if (MODE == 4) {
                    float rs = rowscal[(size_t)tk[r] * Fn + z];
                    float2 mv = *reinterpret_cast<const float2*>(&mixp[off]);
                    v0 = rs * (v0 + mv.x);
                    v1 = rs * (v1 + mv.y);
                }
                *reinterpret_cast<float2*>(&C[off]) = make_float2(v0, v1);
            }
        }
    }
}

// ---------------- host ----------------
#define SYMP(v, T) ({ void* _p = nullptr; cudaGetSymbolAddress(&_p, v); (T*)_p; })

extern "C" void kernel_launch(void* const* d_in, const int* in_sizes, int n_in,
                              void* d_out, int out_size) {
    const float* x          = (const float*)d_in[0];
    const float* gate_wt    = (const float*)d_in[1];
    const int*   inv        = (const int*)d_in[2];
    const float* mask_up_W  = (const float*)d_in[3];
    const float* gate_W     = (const float*)d_in[4];
    const float* gate_qa    = (const float*)d_in[5];
    const float* gate_qb    = (const float*)d_in[6];
    const float* gate_scale = (const float*)d_in[7];
    const float* up_W       = (const float*)d_in[8];
    const float* up_qa      = (const float*)d_in[9];
    const float* up_qb      = (const float*)d_in[10];
    const float* up_scale   = (const float*)d_in[11];
    const float* down_W     = (const float*)d_in[12];
    const float* down_qa    = (const float*)d_in[13];
    const float* down_qb    = (const float*)d_in[14];
    const float* down_scale = (const float*)d_in[15];
    const float* sh_gate_W  = (const float*)d_in[16];
    const float* sh_up_W    = (const float*)d_in[17];
    const float* sh_down_W  = (const float*)d_in[18];
    float* out = (float*)d_out;

    float* p_soft  = SYMP(g_soft, float);
    float* p_scal  = SYMP(g_scalar, float);
    int*   p_cnt   = SYMP(g_cnt, int);
    int*   p_tok   = SYMP(g_tok, int);
    int*   p_pos   = SYMP(g_pos, int);
    float* p_xe    = SYMP(g_xe, float);
    float* p_gu    = SYMP(g_gu, float);
    float* p_mgu   = SYMP(g_mgu, float);
    float* p_hmid  = SYMP(g_hmid, float);
    float* p_md    = SYMP(g_md, float);
    float* p_mixd  = SYMP(g_mixd, float);
    float* p_down  = SYMP(g_down, float);
    float* p_qbtgu = SYMP(g_qbtgu, float);
    float* p_qbtd  = SYMP(g_qbtd, float);
    float* p_shgu  = SYMP(g_shgu, float);
    float* p_shm   = SYMP(g_shm, float);
    float* p_sgu   = SYMP(g_sgu, float);
    float* p_xr    = SYMP(g_xr, float);

#define SETUP(M)                                                                          \
    cudaFuncSetAttribute(gemm_tn<M>, cudaFuncAttributeMaxDynamicSharedMemorySize,         \
                         SMEM_BYTES);                                                     \
    cudaFuncSetAttribute(gemm_tn<M>, cudaFuncAttributePreferredSharedMemoryCarveout, 100)
    SETUP(0); SETUP(1); SETUP(2); SETUP(3); SETUP(4);
#undef SETUP

#define NB(n) ((int)(((n) + 255) / 256))
#define GRID(N, zc) dim3(((N) + 127) / 128, Tn / 64, zc)

    // 1. router (exact fp32)
    router_kernel<<<Tn, 128>>>(x, gate_wt, inv, p_soft, p_scal);
    // 2. deterministic token compaction
    compact_kernel<<<Fn, Tn>>>(p_scal, p_cnt, p_tok, p_pos);
    // 3. xe (compacted, rounded at producer)
    xe_kernel<<<NB((size_t)Fn * Tn * Hn), 256>>>(x, mask_up_W, p_soft, p_cnt, p_tok, p_xe);

    // 4. combined gate||up GEMM (B = gate_W, B2 = up_W; raw weights, B-cvt in kernel)
    gemm_tn<0><<<GRID(IGU, Fn), 256, SMEM_BYTES>>>(
        p_xe, Hn, (size_t)Tn * Hn, gate_W, Hn, (size_t)In * Hn, up_W, In,
        p_gu, IGU, (size_t)Tn * IGU, IGU, Hn, nullptr, nullptr, nullptr, 0, nullptr,
        p_cnt, nullptr);
    // 5. combined LoRA-a GEMM (rounded output via MODE1 epilogue)
    gemm_tn<1><<<GRID(128, Fn), 256, SMEM_BYTES>>>(
        p_xe, Hn, (size_t)Tn * Hn, gate_qa, Hn, (size_t)KRn * Hn, up_qa, KRn,
        p_mgu, 128, (size_t)Tn * 128, 128, Hn, p_soft, nullptr, nullptr, 0, nullptr,
        p_cnt, p_tok);

    // 6. block-diagonal qbt concat (pre-rounded)
    tq2_kernel<<<NB(Fn * IGU * 128), 256>>>(gate_qb, up_qb, p_qbtgu);
    // 7. scale concat
    sc2<<<NB(2 * Fn * In), 256>>>(gate_scale, up_scale, p_sgu);
    // 8. combined mix GEMM, in-place
    gemm_tn<2><<<GRID(IGU, Fn), 256, SMEM_BYTES>>>(
        p_mgu, 128, (size_t)Tn * 128, p_qbtgu, 128, (size_t)IGU * 128, p_qbtgu, IGU,
        p_gu, IGU, (size_t)Tn * IGU, IGU, 128, nullptr, nullptr, p_sgu, IGU, nullptr,
        p_cnt, nullptr);
    // 9. hmid = silu(gate)*up (rounded)
    fuse_kernel<<<NB((size_t)Fn * Tn * In), 256>>>(p_gu, p_cnt, p_hmid);

    // 10. down qbt (pre-rounded)
    tq_kernel<<<NB(Fn * Hn * KRn), 256>>>(down_qb, p_qbtd, Hn);
    // 11. down LoRA a (rounded output via MODE1)
    gemm_tn<1><<<GRID(KRn, Fn), 256, SMEM_BYTES>>>(
        p_hmid, In, (size_t)Tn * In, down_qa, In, (size_t)KRn * In, down_qa, KRn,
        p_md, KRn, (size_t)Tn * KRn, KRn, In, p_soft, nullptr, nullptr, 0, nullptr,
        p_cnt, p_tok);
    // 12. mixd
    gemm_tn<3><<<GRID(Hn, Fn), 256, SMEM_BYTES>>>(
        p_md, KRn, (size_t)Tn * KRn, p_qbtd, KRn, (size_t)Hn * KRn, p_qbtd, Hn,
        p_mixd, Hn, (size_t)Tn * Hn, Hn, KRn, nullptr, nullptr, down_scale, Hn, nullptr,
        p_cnt, nullptr);
    // 13. down GEMM fused
    gemm_tn<4><<<GRID(Hn, Fn), 256, SMEM_BYTES>>>(
        p_hmid, In, (size_t)Tn * In, down_W, In, (size_t)Hn * In, down_W, Hn,
        p_down, Hn, (size_t)Tn * Hn, Hn, In, nullptr, p_scal, nullptr, 0, p_mixd,
        p_cnt, p_tok);

    // 14. rounded x for shared path
    round_copy<<<NB((size_t)Tn * Hn / 4), 256>>>(
        (const float4*)x, (float4*)p_xr, (int)((size_t)Tn * Hn / 4));
    // 15. combined shared gate||up GEMM (N=5632)
    gemm_tn<0><<<GRID(SH2, 1), 256, SMEM_BYTES>>>(
        p_xr, Hn, 0, sh_gate_W, Hn, 0, sh_up_W, ISHn,
        p_shgu, SH2, 0, SH2, Hn, nullptr, nullptr, nullptr, 0, nullptr, nullptr, nullptr);
    // 16. swiglu (rounded)
    swiglu_kernel<<<NB((size_t)Tn * ISHn), 256>>>(p_shgu, p_shm);
    // 17. shared down GEMM -> out
    gemm_tn<0><<<GRID(Hn, 1), 256, SMEM_BYTES>>>(
        p_shm, ISHn, 0, sh_down_W, ISHn, 0, sh_down_W, Hn,
        out, Hn, 0, Hn, ISHn, nullptr, nullptr, nullptr, 0, nullptr, nullptr, nullptr);

    // 18. out += gathered expert outputs
    reduce_kernel<<<NB(Tn * Hn), 256>>>(out, p_down, p_pos);

#undef NB
#undef GRID
    (void)in_sizes; (void)n_in; (void)out_size;
}

// round 11
// speedup vs baseline: 2.0781x; 1.0505x over previous
#include <cuda_runtime.h>
#include <cuda_bf16.h>
#include <math.h>
#include <cstdint>

#define Tn 1024
#define Hn 2048
#define In 1408
#define IGU 2816            // 2*In (gate||up concat)
#define En 64
#define Fn 8
#define Kn 8
#define Rn 8
#define ISHn 2816
#define SH2 5632            // 2*ISHn
#define TOPKn 6
#define KRn 64

// ---------------- scratch (device globals; allocation-free) ----------------
__device__ float g_soft[Tn * Fn * Kn];
__device__ float g_scalar[Tn * Fn];
__device__ int   g_cnt[Fn];
__device__ int   g_tok[Fn * Tn];
__device__ int   g_pos[Fn * Tn];
__device__ float g_xe[(size_t)Fn * Tn * Hn];
__device__ float g_gu[(size_t)Fn * Tn * IGU];      // gate||up outputs
__device__ float g_mgu[(size_t)Fn * Tn * 128];     // LoRA-a gate||up (rounded)
__device__ float g_hmid[(size_t)Fn * Tn * In];
__device__ float g_md[(size_t)Fn * Tn * KRn];
__device__ float g_mixd[(size_t)Fn * Tn * Hn];
__device__ float g_down[(size_t)Fn * Tn * Hn];
__device__ float g_qbtgu[(size_t)Fn * IGU * 128];  // block-diag, pre-rounded
__device__ float g_qbtd[(size_t)Fn * Hn * KRn];    // pre-rounded
__device__ float g_shgu[(size_t)Tn * SH2];
__device__ float g_shm[(size_t)Tn * ISHn];
__device__ float g_sgu[Fn * IGU];                  // gate_scale||up_scale (fp32)
__device__ float g_xr[(size_t)Tn * Hn];            // rounded x (shared path A)

// ---------------- helpers ----------------
__device__ __forceinline__ float tf32r(float x) {
    float y;
    asm("cvt.rna.tf32.f32 %0, %1;" : "=f"(y) : "f"(x));
    return y;
}
__device__ __forceinline__ uint32_t smem_u32(const void* p) {
    uint32_t a;
    asm("{ .reg .u64 t; cvta.to.shared.u64 t, %1; cvt.u32.u64 %0, t; }" : "=r"(a) : "l"(p));
    return a;
}
__device__ __forceinline__ void cpa16(uint32_t dst, const void* src, bool pred) {
    int sz = pred ? 16 : 0;
    asm volatile("cp.async.cg.shared.global [%0], [%1], 16, %2;"
                 :: "r"(dst), "l"(src), "r"(sz) : "memory");
}
#define CP_COMMIT() asm volatile("cp.async.commit_group;" ::: "memory")
#define CP_WAIT1() asm volatile("cp.async.wait_group 1;" ::: "memory")

#define MMA_TF32(d, a, b)                                                      \
    asm volatile(                                                              \
        "mma.sync.aligned.m16n8k8.row.col.f32.tf32.tf32.f32 "                  \
        "{%0,%1,%2,%3}, {%4,%5,%6,%7}, {%8,%9}, {%0,%1,%2,%3};\n"              \
        : "+f"((d)[0]), "+f"((d)[1]), "+f"((d)[2]), "+f"((d)[3])               \
        : "r"(__float_as_uint((a)[0])), "r"(__float_as_uint((a)[1])),          \
          "r"(__float_as_uint((a)[2])), "r"(__float_as_uint((a)[3])),          \
          "r"(__float_as_uint((b)[0])), "r"(__float_as_uint((b)[1])))

// ---------------- rounding copy (fp32 -> tf32 RNA), for x only ----------------
__global__ void round_copy(const float4* __restrict__ in, float4* __restrict__ out, int n4) {
    int i = blockIdx.x * blockDim.x + threadIdx.x;
    if (i >= n4) return;
    float4 v = in[i];
    v.x = tf32r(v.x); v.y = tf32r(v.y); v.z = tf32r(v.z); v.w = tf32r(v.w);
    out[i] = v;
}

// ---------------- router (exact fp32: top-k must not flip) ----------------
__global__ void router_kernel(const float* __restrict__ x,
                              const float* __restrict__ gw,
                              const int* __restrict__ inv,
                              float* __restrict__ soft,
                              float* __restrict__ scal) {
    __shared__ float xs[Hn];
    __shared__ float sc[En];
    const int t = blockIdx.x;
    const int tid = threadIdx.x;  // 128 threads
    const float4* xv = reinterpret_cast<const float4*>(x + (size_t)t * Hn);
    for (int i = tid; i < Hn / 4; i += 128)
        reinterpret_cast<float4*>(xs)[i] = xv[i];
    __syncthreads();
    const int lane = tid & 31, w = tid >> 5;
    for (int e = w; e < En; e += 4) {
        const float* g = gw + (size_t)e * Hn;
        float s = 0.f;
        for (int h = lane; h < Hn; h += 32) s += xs[h] * g[h];
#pragma unroll
        for (int o = 16; o; o >>= 1) s += __shfl_xor_sync(0xffffffffu, s, o);
        if (lane == 0) sc[e] = s;
    }
    __syncthreads();
    if (tid == 0) {
        float mx = -1e30f;
        for (int e = 0; e < En; e++) mx = fmaxf(mx, sc[e]);
        float p[En];
        float sum = 0.f;
        for (int e = 0; e < En; e++) { p[e] = expf(sc[e] - mx); sum += p[e]; }
        float is = 1.f / sum;
        for (int e = 0; e < En; e++) p[e] *= is;
        float wv[En];
        for (int e = 0; e < En; e++) wv[e] = 0.f;
        for (int j = 0; j < TOPKn; j++) {
            int best = 0;
            float bv = -1.f;
            for (int e = 0; e < En; e++) {
                if (wv[e] == 0.f && p[e] > bv) { bv = p[e]; best = e; }
            }
            wv[best] = p[best];
        }
        for (int f = 0; f < Fn; f++) {
            float fl[Kn];
            float ssum = 0.f, fmx = -1e30f;
            for (int k = 0; k < Kn; k++) {
                int e = inv[f * Kn + k];
                float v = wv[e];
                ssum += v;
                float l = (v == 0.f) ? -1e9f : v;
                fl[k] = l;
                fmx = fmaxf(fmx, l);
            }
            float es = 0.f, ex[Kn];
            for (int k = 0; k < Kn; k++) { ex[k] = expf(fl[k] - fmx); es += ex[k]; }
            float ies = 1.f / es;
            for (int k = 0; k < Kn; k++)
                soft[((size_t)t * Fn + f) * Kn + k] = ex[k] * ies;
            scal[(size_t)t * Fn + f] = ssum;
        }
    }
}

// ---------------- deterministic per-group token compaction ----------------
__global__ void compact_kernel(const float* __restrict__ scal,
                               int* __restrict__ cnt,
                               int* __restrict__ tok,
                               int* __restrict__ pos) {
    const int z = blockIdx.x;
    const int t = threadIdx.x;  // Tn threads
    __shared__ int sbuf[Tn];
    int active = (scal[(size_t)t * Fn + z] != 0.f) ? 1 : 0;
    sbuf[t] = active;
    __syncthreads();
    for (int off = 1; off < Tn; off <<= 1) {
        int v = (t >= off) ? sbuf[t - off] : 0;
        __syncthreads();
        sbuf[t] += v;
        __syncthreads();
    }
    int incl = sbuf[t];
    if (active) {
        tok[z * Tn + incl - 1] = t;
        pos[z * Tn + t] = incl - 1;
    } else {
        pos[z * Tn + t] = -1;
    }
    if (t == Tn - 1) cnt[z] = incl;
}

// ---------------- xe (compacted, tf32-rounded at write) ----------------
__global__ void xe_kernel(const float* __restrict__ x,
                          const float* __restrict__ muW,
                          const float* __restrict__ soft,
                          const int* __restrict__ cnt,
                          const int* __restrict__ tok,
                          float* __restrict__ xe) {
    size_t idx = (size_t)blockIdx.x * blockDim.x + threadIdx.x;
    if (idx >= (size_t)Fn * Tn * Hn) return;
    int z = (int)(idx / ((size_t)Tn * Hn));
    int rem = (int)(idx % ((size_t)Tn * Hn));
    int i = rem / Hn, h = rem % Hn;
    if (i >= cnt[z]) return;
    int t = tok[z * Tn + i];
    const float* mw = muW + ((size_t)z * Hn + h) * Kn;
    const float* sf = soft + ((size_t)t * Fn + z) * Kn;
    float s = x[(size_t)t * Hn + h];
#pragma unroll
    for (int k = 0; k < Kn; k++) s += sf[k] * mw[k];
    xe[idx] = tf32r(s);
}

// ---------------- qbt builders (pre-rounded; B-cvt is idempotent) ----------
__global__ void tq2_kernel(const float* __restrict__ gqb, const float* __restrict__ uqb,
                           float* __restrict__ outp) {
    int total = Fn * IGU * 128;
    int idx = blockIdx.x * blockDim.x + threadIdx.x;
    if (idx >= total) return;
    int z = idx / (IGU * 128);
    int rem = idx % (IGU * 128);
    int n = rem >> 7, kr = rem & 127;
    float v = 0.f;
    if (n < In) {
        if (kr < 64) {
            int k = kr >> 3, r = kr & 7;
            v = tf32r(gqb[(((size_t)z * Kn + k) * In + n) * Rn + r]);
        }
    } else {
        if (kr >= 64) {
            int k = (kr - 64) >> 3, r = kr & 7;
            v = tf32r(uqb[(((size_t)z * Kn + k) * In + (n - In)) * Rn + r]);
        }
    }
    outp[idx] = v;
}
__global__ void tq_kernel(const float* __restrict__ qb, float* __restrict__ outp, int Nd) {
    int total = Fn * Nd * KRn;
    int idx = blockIdx.x * blockDim.x + threadIdx.x;
    if (idx >= total) return;
    int z = idx / (Nd * KRn);
    int rem = idx % (Nd * KRn);
    int n = rem >> 6, kr = rem & 63;
    int k = kr >> 3, r = kr & 7;
    outp[idx] = tf32r(qb[(((size_t)z * Kn + k) * Nd + n) * Rn + r]);
}

// ---------------- scale concat (fp32) ----------------
__global__ void sc2(const float* __restrict__ gs, const float* __restrict__ us,
                    float* __restrict__ sgu) {
    int i = blockIdx.x * blockDim.x + threadIdx.x;
    if (i >= 2 * Fn * In) return;
    int seg = i >= Fn * In;
    int j = i - seg * Fn * In;
    int z = j / In, r = j % In;
    sgu[z * IGU + seg * In + r] = (seg ? us : gs)[j];
}

// ---------------- hmid = silu(gate)*up (rounded) ----------------
__global__ void fuse_kernel(const float* __restrict__ gu,
                            const int* __restrict__ cnt,
                            float* __restrict__ hm) {
    size_t idx = (size_t)blockIdx.x * blockDim.x + threadIdx.x;
    if (idx >= (size_t)Fn * Tn * In) return;
    int z = (int)(idx / ((size_t)Tn * In));
    int rem = (int)(idx % ((size_t)Tn * In));
    int i = rem / In, c = rem % In;
    if (i >= cnt[z]) return;
    size_t base = ((size_t)z * Tn + i) * IGU;
    float g = gu[base + c], u = gu[base + In + c];
    hm[idx] = tf32r(g / (1.f + expf(-g)) * u);
}

__global__ void swiglu_kernel(const float* __restrict__ sgu, float* __restrict__ hm) {
    size_t idx = (size_t)blockIdx.x * blockDim.x + threadIdx.x;
    if (idx >= (size_t)Tn * ISHn) return;
    int t = (int)(idx / ISHn), c = (int)(idx % ISHn);
    size_t base = (size_t)t * SH2;
    float g = sgu[base + c], u = sgu[base + ISHn + c];
    hm[idx] = tf32r(g / (1.f + expf(-g)) * u);
}

// ---------------- out[t] += sum_z active: down[z][pos[z,t]] ----------------
__global__ void reduce_kernel(float* __restrict__ out, const float* __restrict__ down,
                              const int* __restrict__ pos) {
    int idx = blockIdx.x * blockDim.x + threadIdx.x;
    if (idx >= Tn * Hn) return;
    int t = idx / Hn, h = idx % Hn;
    float s = out[idx];
#pragma unroll
    for (int z = 0; z < Fn; z++) {
        int p = pos[z * Tn + t];
        if (p >= 0) s += down[((size_t)z * Tn + p) * Hn + h];
    }
    out[idx] = s;
}

// ---------------- cp.async tf32 GEMM, tile 128x128 ----------------
// C[MxN] = A[MxK] * rna(Bcat)[NxK]^T. A must be pre-rounded to tf32 (producers
// round); B fragments rounded in-register (B reads harness weights directly).
// Bcat = B rows [0,nsplit) || B2 rows.
// MODE 0: C=acc
// MODE 1: C=tf32r(acc*soft[tok[r], z, (n&63)>>3])
// MODE 2: C=C + colscale[n]*acc
// MODE 3: C=colscale[n]*acc
// MODE 4: C=rowscal[tok[r]*Fn+z]*(acc + mixadd[z,r,n])
#define KC 32
#define SM_LD 36
#define SM_BUF (128 * SM_LD)
#define STAGE_FLOATS (2 * SM_BUF)
#define SMEM_BYTES (3 * STAGE_FLOATS * 4)

template <int MODE>
__global__ void __launch_bounds__(256, 2)
gemm_tn(const float* __restrict__ A, int lda, size_t sA,
        const float* __restrict__ B, int ldb, size_t sB,
        const float* __restrict__ B2, int nsplit,
        float* __restrict__ C, int ldc, size_t sC,
        int N, int Ktot,
        const float* __restrict__ soft,
        const float* __restrict__ rowscal,
        const float* __restrict__ colscale, size_t sCs,
        const float* __restrict__ mixadd,
        const int* __restrict__ cntp,
        const int* __restrict__ tokp) {
    const int z = blockIdx.z;
    const int Mz = cntp ? cntp[z] : Tn;
    const int bm = blockIdx.y * 128, bn = blockIdx.x * 128;
    if (bm >= Mz) return;
    A += (size_t)z * sA;
    B += (size_t)z * sB;
    B2 += (size_t)z * sB;
    C += (size_t)z * sC;
    const float* cs = (MODE == 2 || MODE == 3) ? colscale + (size_t)z * sCs : nullptr;
    const float* mixp = (MODE == 4) ? mixadd + (size_t)z * sC : nullptr;
    const int* tk = (MODE == 1 || MODE == 4) ? tokp + z * Tn : nullptr;

    extern __shared__ float smf[];
    const uint32_t sbase = smem_u32(smf);
    const int tid = threadIdx.x, lane = tid & 31, wid = tid >> 5;
    const int wm = (wid >> 2) * 64, wn = (wid & 3) * 32;

    int arow[4], kq4[4];
#pragma unroll
    for (int i = 0; i < 4; i++) {
        int lin = tid + i * 256;
        arow[i] = lin >> 3;
        kq4[i] = (lin & 7) << 2;
    }
    float acc[4][4][4];
#pragma unroll
    for (int a = 0; a < 4; a++)
#pragma unroll
        for (int b = 0; b < 4; b++)
#pragma unroll
            for (int c = 0; c < 4; c++) acc[a][b][c] = 0.f;

    auto issue = [&](int kt, int s) {
        const int k0 = kt * KC;
#pragma unroll
        for (int i = 0; i < 4; i++) {
            uint32_t da = sbase + (uint32_t)((s * STAGE_FLOATS + arow[i] * SM_LD + kq4[i]) * 4);
            cpa16(da, A + (size_t)(bm + arow[i]) * lda + k0 + kq4[i], bm + arow[i] < Mz);
            uint32_t db = da + (uint32_t)(SM_BUF * 4);
            int n = bn + arow[i];
            const float* bs = (n < nsplit) ? B + (size_t)n * ldb
                                           : B2 + (size_t)(n - nsplit) * ldb;
            cpa16(db, bs + k0 + kq4[i], n < N);
        }
    };

    const int KT = Ktot / KC;
    issue(0, 0);
    CP_COMMIT();
    if (KT > 1) issue(1, 1);
    CP_COMMIT();

    for (int kt = 0; kt < KT; kt++) {
        CP_WAIT1();
        __syncthreads();
        if (kt + 2 < KT) issue(kt + 2, (kt + 2) % 3);
        CP_COMMIT();
        const float* Ab = smf + (kt % 3) * STAGE_FLOATS;
        const float* Bb = Ab + SM_BUF;
#pragma unroll
        for (int ks = 0; ks < 4; ks++) {
            int kk = ks * 8 + (lane & 3);
            float a[4][4], b[4][2];
#pragma unroll
            for (int mi = 0; mi < 4; mi++) {
                const float* p = Ab + (wm + mi * 16 + (lane >> 2)) * SM_LD + kk;
                a[mi][0] = p[0];
                a[mi][1] = p[8 * SM_LD];
                a[mi][2] = p[4];
                a[mi][3] = p[8 * SM_LD + 4];
            }
#pragma unroll
            for (int ni = 0; ni < 4; ni++) {
                const float* q = Bb + (wn + ni * 8 + (lane >> 2)) * SM_LD + kk;
                b[ni][0] = tf32r(q[0]);
                b[ni][1] = tf32r(q[4]);
            }
#pragma unroll
            for (int mi = 0; mi < 4; mi++)
#pragma unroll
                for (int ni = 0; ni < 4; ni++) MMA_TF32(acc[mi][ni], a[mi], b[ni]);
        }
    }

    // epilogue
#pragma unroll
    for (int mi = 0; mi < 4; mi++) {
#pragma unroll
        for (int ni = 0; ni < 4; ni++) {
            int cb = bn + wn + ni * 8;
            if (cb >= N) continue;
            int c = cb + ((lane & 3) << 1);
#pragma unroll
            for (int hh = 0; hh < 2; hh++) {
                int r = bm + wm + mi * 16 + (lane >> 2) + hh * 8;
                if (r >= Mz) continue;
                float v0 = acc[mi][ni][hh * 2 + 0];
                float v1 = acc[mi][ni][hh * 2 + 1];
                size_t off = (size_t)r * ldc + c;
                if (MODE == 1) {
                    float s = soft[((size_t)tk[r] * Fn + z) * Kn + ((c & 63) >> 3)];
                    v0 = tf32r(v0 * s);
                    v1 = tf32r(v1 * s);
                } else if (MODE == 2) {
                    float2 prev = *reinterpret_cast<const float2*>(&C[off]);
                    v0 = prev.x + cs[c] * v0;
                    v1 = prev.y + cs[c + 1] * v1;
                } else if (MODE == 3) {
                    v0 *= cs[c];
                    v1 *= cs[c + 1];
                } else if (MODE == 4) {
                    float rs = rowscal[(size_t)tk[r] * Fn + z];
                    float2 mv = *reinterpret_cast<const float2*>(&mixp[off]);
                    v0 = rs * (v0 + mv.x);
                    v1 = rs * (v1 + mv.y);
                }
                *reinterpret_cast<float2*>(&C[off]) = make_float2(v0, v1);
            }
        }
    }
}

// ---------------- host ----------------
#define SYMP(v, T) ({ void* _p = nullptr; cudaGetSymbolAddress(&_p, v); (T*)_p; })

extern "C" void kernel_launch(void* const* d_in, const int* in_sizes, int n_in,
                              void* d_out, int out_size) {
    const float* x          = (const float*)d_in[0];
    const float* gate_wt    = (const float*)d_in[1];
    const int*   inv        = (const int*)d_in[2];
    const float* mask_up_W  = (const float*)d_in[3];
    const float* gate_W     = (const float*)d_in[4];
    const float* gate_qa    = (const float*)d_in[5];
    const float* gate_qb    = (const float*)d_in[6];
    const float* gate_scale = (const float*)d_in[7];
    const float* up_W       = (const float*)d_in[8];
    const float* up_qa      = (const float*)d_in[9];
    const float* up_qb      = (const float*)d_in[10];
    const float* up_scale   = (const float*)d_in[11];
    const float* down_W     = (const float*)d_in[12];
    const float* down_qa    = (const float*)d_in[13];
    const float* down_qb    = (const float*)d_in[14];
    const float* down_scale = (const float*)d_in[15];
    const float* sh_gate_W  = (const float*)d_in[16];
    const float* sh_up_W    = (const float*)d_in[17];
    const float* sh_down_W  = (const float*)d_in[18];
    float* out = (float*)d_out;

    float* p_soft  = SYMP(g_soft, float);
    float* p_scal  = SYMP(g_scalar, float);
    int*   p_cnt   = SYMP(g_cnt, int);
    int*   p_tok   = SYMP(g_tok, int);
    int*   p_pos   = SYMP(g_pos, int);
    float* p_xe    = SYMP(g_xe, float);
    float* p_gu    = SYMP(g_gu, float);
    float* p_mgu   = SYMP(g_mgu, float);
    float* p_hmid  = SYMP(g_hmid, float);
    float* p_md    = SYMP(g_md, float);
    float* p_mixd  = SYMP(g_mixd, float);
    float* p_down  = SYMP(g_down, float);
    float* p_qbtgu = SYMP(g_qbtgu, float);
    float* p_qbtd  = SYMP(g_qbtd, float);
    float* p_shgu  = SYMP(g_shgu, float);
    float* p_shm   = SYMP(g_shm, float);
    float* p_sgu   = SYMP(g_sgu, float);
    float* p_xr    = SYMP(g_xr, float);

#define SETUP(M)                                                                          \
    cudaFuncSetAttribute(gemm_tn<M>, cudaFuncAttributeMaxDynamicSharedMemorySize,         \
                         SMEM_BYTES);                                                     \
    cudaFuncSetAttribute(gemm_tn<M>, cudaFuncAttributePreferredSharedMemoryCarveout, 100)
    SETUP(0); SETUP(1); SETUP(2); SETUP(3); SETUP(4);
#undef SETUP

#define NB(n) ((int)(((n) + 255) / 256))
#define GRID(N, zc) dim3(((N) + 127) / 128, Tn / 128, zc)

    // 1. router (exact fp32)
    router_kernel<<<Tn, 128>>>(x, gate_wt, inv, p_soft, p_scal);
    // 2. deterministic token compaction
    compact_kernel<<<Fn, Tn>>>(p_scal, p_cnt, p_tok, p_pos);
    // 3. xe (compacted, rounded at producer)
    xe_kernel<<<NB((size_t)Fn * Tn * Hn), 256>>>(x, mask_up_W, p_soft, p_cnt, p_tok, p_xe);

    // 4. combined gate||up GEMM (B = gate_W, B2 = up_W; raw weights, B-cvt in kernel)
    gemm_tn<0><<<GRID(IGU, Fn), 256, SMEM_BYTES>>>(
        p_xe, Hn, (size_t)Tn * Hn, gate_W, Hn, (size_t)In * Hn, up_W, In,
        p_gu, IGU, (size_t)Tn * IGU, IGU, Hn, nullptr, nullptr, nullptr, 0, nullptr,
        p_cnt, nullptr);
    // 5. combined LoRA-a GEMM (rounded output via MODE1 epilogue)
    gemm_tn<1><<<GRID(128, Fn), 256, SMEM_BYTES>>>(
        p_xe, Hn, (size_t)Tn * Hn, gate_qa, Hn, (size_t)KRn * Hn, up_qa, KRn,
        p_mgu, 128, (size_t)Tn * 128, 128, Hn, p_soft, nullptr, nullptr, 0, nullptr,
        p_cnt, p_tok);

    // 6. block-diagonal qbt concat (pre-rounded)
    tq2_kernel<<<NB(Fn * IGU * 128), 256>>>(gate_qb, up_qb, p_qbtgu);
    // 7. scale concat
    sc2<<<NB(2 * Fn * In), 256>>>(gate_scale, up_scale, p_sgu);
    // 8. combined mix GEMM, in-place
    gemm_tn<2><<<GRID(IGU, Fn), 256, SMEM_BYTES>>>(
        p_mgu, 128, (size_t)Tn * 128, p_qbtgu, 128, (size_t)IGU * 128, p_qbtgu, IGU,
        p_gu, IGU, (size_t)Tn * IGU, IGU, 128, nullptr, nullptr, p_sgu, IGU, nullptr,
        p_cnt, nullptr);
    // 9. hmid = silu(gate)*up (rounded)
    fuse_kernel<<<NB((size_t)Fn * Tn * In), 256>>>(p_gu, p_cnt, p_hmid);

    // 10. down qbt (pre-rounded)
    tq_kernel<<<NB(Fn * Hn * KRn), 256>>>(down_qb, p_qbtd, Hn);
    // 11. down LoRA a (rounded output via MODE1)
    gemm_tn<1><<<GRID(KRn, Fn), 256, SMEM_BYTES>>>(
        p_hmid, In, (size_t)Tn * In, down_qa, In, (size_t)KRn * In, down_qa, KRn,
        p_md, KRn, (size_t)Tn * KRn, KRn, In, p_soft, nullptr, nullptr, 0, nullptr,
        p_cnt, p_tok);
    // 12. mixd
    gemm_tn<3><<<GRID(Hn, Fn), 256, SMEM_BYTES>>>(
        p_md, KRn, (size_t)Tn * KRn, p_qbtd, KRn, (size_t)Hn * KRn, p_qbtd, Hn,
        p_mixd, Hn, (size_t)Tn * Hn, Hn, KRn, nullptr, nullptr, down_scale, Hn, nullptr,
        p_cnt, nullptr);
    // 13. down GEMM fused
    gemm_tn<4><<<GRID(Hn, Fn), 256, SMEM_BYTES>>>(
        p_hmid, In, (size_t)Tn * In, down_W, In, (size_t)Hn * In, down_W, Hn,
        p_down, Hn, (size_t)Tn * Hn, Hn, In, nullptr, p_scal, nullptr, 0, p_mixd,
        p_cnt, p_tok);

    // 14. rounded x for shared path
    round_copy<<<NB((size_t)Tn * Hn / 4), 256>>>(
        (const float4*)x, (float4*)p_xr, (int)((size_t)Tn * Hn / 4));
    // 15. combined shared gate||up GEMM (N=5632)
    gemm_tn<0><<<GRID(SH2, 1), 256, SMEM_BYTES>>>(
        p_xr, Hn, 0, sh_gate_W, Hn, 0, sh_up_W, ISHn,
        p_shgu, SH2, 0, SH2, Hn, nullptr, nullptr, nullptr, 0, nullptr, nullptr, nullptr);
    // 16. swiglu (rounded)
    swiglu_kernel<<<NB((size_t)Tn * ISHn), 256>>>(p_shgu, p_shm);
    // 17. shared down GEMM -> out
    gemm_tn<0><<<GRID(Hn, 1), 256, SMEM_BYTES>>>(
        p_shm, ISHn, 0, sh_down_W, ISHn, 0, sh_down_W, Hn,
        out, Hn, 0, Hn, ISHn, nullptr, nullptr, nullptr, 0, nullptr, nullptr, nullptr);

    // 18. out += gathered expert outputs
    reduce_kernel<<<NB(Tn * Hn), 256>>>(out, p_down, p_pos);

#undef NB
#undef GRID
    (void)in_sizes; (void)n_in; (void)out_size;
}

// round 12
// speedup vs baseline: 2.3167x; 1.1148x over previous
#include <cuda_runtime.h>
#include <cuda_bf16.h>
#include <math.h>
#include <cstdint>

#define Tn 1024
#define Hn 2048
#define In 1408
#define IGU 2816            // 2*In (gate||up concat)
#define En 64
#define Fn 8
#define Kn 8
#define Rn 8
#define ISHn 2816
#define SH2 5632            // 2*ISHn
#define TOPKn 6
#define KRn 64

// ---------------- scratch (device globals; allocation-free) ----------------
__device__ float g_soft[Tn * Fn * Kn];
__device__ float g_scalar[Tn * Fn];
__device__ int   g_cnt[Fn];
__device__ int   g_tok[Fn * Tn];
__device__ int   g_pos[Fn * Tn];
__device__ float g_xe[(size_t)Fn * Tn * Hn];
__device__ float g_gu[(size_t)Fn * Tn * IGU];      // gate||up outputs
__device__ float g_mgu[(size_t)Fn * Tn * 128];     // LoRA-a gate||up (rounded)
__device__ float g_hmid[(size_t)Fn * Tn * In];
__device__ float g_md[(size_t)Fn * Tn * KRn];
__device__ float g_mixd[(size_t)Fn * Tn * Hn];
__device__ float g_down[(size_t)Fn * Tn * Hn];
__device__ float g_qbtgu[(size_t)Fn * IGU * 128];  // block-diag, pre-rounded
__device__ float g_qbtd[(size_t)Fn * Hn * KRn];    // pre-rounded
__device__ float g_shgu[(size_t)Tn * SH2];
__device__ float g_shm[(size_t)Tn * ISHn];
__device__ float g_sgu[Fn * IGU];                  // gate_scale||up_scale (fp32)
__device__ float g_xr[(size_t)Tn * Hn];            // rounded x (shared path A)

// ---------------- helpers ----------------
__device__ __forceinline__ float tf32r(float x) {
    float y;
    asm("cvt.rna.tf32.f32 %0, %1;" : "=f"(y) : "f"(x));
    return y;
}
__device__ __forceinline__ uint32_t smem_u32(const void* p) {
    uint32_t a;
    asm("{ .reg .u64 t; cvta.to.shared.u64 t, %1; cvt.u32.u64 %0, t; }" : "=r"(a) : "l"(p));
    return a;
}
__device__ __forceinline__ void cpa16(uint32_t dst, const void* src, bool pred) {
    int sz = pred ? 16 : 0;
    asm volatile("cp.async.cg.shared.global [%0], [%1], 16, %2;"
                 :: "r"(dst), "l"(src), "r"(sz) : "memory");
}
#define CP_COMMIT() asm volatile("cp.async.commit_group;" ::: "memory")
#define CP_WAIT1() asm volatile("cp.async.wait_group 1;" ::: "memory")

#define MMA_TF32(d, a, b)                                                      \
    asm volatile(                                                              \
        "mma.sync.aligned.m16n8k8.row.col.f32.tf32.tf32.f32 "                  \
        "{%0,%1,%2,%3}, {%4,%5,%6,%7}, {%8,%9}, {%0,%1,%2,%3};\n"              \
        : "+f"((d)[0]), "+f"((d)[1]), "+f"((d)[2]), "+f"((d)[3])               \
        : "r"(__float_as_uint((a)[0])), "r"(__float_as_uint((a)[1])),          \
          "r"(__float_as_uint((a)[2])), "r"(__float_as_uint((a)[3])),          \
          "r"(__float_as_uint((b)[0])), "r"(__float_as_uint((b)[1])))

// ---------------- rounding copy (fp32 -> tf32 RNA), for x only ----------------
__global__ void round_copy(const float4* __restrict__ in, float4* __restrict__ out, int n4) {
    int i = blockIdx.x * blockDim.x + threadIdx.x;
    if (i >= n4) return;
    float4 v = in[i];
    v.x = tf32r(v.x); v.y = tf32r(v.y); v.z = tf32r(v.z); v.w = tf32r(v.w);
    out[i] = v;
}

// ---------------- router (exact fp32: top-k must not flip) ----------------
__global__ void router_kernel(const float* __restrict__ x,
                              const float* __restrict__ gw,
                              const int* __restrict__ inv,
                              float* __restrict__ soft,
                              float* __restrict__ scal) {
    __shared__ float xs[Hn];
    __shared__ float sc[En];
    const int t = blockIdx.x;
    const int tid = threadIdx.x;  // 128 threads
    const float4* xv = reinterpret_cast<const float4*>(x + (size_t)t * Hn);
    for (int i = tid; i < Hn / 4; i += 128)
        reinterpret_cast<float4*>(xs)[i] = xv[i];
    __syncthreads();
    const int lane = tid & 31, w = tid >> 5;
    for (int e = w; e < En; e += 4) {
        const float* g = gw + (size_t)e * Hn;
        float s = 0.f;
        for (int h = lane; h < Hn; h += 32) s += xs[h] * g[h];
#pragma unroll
        for (int o = 16; o; o >>= 1) s += __shfl_xor_sync(0xffffffffu, s, o);
        if (lane == 0) sc[e] = s;
    }
    __syncthreads();
    if (tid == 0) {
        float mx = -1e30f;
        for (int e = 0; e < En; e++) mx = fmaxf(mx, sc[e]);
        float p[En];
        float sum = 0.f;
        for (int e = 0; e < En; e++) { p[e] = expf(sc[e] - mx); sum += p[e]; }
        float is = 1.f / sum;
        for (int e = 0; e < En; e++) p[e] *= is;
        float wv[En];
        for (int e = 0; e < En; e++) wv[e] = 0.f;
        for (int j = 0; j < TOPKn; j++) {
            int best = 0;
            float bv = -1.f;
            for (int e = 0; e < En; e++) {
                if (wv[e] == 0.f && p[e] > bv) { bv = p[e]; best = e; }
            }
            wv[best] = p[best];
        }
        for (int f = 0; f < Fn; f++) {
            float fl[Kn];
            float ssum = 0.f, fmx = -1e30f;
            for (int k = 0; k < Kn; k++) {
                int e = inv[f * Kn + k];
                float v = wv[e];
                ssum += v;
                float l = (v == 0.f) ? -1e9f : v;
                fl[k] = l;
                fmx = fmaxf(fmx, l);
            }
            float es = 0.f, ex[Kn];
            for (int k = 0; k < Kn; k++) { ex[k] = expf(fl[k] - fmx); es += ex[k]; }
            float ies = 1.f / es;
            for (int k = 0; k < Kn; k++)
                soft[((size_t)t * Fn + f) * Kn + k] = ex[k] * ies;
            scal[(size_t)t * Fn + f] = ssum;
        }
    }
}

// ---------------- deterministic per-group token compaction ----------------
__global__ void compact_kernel(const float* __restrict__ scal,
                               int* __restrict__ cnt,
                               int* __restrict__ tok,
                               int* __restrict__ pos) {
    const int z = blockIdx.x;
    const int t = threadIdx.x;  // Tn threads
    __shared__ int sbuf[Tn];
    int active = (scal[(size_t)t * Fn + z] != 0.f) ? 1 : 0;
    sbuf[t] = active;
    __syncthreads();
    for (int off = 1; off < Tn; off <<= 1) {
        int v = (t >= off) ? sbuf[t - off] : 0;
        __syncthreads();
        sbuf[t] += v;
        __syncthreads();
    }
    int incl = sbuf[t];
    if (active) {
        tok[z * Tn + incl - 1] = t;
        pos[z * Tn + t] = incl - 1;
    } else {
        pos[z * Tn + t] = -1;
    }
    if (t == Tn - 1) cnt[z] = incl;
}

// ---------------- xe (compacted, tf32-rounded at write) ----------------
__global__ void xe_kernel(const float* __restrict__ x,
                          const float* __restrict__ muW,
                          const float* __restrict__ soft,
                          const int* __restrict__ cnt,
                          const int* __restrict__ tok,
                          float* __restrict__ xe) {
    size_t idx = (size_t)blockIdx.x * blockDim.x + threadIdx.x;
    if (idx >= (size_t)Fn * Tn * Hn) return;
    int z = (int)(idx / ((size_t)Tn * Hn));
    int rem = (int)(idx % ((size_t)Tn * Hn));
    int i = rem / Hn, h = rem % Hn;
    if (i >= cnt[z]) return;
    int t = tok[z * Tn + i];
    const float* mw = muW + ((size_t)z * Hn + h) * Kn;
    const float* sf = soft + ((size_t)t * Fn + z) * Kn;
    float s = x[(size_t)t * Hn + h];
#pragma unroll
    for (int k = 0; k < Kn; k++) s += sf[k] * mw[k];
    xe[idx] = tf32r(s);
}

// ---------------- qbt builders (pre-rounded; B-cvt is idempotent) ----------
__global__ void tq2_kernel(const float* __restrict__ gqb, const float* __restrict__ uqb,
                           float* __restrict__ outp) {
    int total = Fn * IGU * 128;
    int idx = blockIdx.x * blockDim.x + threadIdx.x;
    if (idx >= total) return;
    int z = idx / (IGU * 128);
    int rem = idx % (IGU * 128);
    int n = rem >> 7, kr = rem & 127;
    float v = 0.f;
    if (n < In) {
        if (kr < 64) {
            int k = kr >> 3, r = kr & 7;
            v = tf32r(gqb[(((size_t)z * Kn + k) * In + n) * Rn + r]);
        }
    } else {
        if (kr >= 64) {
            int k = (kr - 64) >> 3, r = kr & 7;
            v = tf32r(uqb[(((size_t)z * Kn + k) * In + (n - In)) * Rn + r]);
        }
    }
    outp[idx] = v;
}
__global__ void tq_kernel(const float* __restrict__ qb, float* __restrict__ outp, int Nd) {
    int total = Fn * Nd * KRn;
    int idx = blockIdx.x * blockDim.x + threadIdx.x;
    if (idx >= total) return;
    int z = idx / (Nd * KRn);
    int rem = idx % (Nd * KRn);
    int n = rem >> 6, kr = rem & 63;
    int k = kr >> 3, r = kr & 7;
    outp[idx] = tf32r(qb[(((size_t)z * Kn + k) * Nd + n) * Rn + r]);
}

// ---------------- scale concat (fp32) ----------------
__global__ void sc2(const float* __restrict__ gs, const float* __restrict__ us,
                    float* __restrict__ sgu) {
    int i = blockIdx.x * blockDim.x + threadIdx.x;
    if (i >= 2 * Fn * In) return;
    int seg = i >= Fn * In;
    int j = i - seg * Fn * In;
    int z = j / In, r = j % In;
    sgu[z * IGU + seg * In + r] = (seg ? us : gs)[j];
}

// ---------------- hmid = silu(gate)*up (rounded) ----------------
__global__ void fuse_kernel(const float* __restrict__ gu,
                            const int* __restrict__ cnt,
                            float* __restrict__ hm) {
    size_t idx = (size_t)blockIdx.x * blockDim.x + threadIdx.x;
    if (idx >= (size_t)Fn * Tn * In) return;
    int z = (int)(idx / ((size_t)Tn * In));
    int rem = (int)(idx % ((size_t)Tn * In));
    int i = rem / In, c = rem % In;
    if (i >= cnt[z]) return;
    size_t base = ((size_t)z * Tn + i) * IGU;
    float g = gu[base + c], u = gu[base + In + c];
    hm[idx] = tf32r(g / (1.f + expf(-g)) * u);
}

__global__ void swiglu_kernel(const float* __restrict__ sgu, float* __restrict__ hm) {
    size_t idx = (size_t)blockIdx.x * blockDim.x + threadIdx.x;
    if (idx >= (size_t)Tn * ISHn) return;
    int t = (int)(idx / ISHn), c = (int)(idx % ISHn);
    size_t base = (size_t)t * SH2;
    float g = sgu[base + c], u = sgu[base + ISHn + c];
    hm[idx] = tf32r(g / (1.f + expf(-g)) * u);
}

// ---------------- out[t] += sum_z active: down[z][pos[z,t]] ----------------
__global__ void reduce_kernel(float* __restrict__ out, const float* __restrict__ down,
                              const int* __restrict__ pos) {
    int idx = blockIdx.x * blockDim.x + threadIdx.x;
    if (idx >= Tn * Hn) return;
    int t = idx / Hn, h = idx % Hn;
    float s = out[idx];
#pragma unroll
    for (int z = 0; z < Fn; z++) {
        int p = pos[z * Tn + t];
        if (p >= 0) s += down[((size_t)z * Tn + p) * Hn + h];
    }
    out[idx] = s;
}

// ---------------- cp.async tf32 GEMM body, tile 128x128 ----------------
// C[MxN] = A[MxK] * rna(Bcat)[NxK]^T. A pre-rounded by producers; B fragments
// rounded in-register. Bcat = B rows [0,nsplit) || B2 rows.
// MODE 0: C=acc
// MODE 1: C=tf32r(acc*soft[tok[r], z, (n&63)>>3])
// MODE 2: C=C + colscale[n]*acc
// MODE 3: C=colscale[n]*acc
// MODE 4: C=rowscal[tok[r]*Fn+z]*(acc + mixadd[z,r,n])
#define KC 32
#define SM_LD 36
#define SM_BUF (128 * SM_LD)
#define STAGE_FLOATS (2 * SM_BUF)
#define SMEM_BYTES (3 * STAGE_FLOATS * 4)

struct GArgs {
    const float* A; int lda; size_t sA;
    const float* B; int ldb; size_t sB;
    const float* B2; int nsplit;
    float* C; int ldc; size_t sC;
    int N, Ktot;
    const float* soft;
    const float* rowscal;
    const float* colscale; size_t sCs;
    const float* mixadd;
    const int* cntp;
    const int* tokp;
};

template <int MODE>
__device__ void gemm_body(const GArgs& g, int bxi, int byi, int z) {
    const int Mz = g.cntp ? g.cntp[z] : Tn;
    const int bm = byi * 128, bn = bxi * 128;
    if (bm >= Mz) return;
    const float* A = g.A + (size_t)z * g.sA;
    const float* B = g.B + (size_t)z * g.sB;
    const float* B2 = g.B2 + (size_t)z * g.sB;
    float* C = g.C + (size_t)z * g.sC;
    const int lda = g.lda, ldb = g.ldb, ldc = g.ldc, N = g.N, nsplit = g.nsplit;
    const float* cs = (MODE == 2 || MODE == 3) ? g.colscale + (size_t)z * g.sCs : nullptr;
    const float* mixp = (MODE == 4) ? g.mixadd + (size_t)z * g.sC : nullptr;
    const int* tk = (MODE == 1 || MODE == 4) ? g.tokp + z * Tn : nullptr;

    extern __shared__ float smf[];
    const uint32_t sbase = smem_u32(smf);
    const int tid = threadIdx.x, lane = tid & 31, wid = tid >> 5;
    const int wm = (wid >> 2) * 64, wn = (wid & 3) * 32;

    int arow[4], kq4[4];
#pragma unroll
    for (int i = 0; i < 4; i++) {
        int lin = tid + i * 256;
        arow[i] = lin >> 3;
        kq4[i] = (lin & 7) << 2;
    }
    float acc[4][4][4];
#pragma unroll
    for (int a = 0; a < 4; a++)
#pragma unroll
        for (int b = 0; b < 4; b++)
#pragma unroll
            for (int c = 0; c < 4; c++) acc[a][b][c] = 0.f;

    auto issue = [&](int kt, int s) {
        const int k0 = kt * KC;
#pragma unroll
        for (int i = 0; i < 4; i++) {
            uint32_t da = sbase + (uint32_t)((s * STAGE_FLOATS + arow[i] * SM_LD + kq4[i]) * 4);
            cpa16(da, A + (size_t)(bm + arow[i]) * lda + k0 + kq4[i], bm + arow[i] < Mz);
            uint32_t db = da + (uint32_t)(SM_BUF * 4);
            int n = bn + arow[i];
            const float* bs = (n < nsplit) ? B + (size_t)n * ldb
                                           : B2 + (size_t)(n - nsplit) * ldb;
            cpa16(db, bs + k0 + kq4[i], n < N);
        }
    };

    const int KT = g.Ktot / KC;
    issue(0, 0);
    CP_COMMIT();
    if (KT > 1) issue(1, 1);
    CP_COMMIT();

    for (int kt = 0; kt < KT; kt++) {
        CP_WAIT1();
        __syncthreads();
        if (kt + 2 < KT) issue(kt + 2, (kt + 2) % 3);
        CP_COMMIT();
        const float* Ab = smf + (kt % 3) * STAGE_FLOATS;
        const float* Bb = Ab + SM_BUF;
#pragma unroll
        for (int ks = 0; ks < 4; ks++) {
            int kk = ks * 8 + (lane & 3);
            float a[4][4], b[4][2];
#pragma unroll
            for (int mi = 0; mi < 4; mi++) {
                const float* p = Ab + (wm + mi * 16 + (lane >> 2)) * SM_LD + kk;
                a[mi][0] = p[0];
                a[mi][1] = p[8 * SM_LD];
                a[mi][2] = p[4];
                a[mi][3] = p[8 * SM_LD + 4];
            }
#pragma unroll
            for (int ni = 0; ni < 4; ni++) {
                const float* q = Bb + (wn + ni * 8 + (lane >> 2)) * SM_LD + kk;
                b[ni][0] = tf32r(q[0]);
                b[ni][1] = tf32r(q[4]);
            }
#pragma unroll
            for (int mi = 0; mi < 4; mi++)
#pragma unroll
                for (int ni = 0; ni < 4; ni++) MMA_TF32(acc[mi][ni], a[mi], b[ni]);
        }
    }

    // epilogue
#pragma unroll
    for (int mi = 0; mi < 4; mi++) {
#pragma unroll
        for (int ni = 0; ni < 4; ni++) {
            int cb = bn + wn + ni * 8;
            if (cb >= N) continue;
            int c = cb + ((lane & 3) << 1);
#pragma unroll
            for (int hh = 0; hh < 2; hh++) {
                int r = bm + wm + mi * 16 + (lane >> 2) + hh * 8;
                if (r >= Mz) continue;
                float v0 = acc[mi][ni][hh * 2 + 0];
                float v1 = acc[mi][ni][hh * 2 + 1];
                size_t off = (size_t)r * ldc + c;
                if (MODE == 1) {
                    float s = g.soft[((size_t)tk[r] * Fn + z) * Kn + ((c & 63) >> 3)];
                    v0 = tf32r(v0 * s);
                    v1 = tf32r(v1 * s);
                } else if (MODE == 2) {
                    float2 prev = *reinterpret_cast<const float2*>(&C[off]);
                    v0 = prev.x + cs[c] * v0;
                    v1 = prev.y + cs[c + 1] * v1;
                } else if (MODE == 3) {
                    v0 *= cs[c];
                    v1 *= cs[c + 1];
                } else if (MODE == 4) {
                    float rs = g.rowscal[(size_t)tk[r] * Fn + z];
                    float2 mv = *reinterpret_cast<const float2*>(&mixp[off]);
                    v0 = rs * (v0 + mv.x);
                    v1 = rs * (v1 + mv.y);
                }
                *reinterpret_cast<float2*>(&C[off]) = make_float2(v0, v1);
            }
        }
    }
}

// single-GEMM kernel (3D grid as before)
template <int MODE>
__global__ void __launch_bounds__(256, 2)
gemm_tn(GArgs g) {
    gemm_body<MODE>(g, blockIdx.x, blockIdx.y, blockIdx.z);
}

// dual-GEMM kernel: linear grid; first nb1 blocks run GEMM1 (small, wave-1),
// the rest run GEMM2. Decode x-fastest to match the 3D grid ordering.
template <int M1, int M2>
__global__ void __launch_bounds__(256, 2)
gemm_dual(GArgs g1, int gx1, int gy1, int nb1, GArgs g2, int gx2, int gy2) {
    int b = blockIdx.x;
    if (b < nb1) {
        int z = b / (gx1 * gy1);
        int rem = b % (gx1 * gy1);
        gemm_body<M1>(g1, rem % gx1, rem / gx1, z);
    } else {
        b -= nb1;
        int z = b / (gx2 * gy2);
        int rem = b % (gx2 * gy2);
        gemm_body<M2>(g2, rem % gx2, rem / gx2, z);
    }
}

// ---------------- host ----------------
#define SYMP(v, T) ({ void* _p = nullptr; cudaGetSymbolAddress(&_p, v); (T*)_p; })

extern "C" void kernel_launch(void* const* d_in, const int* in_sizes, int n_in,
                              void* d_out, int out_size) {
    const float* x          = (const float*)d_in[0];
    const float* gate_wt    = (const float*)d_in[1];
    const int*   inv        = (const int*)d_in[2];
    const float* mask_up_W  = (const float*)d_in[3];
    const float* gate_W     = (const float*)d_in[4];
    const float* gate_qa    = (const float*)d_in[5];
    const float* gate_qb    = (const float*)d_in[6];
    const float* gate_scale = (const float*)d_in[7];
    const float* up_W       = (const float*)d_in[8];
    const float* up_qa      = (const float*)d_in[9];
    const float* up_qb      = (const float*)d_in[10];
    const float* up_scale   = (const float*)d_in[11];
    const float* down_W     = (const float*)d_in[12];
    const float* down_qa    = (const float*)d_in[13];
    const float* down_qb    = (const float*)d_in[14];
    const float* down_scale = (const float*)d_in[15];
    const float* sh_gate_W  = (const float*)d_in[16];
    const float* sh_up_W    = (const float*)d_in[17];
    const float* sh_down_W  = (const float*)d_in[18];
    float* out = (float*)d_out;

    float* p_soft  = SYMP(g_soft, float);
    float* p_scal  = SYMP(g_scalar, float);
    int*   p_cnt   = SYMP(g_cnt, int);
    int*   p_tok   = SYMP(g_tok, int);
    int*   p_pos   = SYMP(g_pos, int);
    float* p_xe    = SYMP(g_xe, float);
    float* p_gu    = SYMP(g_gu, float);
    float* p_mgu   = SYMP(g_mgu, float);
    float* p_hmid  = SYMP(g_hmid, float);
    float* p_md    = SYMP(g_md, float);
    float* p_mixd  = SYMP(g_mixd, float);
    float* p_down  = SYMP(g_down, float);
    float* p_qbtgu = SYMP(g_qbtgu, float);
    float* p_qbtd  = SYMP(g_qbtd, float);
    float* p_shgu  = SYMP(g_shgu, float);
    float* p_shm   = SYMP(g_shm, float);
    float* p_sgu   = SYMP(g_sgu, float);
    float* p_xr    = SYMP(g_xr, float);

    cudaFuncSetAttribute(gemm_tn<2>, cudaFuncAttributeMaxDynamicSharedMemorySize, SMEM_BYTES);
    cudaFuncSetAttribute(gemm_tn<2>, cudaFuncAttributePreferredSharedMemoryCarveout, 100);
    cudaFuncSetAttribute(gemm_tn<3>, cudaFuncAttributeMaxDynamicSharedMemorySize, SMEM_BYTES);
    cudaFuncSetAttribute(gemm_tn<3>, cudaFuncAttributePreferredSharedMemoryCarveout, 100);
    cudaFuncSetAttribute(gemm_dual<1, 0>, cudaFuncAttributeMaxDynamicSharedMemorySize, SMEM_BYTES);
    cudaFuncSetAttribute(gemm_dual<1, 0>, cudaFuncAttributePreferredSharedMemoryCarveout, 100);
    cudaFuncSetAttribute(gemm_dual<0, 4>, cudaFuncAttributeMaxDynamicSharedMemorySize, SMEM_BYTES);
    cudaFuncSetAttribute(gemm_dual<0, 4>, cudaFuncAttributePreferredSharedMemoryCarveout, 100);

#define NB(n) ((int)(((n) + 255) / 256))

    // 1. router (exact fp32)
    router_kernel<<<Tn, 128>>>(x, gate_wt, inv, p_soft, p_scal);
    // 2. deterministic token compaction
    compact_kernel<<<Fn, Tn>>>(p_scal, p_cnt, p_tok, p_pos);
    // 3. xe (compacted, rounded at producer)
    xe_kernel<<<NB((size_t)Fn * Tn * Hn), 256>>>(x, mask_up_W, p_soft, p_cnt, p_tok, p_xe);
    // 4. rounded x for shared path (early; independent)
    round_copy<<<NB((size_t)Tn * Hn / 4), 256>>>(
        (const float4*)x, (float4*)p_xr, (int)((size_t)Tn * Hn / 4));

    // arg structs
    GArgs aGU  = { p_xe, Hn, (size_t)Tn * Hn, gate_W, Hn, (size_t)In * Hn, up_W, In,
                   p_gu, IGU, (size_t)Tn * IGU, IGU, Hn,
                   nullptr, nullptr, nullptr, 0, nullptr, p_cnt, nullptr };
    GArgs aLA  = { p_xe, Hn, (size_t)Tn * Hn, gate_qa, Hn, (size_t)KRn * Hn, up_qa, KRn,
                   p_mgu, 128, (size_t)Tn * 128, 128, Hn,
                   p_soft, nullptr, nullptr, 0, nullptr, p_cnt, p_tok };
    GArgs aMIX = { p_mgu, 128, (size_t)Tn * 128, p_qbtgu, 128, (size_t)IGU * 128, p_qbtgu, IGU,
                   p_gu, IGU, (size_t)Tn * IGU, IGU, 128,
                   nullptr, nullptr, p_sgu, IGU, nullptr, p_cnt, nullptr };
    GArgs aDLA = { p_hmid, In, (size_t)Tn * In, down_qa, In, (size_t)KRn * In, down_qa, KRn,
                   p_md, KRn, (size_t)Tn * KRn, KRn, In,
                   p_soft, nullptr, nullptr, 0, nullptr, p_cnt, p_tok };
    GArgs aSHG = { p_xr, Hn, 0, sh_gate_W, Hn, 0, sh_up_W, ISHn,
                   p_shgu, SH2, 0, SH2, Hn,
                   nullptr, nullptr, nullptr, 0, nullptr, nullptr, nullptr };
    GArgs aMXD = { p_md, KRn, (size_t)Tn * KRn, p_qbtd, KRn, (size_t)Hn * KRn, p_qbtd, Hn,
                   p_mixd, Hn, (size_t)Tn * Hn, Hn, KRn,
                   nullptr, nullptr, down_scale, Hn, nullptr, p_cnt, nullptr };
    GArgs aDWN = { p_hmid, In, (size_t)Tn * In, down_W, In, (size_t)Hn * In, down_W, Hn,
                   p_down, Hn, (size_t)Tn * Hn, Hn, In,
                   nullptr, p_scal, nullptr, 0, p_mixd, p_cnt, p_tok };
    GArgs aSHD = { p_shm, ISHn, 0, sh_down_W, ISHn, 0, sh_down_W, Hn,
                   out, Hn, 0, Hn, ISHn,
                   nullptr, nullptr, nullptr, 0, nullptr, nullptr, nullptr };

    // 5. DUAL: LoRA-a (1x8x8=64 blocks, first) + gate||up GEMM (22x8x8=1408)
    gemm_dual<1, 0><<<64 + 1408, 256, SMEM_BYTES>>>(aLA, 1, 8, 64, aGU, 22, 8);

    // 6. block-diagonal qbt concat
    tq2_kernel<<<NB(Fn * IGU * 128), 256>>>(gate_qb, up_qb, p_qbtgu);
    // 7. scale concat
    sc2<<<NB(2 * Fn * In), 256>>>(gate_scale, up_scale, p_sgu);
    // 8. combined mix GEMM, in-place (22x8x8)
    gemm_tn<2><<<dim3(22, 8, Fn), 256, SMEM_BYTES>>>(aMIX);
    // 9. hmid = silu(gate)*up
    fuse_kernel<<<NB((size_t)Fn * Tn * In), 256>>>(p_gu, p_cnt, p_hmid);
    // 10. down qbt
    tq_kernel<<<NB(Fn * Hn * KRn), 256>>>(down_qb, p_qbtd, Hn);

    // 11. DUAL: down LoRA-a (1x8x8=64, first) + shared gate||up GEMM (44x8x1=352)
    gemm_dual<1, 0><<<64 + 352, 256, SMEM_BYTES>>>(aDLA, 1, 8, 64, aSHG, 44, 8);

    // 12. mixd (16x8x8)
    gemm_tn<3><<<dim3(16, 8, Fn), 256, SMEM_BYTES>>>(aMXD);
    // 13. swiglu
    swiglu_kernel<<<NB((size_t)Tn * ISHn), 256>>>(p_shgu, p_shm);

    // 14. DUAL: shared down GEMM (16x8x1=128, first) + down GEMM (16x8x8=1024)
    gemm_dual<0, 4><<<128 + 1024, 256, SMEM_BYTES>>>(aSHD, 16, 8, 128, aDWN, 16, 8);

    // 15. out += gathered expert outputs
    reduce_kernel<<<NB(Tn * Hn), 256>>>(out, p_down, p_pos);

#undef NB
    (void)in_sizes; (void)n_in; (void)out_size;
}